// round 3
// baseline (speedup 1.0000x reference)
#include <cuda_runtime.h>
#include <cuda_bf16.h>
#include <math.h>

// ---------------- problem constants ----------------
#define TT    2048
#define DD    4096
#define HH    16
#define DHD   256
#define DFF   16384
#define ROTD  64

// ---------------- scratch (device globals; no cudaMalloc allowed) ----------------
__device__ float g_h  [TT * DD];
__device__ float g_q  [TT * DD];
__device__ float g_k  [TT * DD];
__device__ float g_v  [TT * DD];
__device__ float g_y  [TT * DD];
__device__ float g_tmp[TT * DD];
__device__ float g_m  [TT * DFF];

// ---------------- LayerNorm ----------------
__global__ __launch_bounds__(256) void ln_kernel(const float* __restrict__ x,
                                                 const float* __restrict__ g,
                                                 const float* __restrict__ b,
                                                 float* __restrict__ h) {
    int row = blockIdx.x;
    const float4* xr = (const float4*)(x + (size_t)row * DD);
    float s = 0.f, s2 = 0.f;
    for (int i = threadIdx.x; i < DD / 4; i += 256) {
        float4 v = xr[i];
        s  += v.x + v.y + v.z + v.w;
        s2 += v.x*v.x + v.y*v.y + v.z*v.z + v.w*v.w;
    }
    for (int o = 16; o > 0; o >>= 1) {
        s  += __shfl_xor_sync(~0u, s,  o);
        s2 += __shfl_xor_sync(~0u, s2, o);
    }
    __shared__ float sh[16];
    int w = threadIdx.x >> 5;
    if ((threadIdx.x & 31) == 0) { sh[w] = s; sh[8 + w] = s2; }
    __syncthreads();
    if (threadIdx.x < 32) {
        float a = threadIdx.x < 8 ? sh[threadIdx.x]     : 0.f;
        float c = threadIdx.x < 8 ? sh[8 + threadIdx.x] : 0.f;
        for (int o = 4; o > 0; o >>= 1) {
            a += __shfl_xor_sync(~0u, a, o);
            c += __shfl_xor_sync(~0u, c, o);
        }
        if (threadIdx.x == 0) { sh[0] = a; sh[8] = c; }
    }
    __syncthreads();
    float mean = sh[0] * (1.f / DD);
    float var  = sh[8] * (1.f / DD) - mean * mean;
    float rstd = rsqrtf(var + 1e-6f);
    float4* hr = (float4*)(h + (size_t)row * DD);
    const float4* gg4 = (const float4*)g;
    const float4* bb4 = (const float4*)b;
    for (int i = threadIdx.x; i < DD / 4; i += 256) {
        float4 v = xr[i], gg = gg4[i], bb = bb4[i], o;
        o.x = (v.x - mean) * rstd * gg.x + bb.x;
        o.y = (v.y - mean) * rstd * gg.y + bb.y;
        o.z = (v.z - mean) * rstd * gg.z + bb.z;
        o.w = (v.w - mean) * rstd * gg.w + bb.w;
        hr[i] = o;
    }
}

// ---------------- RoPE (applied in-place to q and k) ----------------
__global__ __launch_bounds__(256) void rope_kernel(float* __restrict__ q, float* __restrict__ k) {
    int idx = blockIdx.x * 256 + threadIdx.x;   // T*H*32 threads
    int f = idx & 31;
    int hh = (idx >> 5) & (HH - 1);
    int t = idx >> 9;
    float inv = 1.0f / powf(10000.0f, (float)f * (1.0f / 32.0f));
    float ang = (float)t * inv;                 // fp32 to mimic reference rounding
    float sn, cs;
    sincosf(ang, &sn, &cs);
    size_t base = (size_t)t * DD + hh * DHD + f;
    {
        float a = q[base], b = q[base + 32];
        q[base]      = a * cs - b * sn;
        q[base + 32] = a * sn + b * cs;
    }
    {
        float a = k[base], b = k[base + 32];
        k[base]      = a * cs - b * sn;
        k[base + 32] = a * sn + b * cs;
    }
}

// ---------------- GEMM 128x128x16, 256 threads, 8x8 microtiles ----------------
// EPI: 0 = store, 1 = gelu(acc+bias), 2 = acc+res, 3 = acc+bias+res
__device__ __forceinline__ float gelu_f(float v) {
    float t = tanhf(0.7978845608028654f * (v + 0.044715f * v * v * v));
    return 0.5f * v * (1.f + t);
}

template <int EPI>
__device__ __forceinline__ void sgemm_body(const float* __restrict__ A, const float* __restrict__ B,
                                           const float* __restrict__ bias, const float* __restrict__ res,
                                           float* __restrict__ C, int N, int K) {
    __shared__ float As[16][132];
    __shared__ float Bs[16][128];
    int tid = threadIdx.x;
    int bm = blockIdx.y * 128, bn = blockIdx.x * 128;
    int tr = tid >> 4, tc = tid & 15;

    int arow = tid >> 2, ak = (tid & 3) << 2;
    int brow = tid >> 5, bc = (tid & 31) << 2;
    const float* Aptr = A + (size_t)(bm + arow) * K + ak;
    const float* Bptr = B + (size_t)brow * N + bn + bc;

    float4 aReg0 = *(const float4*)Aptr;
    float4 aReg1 = *(const float4*)(Aptr + (size_t)64 * K);
    float4 bReg0 = *(const float4*)Bptr;
    float4 bReg1 = *(const float4*)(Bptr + (size_t)8 * N);

    float acc[8][8];
#pragma unroll
    for (int i = 0; i < 8; ++i)
#pragma unroll
        for (int j = 0; j < 8; ++j) acc[i][j] = 0.f;

    int ntiles = K >> 4;
    for (int kt = 0; kt < ntiles; ++kt) {
        As[ak + 0][arow]      = aReg0.x;
        As[ak + 1][arow]      = aReg0.y;
        As[ak + 2][arow]      = aReg0.z;
        As[ak + 3][arow]      = aReg0.w;
        As[ak + 0][64 + arow] = aReg1.x;
        As[ak + 1][64 + arow] = aReg1.y;
        As[ak + 2][64 + arow] = aReg1.z;
        As[ak + 3][64 + arow] = aReg1.w;
        *(float4*)&Bs[brow][bc]     = bReg0;
        *(float4*)&Bs[brow + 8][bc] = bReg1;
        __syncthreads();

        if (kt + 1 < ntiles) {
            Aptr += 16;
            Bptr += (size_t)16 * N;
            aReg0 = *(const float4*)Aptr;
            aReg1 = *(const float4*)(Aptr + (size_t)64 * K);
            bReg0 = *(const float4*)Bptr;
            bReg1 = *(const float4*)(Bptr + (size_t)8 * N);
        }

#pragma unroll
        for (int kk = 0; kk < 16; ++kk) {
            float a[8], b[8];
            *(float4*)&a[0] = *(const float4*)&As[kk][tr * 4];
            *(float4*)&a[4] = *(const float4*)&As[kk][64 + tr * 4];
            *(float4*)&b[0] = *(const float4*)&Bs[kk][tc * 4];
            *(float4*)&b[4] = *(const float4*)&Bs[kk][64 + tc * 4];
#pragma unroll
            for (int i = 0; i < 8; ++i)
#pragma unroll
                for (int j = 0; j < 8; ++j) acc[i][j] += a[i] * b[j];
        }
        __syncthreads();
    }

    // epilogue
#pragma unroll
    for (int ih = 0; ih < 2; ++ih) {
#pragma unroll
        for (int i = 0; i < 4; ++i) {
            int r = bm + ih * 64 + tr * 4 + i;
#pragma unroll
            for (int jh = 0; jh < 2; ++jh) {
                int c = bn + jh * 64 + tc * 4;
                float4 v;
                v.x = acc[ih * 4 + i][jh * 4 + 0];
                v.y = acc[ih * 4 + i][jh * 4 + 1];
                v.z = acc[ih * 4 + i][jh * 4 + 2];
                v.w = acc[ih * 4 + i][jh * 4 + 3];
                if (EPI == 1) {
                    float4 bb = *(const float4*)(bias + c);
                    v.x = gelu_f(v.x + bb.x);
                    v.y = gelu_f(v.y + bb.y);
                    v.z = gelu_f(v.z + bb.z);
                    v.w = gelu_f(v.w + bb.w);
                } else if (EPI == 2) {
                    float4 rr = *(const float4*)(res + (size_t)r * N + c);
                    v.x += rr.x; v.y += rr.y; v.z += rr.z; v.w += rr.w;
                } else if (EPI == 3) {
                    float4 bb = *(const float4*)(bias + c);
                    float4 rr = *(const float4*)(res + (size_t)r * N + c);
                    v.x += bb.x + rr.x; v.y += bb.y + rr.y;
                    v.z += bb.z + rr.z; v.w += bb.w + rr.w;
                }
                *(float4*)&C[(size_t)r * N + c] = v;
            }
        }
    }
}

template <int EPI>
__global__ __launch_bounds__(256) void gemm_kernel(const float* __restrict__ A, const float* __restrict__ B,
                                                   const float* __restrict__ bias, const float* __restrict__ res,
                                                   float* __restrict__ C, int N, int K) {
    sgemm_body<EPI>(A, B, bias, res, C, N, K);
}

__global__ __launch_bounds__(256) void qkv_kernel(const float* __restrict__ h,
                                                  const float* __restrict__ wq, const float* __restrict__ wk,
                                                  const float* __restrict__ wv,
                                                  float* __restrict__ q, float* __restrict__ k, float* __restrict__ v) {
    const float* B = (blockIdx.z == 0) ? wq : (blockIdx.z == 1) ? wk : wv;
    float* C       = (blockIdx.z == 0) ? q  : (blockIdx.z == 1) ? k  : v;
    sgemm_body<0>(h, B, nullptr, nullptr, C, DD, DD);
}

// ---------------- Flash attention (fp32, Br=Bc=64, online softmax) ----------------
#define QS_STRIDE 260
#define PS_STRIDE 68
#define ATTN_SMEM ((3 * 64 * QS_STRIDE + 64 * PS_STRIDE) * 4)

__global__ __launch_bounds__(256) void attn_kernel(const float* __restrict__ q,
                                                   const float* __restrict__ k,
                                                   const float* __restrict__ v,
                                                   float* __restrict__ y) {
    extern __shared__ float sm[];
    float* Qs = sm;
    float* Ks = Qs + 64 * QS_STRIDE;
    float* Vs = Ks + 64 * QS_STRIDE;
    float* Ps = Vs + 64 * QS_STRIDE;

    int qt = blockIdx.x, hh = blockIdx.y;
    int tid = threadIdx.x, ty = tid >> 4, tx = tid & 15;
    int r0 = ty * 4, c0 = tx * 4;
    size_t hoff = (size_t)hh * DHD;

    // load Q tile (pre-scaled by 1/sqrt(Dh) = 1/16)
    for (int i = tid; i < 64 * 64; i += 256) {
        int row = i >> 6, c4 = i & 63;
        float4 t = *(const float4*)(q + (size_t)(qt * 64 + row) * DD + hoff + c4 * 4);
        t.x *= 0.0625f; t.y *= 0.0625f; t.z *= 0.0625f; t.w *= 0.0625f;
        *(float4*)&Qs[row * QS_STRIDE + c4 * 4] = t;
    }

    float O[4][16];
#pragma unroll
    for (int i = 0; i < 4; ++i)
#pragma unroll
        for (int cc = 0; cc < 16; ++cc) O[i][cc] = 0.f;
    float mrow[4] = {-1e30f, -1e30f, -1e30f, -1e30f};
    float lrow[4] = {0.f, 0.f, 0.f, 0.f};

    for (int kt = 0; kt <= qt; ++kt) {
        __syncthreads();  // protect Ks/Vs/Ps (and Qs on first iteration)
        for (int i = tid; i < 64 * 64; i += 256) {
            int row = i >> 6, c4 = i & 63;
            *(float4*)&Ks[row * QS_STRIDE + c4 * 4] =
                *(const float4*)(k + (size_t)(kt * 64 + row) * DD + hoff + c4 * 4);
            *(float4*)&Vs[row * QS_STRIDE + c4 * 4] =
                *(const float4*)(v + (size_t)(kt * 64 + row) * DD + hoff + c4 * 4);
        }
        __syncthreads();

        float S[4][4];
#pragma unroll
        for (int i = 0; i < 4; ++i)
#pragma unroll
            for (int j = 0; j < 4; ++j) S[i][j] = 0.f;

#pragma unroll 8
        for (int d4 = 0; d4 < 64; ++d4) {
            float4 qa[4], kb[4];
#pragma unroll
            for (int i = 0; i < 4; ++i) qa[i] = *(const float4*)&Qs[(r0 + i) * QS_STRIDE + d4 * 4];
#pragma unroll
            for (int j = 0; j < 4; ++j) kb[j] = *(const float4*)&Ks[(c0 + j) * QS_STRIDE + d4 * 4];
#pragma unroll
            for (int i = 0; i < 4; ++i)
#pragma unroll
                for (int j = 0; j < 4; ++j)
                    S[i][j] += qa[i].x * kb[j].x + qa[i].y * kb[j].y + qa[i].z * kb[j].z + qa[i].w * kb[j].w;
        }

        if (kt == qt) {
#pragma unroll
            for (int i = 0; i < 4; ++i)
#pragma unroll
                for (int j = 0; j < 4; ++j)
                    if (c0 + j > r0 + i) S[i][j] = -1e30f;
        }

#pragma unroll
        for (int i = 0; i < 4; ++i) {
            float tm = fmaxf(fmaxf(S[i][0], S[i][1]), fmaxf(S[i][2], S[i][3]));
            for (int o = 8; o > 0; o >>= 1) tm = fmaxf(tm, __shfl_xor_sync(~0u, tm, o, 16));
            float nm = fmaxf(mrow[i], tm);
            float alpha = expf(mrow[i] - nm);
            mrow[i] = nm;
            float rs = 0.f;
#pragma unroll
            for (int j = 0; j < 4; ++j) {
                float p = expf(S[i][j] - nm);
                S[i][j] = p;
                rs += p;
            }
            for (int o = 8; o > 0; o >>= 1) rs += __shfl_xor_sync(~0u, rs, o, 16);
            lrow[i] = lrow[i] * alpha + rs;
#pragma unroll
            for (int cc = 0; cc < 16; ++cc) O[i][cc] *= alpha;
            float4 pp;
            pp.x = S[i][0]; pp.y = S[i][1]; pp.z = S[i][2]; pp.w = S[i][3];
            *(float4*)&Ps[(r0 + i) * PS_STRIDE + c0] = pp;
        }
        __syncthreads();

        // O += P @ V
#pragma unroll 4
        for (int j = 0; j < 64; ++j) {
            float pv[4];
#pragma unroll
            for (int i = 0; i < 4; ++i) pv[i] = Ps[(r0 + i) * PS_STRIDE + j];
#pragma unroll
            for (int cc = 0; cc < 16; ++cc) {
                float vv = Vs[j * QS_STRIDE + cc * 16 + tx];
#pragma unroll
                for (int i = 0; i < 4; ++i) O[i][cc] += pv[i] * vv;
            }
        }
    }

#pragma unroll
    for (int i = 0; i < 4; ++i) {
        float inv = 1.f / lrow[i];
        size_t rb = (size_t)(qt * 64 + r0 + i) * DD + hoff;
#pragma unroll
        for (int cc = 0; cc < 16; ++cc) y[rb + cc * 16 + tx] = O[i][cc] * inv;
    }
}

// ---------------- launcher ----------------
extern "C" void kernel_launch(void* const* d_in, const int* in_sizes, int n_in,
                              void* d_out, int out_size) {
    const float* x       = (const float*)d_in[0];
    const float* wq      = (const float*)d_in[1];
    const float* wk      = (const float*)d_in[2];
    const float* wv      = (const float*)d_in[3];
    const float* wo      = (const float*)d_in[4];
    const float* w_in    = (const float*)d_in[5];
    const float* b_in    = (const float*)d_in[6];
    const float* w_out   = (const float*)d_in[7];
    const float* b_out   = (const float*)d_in[8];
    const float* ln_s    = (const float*)d_in[9];
    const float* ln_o    = (const float*)d_in[10];
    float* out = (float*)d_out;

    float *h, *q, *k, *v, *y, *tmp, *m;
    cudaGetSymbolAddress((void**)&h,   g_h);
    cudaGetSymbolAddress((void**)&q,   g_q);
    cudaGetSymbolAddress((void**)&k,   g_k);
    cudaGetSymbolAddress((void**)&v,   g_v);
    cudaGetSymbolAddress((void**)&y,   g_y);
    cudaGetSymbolAddress((void**)&tmp, g_tmp);
    cudaGetSymbolAddress((void**)&m,   g_m);

    cudaFuncSetAttribute(attn_kernel, cudaFuncAttributeMaxDynamicSharedMemorySize, ATTN_SMEM);

    // 1. LayerNorm
    ln_kernel<<<TT, 256>>>(x, ln_s, ln_o, h);
    // 2. QKV projections (z-batched)
    qkv_kernel<<<dim3(DD / 128, TT / 128, 3), 256>>>(h, wq, wk, wv, q, k, v);
    // 3. RoPE on q, k
    rope_kernel<<<(TT * HH * 32) / 256, 256>>>(q, k);
    // 4. Causal flash attention
    attn_kernel<<<dim3(TT / 64, HH), 256, ATTN_SMEM>>>(q, k, v, y);
    // 5. tmp = y @ wo + x
    gemm_kernel<2><<<dim3(DD / 128, TT / 128), 256>>>(y, wo, nullptr, x, tmp, DD, DD);
    // 6. m = gelu(h @ w_in + b_in)
    gemm_kernel<1><<<dim3(DFF / 128, TT / 128), 256>>>(h, w_in, b_in, nullptr, m, DFF, DD);
    // 7. out = m @ w_out + b_out + tmp
    gemm_kernel<3><<<dim3(DD / 128, TT / 128), 256>>>(m, w_out, b_out, tmp, out, DD, DFF);
}

// round 5
// speedup vs baseline: 1.3610x; 1.3610x over previous
#include <cuda_runtime.h>
#include <cuda_bf16.h>
#include <mma.h>
#include <math.h>
#include <stdint.h>

using namespace nvcuda;

// ---------------- problem constants ----------------
#define TT    2048
#define DD    4096
#define HH    16
#define DHD   256
#define DFF   16384

// ---------------- scratch (device globals; no cudaMalloc allowed) ----------------
__device__ float g_h  [TT * DD];
__device__ float g_q  [TT * DD];
__device__ float g_k  [TT * DD];
__device__ float g_v  [TT * DD];
__device__ float g_y  [TT * DD];
__device__ float g_tmp[TT * DD];
__device__ float g_m  [TT * DFF];
// transposed (tf32-rounded) weights
__device__ float g_wt [4u*4096u*4096u + 2u*4096u*16384u];

#define WQT_OFF   0u
#define WKT_OFF   16777216u
#define WVT_OFF   33554432u
#define WOT_OFF   50331648u
#define WINT_OFF  67108864u
#define WOUTT_OFF 134217728u

// ---------------- helpers ----------------
__device__ __forceinline__ float to_tf32(float x) {
    uint32_t r;
    asm("cvt.rna.tf32.f32 %0, %1;" : "=r"(r) : "f"(x));
    return __uint_as_float(r);
}
__device__ __forceinline__ uint32_t smem_u32(const void* p) {
    uint32_t r;
    asm("{ .reg .u64 t; cvta.to.shared.u64 t, %1; cvt.u32.u64 %0, t; }" : "=r"(r) : "l"(p));
    return r;
}
__device__ __forceinline__ void cpasync16(uint32_t dst, const void* src) {
    asm volatile("cp.async.cg.shared.global [%0], [%1], 16;" :: "r"(dst), "l"(src));
}
#define CP_COMMIT() asm volatile("cp.async.commit_group;" ::: "memory")

// ---------------- LayerNorm (tf32-rounded output: feeds GEMMs only) ----------------
__global__ __launch_bounds__(256) void ln_kernel(const float* __restrict__ x,
                                                 const float* __restrict__ g,
                                                 const float* __restrict__ b,
                                                 float* __restrict__ h) {
    int row = blockIdx.x;
    const float4* xr = (const float4*)(x + (size_t)row * DD);
    float s = 0.f, s2 = 0.f;
    for (int i = threadIdx.x; i < DD / 4; i += 256) {
        float4 v = xr[i];
        s  += v.x + v.y + v.z + v.w;
        s2 += v.x*v.x + v.y*v.y + v.z*v.z + v.w*v.w;
    }
    for (int o = 16; o > 0; o >>= 1) {
        s  += __shfl_xor_sync(~0u, s,  o);
        s2 += __shfl_xor_sync(~0u, s2, o);
    }
    __shared__ float sh[16];
    int w = threadIdx.x >> 5;
    if ((threadIdx.x & 31) == 0) { sh[w] = s; sh[8 + w] = s2; }
    __syncthreads();
    if (threadIdx.x < 32) {
        float a = threadIdx.x < 8 ? sh[threadIdx.x]     : 0.f;
        float c = threadIdx.x < 8 ? sh[8 + threadIdx.x] : 0.f;
        for (int o = 4; o > 0; o >>= 1) {
            a += __shfl_xor_sync(~0u, a, o);
            c += __shfl_xor_sync(~0u, c, o);
        }
        if (threadIdx.x == 0) { sh[0] = a; sh[8] = c; }
    }
    __syncthreads();
    float mean = sh[0] * (1.f / DD);
    float var  = sh[8] * (1.f / DD) - mean * mean;
    float rstd = rsqrtf(var + 1e-6f);
    float4* hr = (float4*)(h + (size_t)row * DD);
    const float4* gg4 = (const float4*)g;
    const float4* bb4 = (const float4*)b;
    for (int i = threadIdx.x; i < DD / 4; i += 256) {
        float4 v = xr[i], gg = gg4[i], bb = bb4[i], o;
        o.x = to_tf32((v.x - mean) * rstd * gg.x + bb.x);
        o.y = to_tf32((v.y - mean) * rstd * gg.y + bb.y);
        o.z = to_tf32((v.z - mean) * rstd * gg.z + bb.z);
        o.w = to_tf32((v.w - mean) * rstd * gg.w + bb.w);
        hr[i] = o;
    }
}

// ---------------- weight transpose [R,C] -> [C,R], rounded to tf32 ----------------
__global__ __launch_bounds__(256) void transpose_kernel(const float* __restrict__ in,
                                                        float* __restrict__ out, int R, int C) {
    __shared__ float t[32][33];
    int bx = blockIdx.x * 32, by = blockIdx.y * 32;
    int tx = threadIdx.x & 31, ty = threadIdx.x >> 5;
#pragma unroll
    for (int i = 0; i < 32; i += 8)
        t[ty + i][tx] = in[(size_t)(by + ty + i) * C + bx + tx];
    __syncthreads();
#pragma unroll
    for (int i = 0; i < 32; i += 8)
        out[(size_t)(bx + ty + i) * R + by + tx] = to_tf32(t[tx][ty + i]);
}

// ---------------- RoPE (applied in-place to q and k) ----------------
__global__ __launch_bounds__(256) void rope_kernel(float* __restrict__ q, float* __restrict__ k) {
    int idx = blockIdx.x * 256 + threadIdx.x;
    int f = idx & 31;
    int hh = (idx >> 5) & (HH - 1);
    int t = idx >> 9;
    float inv = 1.0f / powf(10000.0f, (float)f * (1.0f / 32.0f));
    float ang = (float)t * inv;
    float sn, cs;
    sincosf(ang, &sn, &cs);
    size_t base = (size_t)t * DD + hh * DHD + f;
    {
        float a = q[base], b = q[base + 32];
        q[base]      = a * cs - b * sn;
        q[base + 32] = a * sn + b * cs;
    }
    {
        float a = k[base], b = k[base + 32];
        k[base]      = a * cs - b * sn;
        k[base + 32] = a * sn + b * cs;
    }
}

// ---------------- tf32 wmma GEMM: tile 128x128, K-step 32, 4-stage cp.async ----------------
// A: [M,K] K-major (tf32-rounded). BT: [N,K] K-major (tf32-rounded). C: [M,N].
// EPI: 0 = store, 1 = gelu(acc+bias) (tf32-rounded), 2 = acc+res, 3 = acc+bias+res
__device__ __forceinline__ float gelu_f(float v) {
    float t = tanhf(0.7978845608028654f * (v + 0.044715f * v * v * v));
    return 0.5f * v * (1.f + t);
}

#define TSTRIDE 36                         // smem row stride (floats), 144B = 9x16B
#define STAGE_FLOATS (2 * 128 * TSTRIDE)   // A tile + B tile
#define STAGE_BYTES  (STAGE_FLOATS * 4)    // 36864
#define GSTAGES 4
#define GSMEM_TOTAL (GSTAGES * STAGE_BYTES) // 147456

template <int EPI>
__device__ __forceinline__ void tgemm_body(const float* __restrict__ A, const float* __restrict__ BT,
                                           const float* __restrict__ bias, const float* __restrict__ res,
                                           float* __restrict__ C, int N, int K) {
    extern __shared__ __align__(16) float gsm[];
    uint32_t sbase = smem_u32(gsm);
    int tid = threadIdx.x;
    int wid = tid >> 5;
    int bm = blockIdx.y * 128;
    int bn = blockIdx.x * 128;
    int ntiles = K >> 5;

    // per-thread cp.async slots: 2048 16B chunks per stage / 256 threads = 8
    const float* src[8];
    uint32_t doff[8];   // byte offset within a stage
#pragma unroll
    for (int j = 0; j < 8; ++j) {
        int idx = tid + 256 * j;
        if (idx < 1024) {           // A: 128 rows x 8 chunks(16B)
            int row = idx >> 3, seg = idx & 7;
            src[j]  = A + (size_t)(bm + row) * K + seg * 4;
            doff[j] = (row * TSTRIDE + seg * 4) * 4;
        } else {                    // B: 128 rows x 8 chunks
            int i2 = idx - 1024;
            int row = i2 >> 3, seg = i2 & 7;
            src[j]  = BT + (size_t)(bn + row) * K + seg * 4;
            doff[j] = (128 * TSTRIDE + row * TSTRIDE + seg * 4) * 4;
        }
    }

    // prologue: stages 0..2
#pragma unroll
    for (int p = 0; p < GSTAGES - 1; ++p) {
        uint32_t stb = sbase + p * STAGE_BYTES;
#pragma unroll
        for (int j = 0; j < 8; ++j) cpasync16(stb + doff[j], src[j] + p * 32);
        CP_COMMIT();
    }

    wmma::fragment<wmma::accumulator, 16, 16, 8, float> acc[4][2];
#pragma unroll
    for (int i = 0; i < 4; ++i)
#pragma unroll
        for (int j = 0; j < 2; ++j) wmma::fill_fragment(acc[i][j], 0.f);

    int wm = (wid >> 2) * 64;   // warp row within tile
    int wn = (wid & 3) * 32;    // warp col within tile

    for (int kt = 0; kt < ntiles; ++kt) {
        asm volatile("cp.async.wait_group 2;" ::: "memory");
        __syncthreads();

        // prefetch stage kt+3
        int jt = kt + GSTAGES - 1;
        if (jt < ntiles) {
            uint32_t stb = sbase + (jt & (GSTAGES - 1)) * STAGE_BYTES;
#pragma unroll
            for (int j = 0; j < 8; ++j) cpasync16(stb + doff[j], src[j] + jt * 32);
        }
        CP_COMMIT();

        const float* As = gsm + (kt & (GSTAGES - 1)) * STAGE_FLOATS;
        const float* Bs = As + 128 * TSTRIDE;
#pragma unroll
        for (int k8 = 0; k8 < 4; ++k8) {
            wmma::fragment<wmma::matrix_a, 16, 16, 8, wmma::precision::tf32, wmma::row_major> a[4];
            wmma::fragment<wmma::matrix_b, 16, 16, 8, wmma::precision::tf32, wmma::col_major> b[2];
#pragma unroll
            for (int i = 0; i < 4; ++i)
                wmma::load_matrix_sync(a[i], As + (wm + i * 16) * TSTRIDE + k8 * 8, TSTRIDE);
#pragma unroll
            for (int j = 0; j < 2; ++j)
                wmma::load_matrix_sync(b[j], Bs + (wn + j * 16) * TSTRIDE + k8 * 8, TSTRIDE);
#pragma unroll
            for (int i = 0; i < 4; ++i)
#pragma unroll
                for (int j = 0; j < 2; ++j)
                    wmma::mma_sync(acc[i][j], a[i], b[j], acc[i][j]);
        }
    }

    // epilogue: dump accumulators to smem (reuse pipeline buffers), then elementwise out
    __syncthreads();
    float* Cs = gsm;   // 128 x 132 floats = 67.6KB < 144KB
#pragma unroll
    for (int i = 0; i < 4; ++i)
#pragma unroll
        for (int j = 0; j < 2; ++j)
            wmma::store_matrix_sync(Cs + (wm + i * 16) * 132 + (wn + j * 16), acc[i][j], 132, wmma::mem_row_major);
    __syncthreads();

    for (int it = tid; it < 128 * 32; it += 256) {
        int row = it >> 5, c4 = it & 31;
        float4 v = *(const float4*)&Cs[row * 132 + c4 * 4];
        int r = bm + row, c = bn + c4 * 4;
        size_t rowoff = (size_t)r * N;
        if (EPI == 1) {
            float4 bb = *(const float4*)(bias + c);
            v.x = to_tf32(gelu_f(v.x + bb.x));
            v.y = to_tf32(gelu_f(v.y + bb.y));
            v.z = to_tf32(gelu_f(v.z + bb.z));
            v.w = to_tf32(gelu_f(v.w + bb.w));
        } else if (EPI == 2) {
            float4 rr = *(const float4*)(res + rowoff + c);
            v.x += rr.x; v.y += rr.y; v.z += rr.z; v.w += rr.w;
        } else if (EPI == 3) {
            float4 bb = *(const float4*)(bias + c);
            float4 rr = *(const float4*)(res + rowoff + c);
            v.x += bb.x + rr.x; v.y += bb.y + rr.y;
            v.z += bb.z + rr.z; v.w += bb.w + rr.w;
        }
        *(float4*)&C[rowoff + c] = v;
    }
}

template <int EPI>
__global__ __launch_bounds__(256)
void tgemm_kernel(const float* __restrict__ A, const float* __restrict__ BT,
                  const float* __restrict__ bias, const float* __restrict__ res,
                  float* __restrict__ C, int N, int K) {
    tgemm_body<EPI>(A, BT, bias, res, C, N, K);
}

__global__ __launch_bounds__(256)
void tgemm_qkv_kernel(const float* __restrict__ h, const float* __restrict__ wt,
                      float* __restrict__ q, float* __restrict__ k, float* __restrict__ v) {
    const float* BT = (blockIdx.z == 0) ? (wt + WQT_OFF) : (blockIdx.z == 1) ? (wt + WKT_OFF) : (wt + WVT_OFF);
    float* C        = (blockIdx.z == 0) ? q : (blockIdx.z == 1) ? k : v;
    tgemm_body<0>(h, BT, nullptr, nullptr, C, DD, DD);
}

// ---------------- Flash attention (fp32, Br=Bc=64, online softmax) ----------------
#define QS_STRIDE 260
#define PS_STRIDE 68
#define ATTN_SMEM ((3 * 64 * QS_STRIDE + 64 * PS_STRIDE) * 4)

__global__ __launch_bounds__(256) void attn_kernel(const float* __restrict__ q,
                                                   const float* __restrict__ k,
                                                   const float* __restrict__ v,
                                                   float* __restrict__ y) {
    extern __shared__ float sm[];
    float* Qs = sm;
    float* Ks = Qs + 64 * QS_STRIDE;
    float* Vs = Ks + 64 * QS_STRIDE;
    float* Ps = Vs + 64 * QS_STRIDE;

    int qt = blockIdx.x, hh = blockIdx.y;
    int tid = threadIdx.x, ty = tid >> 4, tx = tid & 15;
    int r0 = ty * 4, c0 = tx * 4;
    size_t hoff = (size_t)hh * DHD;

    for (int i = tid; i < 64 * 64; i += 256) {
        int row = i >> 6, c4 = i & 63;
        float4 t = *(const float4*)(q + (size_t)(qt * 64 + row) * DD + hoff + c4 * 4);
        t.x *= 0.0625f; t.y *= 0.0625f; t.z *= 0.0625f; t.w *= 0.0625f;
        *(float4*)&Qs[row * QS_STRIDE + c4 * 4] = t;
    }

    float O[4][16];
#pragma unroll
    for (int i = 0; i < 4; ++i)
#pragma unroll
        for (int cc = 0; cc < 16; ++cc) O[i][cc] = 0.f;
    float mrow[4] = {-1e30f, -1e30f, -1e30f, -1e30f};
    float lrow[4] = {0.f, 0.f, 0.f, 0.f};

    for (int kt = 0; kt <= qt; ++kt) {
        __syncthreads();
        for (int i = tid; i < 64 * 64; i += 256) {
            int row = i >> 6, c4 = i & 63;
            *(float4*)&Ks[row * QS_STRIDE + c4 * 4] =
                *(const float4*)(k + (size_t)(kt * 64 + row) * DD + hoff + c4 * 4);
            *(float4*)&Vs[row * QS_STRIDE + c4 * 4] =
                *(const float4*)(v + (size_t)(kt * 64 + row) * DD + hoff + c4 * 4);
        }
        __syncthreads();

        float S[4][4];
#pragma unroll
        for (int i = 0; i < 4; ++i)
#pragma unroll
            for (int j = 0; j < 4; ++j) S[i][j] = 0.f;

#pragma unroll 8
        for (int d4 = 0; d4 < 64; ++d4) {
            float4 qa[4], kb[4];
#pragma unroll
            for (int i = 0; i < 4; ++i) qa[i] = *(const float4*)&Qs[(r0 + i) * QS_STRIDE + d4 * 4];
#pragma unroll
            for (int j = 0; j < 4; ++j) kb[j] = *(const float4*)&Ks[(c0 + j) * QS_STRIDE + d4 * 4];
#pragma unroll
            for (int i = 0; i < 4; ++i)
#pragma unroll
                for (int j = 0; j < 4; ++j)
                    S[i][j] += qa[i].x * kb[j].x + qa[i].y * kb[j].y + qa[i].z * kb[j].z + qa[i].w * kb[j].w;
        }

        if (kt == qt) {
#pragma unroll
            for (int i = 0; i < 4; ++i)
#pragma unroll
                for (int j = 0; j < 4; ++j)
                    if (c0 + j > r0 + i) S[i][j] = -1e30f;
        }

#pragma unroll
        for (int i = 0; i < 4; ++i) {
            float tm = fmaxf(fmaxf(S[i][0], S[i][1]), fmaxf(S[i][2], S[i][3]));
            for (int o = 8; o > 0; o >>= 1) tm = fmaxf(tm, __shfl_xor_sync(~0u, tm, o, 16));
            float nm = fmaxf(mrow[i], tm);
            float alpha = expf(mrow[i] - nm);
            mrow[i] = nm;
            float rs = 0.f;
#pragma unroll
            for (int j = 0; j < 4; ++j) {
                float p = expf(S[i][j] - nm);
                S[i][j] = p;
                rs += p;
            }
            for (int o = 8; o > 0; o >>= 1) rs += __shfl_xor_sync(~0u, rs, o, 16);
            lrow[i] = lrow[i] * alpha + rs;
#pragma unroll
            for (int cc = 0; cc < 16; ++cc) O[i][cc] *= alpha;
            float4 pp;
            pp.x = S[i][0]; pp.y = S[i][1]; pp.z = S[i][2]; pp.w = S[i][3];
            *(float4*)&Ps[(r0 + i) * PS_STRIDE + c0] = pp;
        }
        __syncthreads();

#pragma unroll 4
        for (int j = 0; j < 64; ++j) {
            float pv[4];
#pragma unroll
            for (int i = 0; i < 4; ++i) pv[i] = Ps[(r0 + i) * PS_STRIDE + j];
#pragma unroll
            for (int cc = 0; cc < 16; ++cc) {
                float vv = Vs[j * QS_STRIDE + cc * 16 + tx];
#pragma unroll
                for (int i = 0; i < 4; ++i) O[i][cc] += pv[i] * vv;
            }
        }
    }

#pragma unroll
    for (int i = 0; i < 4; ++i) {
        float inv = 1.f / lrow[i];
        size_t rb = (size_t)(qt * 64 + r0 + i) * DD + hoff;
#pragma unroll
        for (int cc = 0; cc < 16; ++cc) y[rb + cc * 16 + tx] = to_tf32(O[i][cc] * inv);
    }
}

// ---------------- launcher ----------------
extern "C" void kernel_launch(void* const* d_in, const int* in_sizes, int n_in,
                              void* d_out, int out_size) {
    const float* x     = (const float*)d_in[0];
    const float* wq    = (const float*)d_in[1];
    const float* wk    = (const float*)d_in[2];
    const float* wv    = (const float*)d_in[3];
    const float* wo    = (const float*)d_in[4];
    const float* w_in  = (const float*)d_in[5];
    const float* b_in  = (const float*)d_in[6];
    const float* w_out = (const float*)d_in[7];
    const float* b_out = (const float*)d_in[8];
    const float* ln_s  = (const float*)d_in[9];
    const float* ln_o  = (const float*)d_in[10];
    float* out = (float*)d_out;

    float *h, *q, *k, *v, *y, *tmp, *m, *wt;
    cudaGetSymbolAddress((void**)&h,   g_h);
    cudaGetSymbolAddress((void**)&q,   g_q);
    cudaGetSymbolAddress((void**)&k,   g_k);
    cudaGetSymbolAddress((void**)&v,   g_v);
    cudaGetSymbolAddress((void**)&y,   g_y);
    cudaGetSymbolAddress((void**)&tmp, g_tmp);
    cudaGetSymbolAddress((void**)&m,   g_m);
    cudaGetSymbolAddress((void**)&wt,  g_wt);

    cudaFuncSetAttribute(attn_kernel, cudaFuncAttributeMaxDynamicSharedMemorySize, ATTN_SMEM);
    cudaFuncSetAttribute(tgemm_qkv_kernel, cudaFuncAttributeMaxDynamicSharedMemorySize, GSMEM_TOTAL);
    cudaFuncSetAttribute(tgemm_kernel<1>,  cudaFuncAttributeMaxDynamicSharedMemorySize, GSMEM_TOTAL);
    cudaFuncSetAttribute(tgemm_kernel<2>,  cudaFuncAttributeMaxDynamicSharedMemorySize, GSMEM_TOTAL);
    cudaFuncSetAttribute(tgemm_kernel<3>,  cudaFuncAttributeMaxDynamicSharedMemorySize, GSMEM_TOTAL);

    // 0. transpose (+ tf32-round) weights into [N,K] K-major scratch
    transpose_kernel<<<dim3(DD / 32, DD / 32), 256>>>(wq, wt + WQT_OFF, DD, DD);
    transpose_kernel<<<dim3(DD / 32, DD / 32), 256>>>(wk, wt + WKT_OFF, DD, DD);
    transpose_kernel<<<dim3(DD / 32, DD / 32), 256>>>(wv, wt + WVT_OFF, DD, DD);
    transpose_kernel<<<dim3(DD / 32, DD / 32), 256>>>(wo, wt + WOT_OFF, DD, DD);
    transpose_kernel<<<dim3(DFF / 32, DD / 32), 256>>>(w_in,  wt + WINT_OFF,  DD, DFF);
    transpose_kernel<<<dim3(DD / 32, DFF / 32), 256>>>(w_out, wt + WOUTT_OFF, DFF, DD);

    // 1. LayerNorm (tf32-rounded output)
    ln_kernel<<<TT, 256>>>(x, ln_s, ln_o, h);
    // 2. QKV projections (wmma tf32)
    tgemm_qkv_kernel<<<dim3(DD / 128, TT / 128, 3), 256, GSMEM_TOTAL>>>(h, wt, q, k, v);
    // 3. RoPE on q, k
    rope_kernel<<<(TT * HH * 32) / 256, 256>>>(q, k);
    // 4. Causal flash attention (fp32)
    attn_kernel<<<dim3(TT / 64, HH), 256, ATTN_SMEM>>>(q, k, v, y);
    // 5. tmp = y @ wo + x
    tgemm_kernel<2><<<dim3(DD / 128, TT / 128), 256, GSMEM_TOTAL>>>(y, wt + WOT_OFF, nullptr, x, tmp, DD, DD);
    // 6. m = gelu(h @ w_in + b_in)   (tf32-rounded: feeds next GEMM)
    tgemm_kernel<1><<<dim3(DFF / 128, TT / 128), 256, GSMEM_TOTAL>>>(h, wt + WINT_OFF, b_in, nullptr, m, DFF, DD);
    // 7. out = m @ w_out + b_out + tmp
    tgemm_kernel<3><<<dim3(DD / 128, TT / 128), 256, GSMEM_TOTAL>>>(m, wt + WOUTT_OFF, b_out, tmp, out, DD, DFF);
}

// round 7
// speedup vs baseline: 2.7817x; 2.0439x over previous
#include <cuda_runtime.h>
#include <cuda_bf16.h>
#include <math.h>
#include <stdint.h>

// ---------------- problem constants ----------------
#define TT    2048
#define DD    4096
#define HH    16
#define DHD   256
#define DFF   16384

// ---------------- scratch (device globals; no cudaMalloc allowed) ----------------
__device__ float g_h  [TT * DD];
__device__ float g_q  [TT * DD];
__device__ float g_k  [TT * DD];
__device__ float g_v  [TT * DD];
__device__ float g_y  [TT * DD];
__device__ float g_tmp[TT * DD];
__device__ float g_m  [TT * DFF];
// transposed (tf32-rounded) weights
__device__ float g_wt [4u*4096u*4096u + 2u*4096u*16384u];

#define WQT_OFF   0u
#define WKT_OFF   16777216u
#define WVT_OFF   33554432u
#define WOT_OFF   50331648u
#define WINT_OFF  67108864u
#define WOUTT_OFF 134217728u

// ---------------- helpers ----------------
__device__ __forceinline__ float to_tf32(float x) {
    uint32_t r;
    asm("cvt.rna.tf32.f32 %0, %1;" : "=r"(r) : "f"(x));
    return __uint_as_float(r);
}
__device__ __forceinline__ uint32_t smem_u32(const void* p) {
    uint32_t r;
    asm("{ .reg .u64 t; cvta.to.shared.u64 t, %1; cvt.u32.u64 %0, t; }" : "=r"(r) : "l"(p));
    return r;
}
__device__ __forceinline__ void cpasync16(uint32_t dst, const void* src) {
    asm volatile("cp.async.cg.shared.global [%0], [%1], 16;" :: "r"(dst), "l"(src));
}
#define CP_COMMIT() asm volatile("cp.async.commit_group;" ::: "memory")

__device__ __forceinline__ void ldsm_x4(uint32_t (&r)[4], uint32_t addr) {
    asm volatile("ldmatrix.sync.aligned.m8n8.x4.shared.b16 {%0,%1,%2,%3}, [%4];"
        : "=r"(r[0]), "=r"(r[1]), "=r"(r[2]), "=r"(r[3]) : "r"(addr));
}
__device__ __forceinline__ void mma_tf32(float (&d)[4], const uint32_t (&a)[4],
                                         uint32_t b0, uint32_t b1) {
    asm volatile("mma.sync.aligned.m16n8k8.row.col.f32.tf32.tf32.f32 "
        "{%0,%1,%2,%3}, {%4,%5,%6,%7}, {%8,%9}, {%0,%1,%2,%3};"
        : "+f"(d[0]), "+f"(d[1]), "+f"(d[2]), "+f"(d[3])
        : "r"(a[0]), "r"(a[1]), "r"(a[2]), "r"(a[3]), "r"(b0), "r"(b1));
}

// SW128 swizzle: bits[6:4] ^= bits[9:7]
#define TSWZ(off) ((off) ^ (((off) >> 3) & 0x70))

// ---------------- LayerNorm (tf32-rounded output: feeds GEMMs only) ----------------
__global__ __launch_bounds__(256) void ln_kernel(const float* __restrict__ x,
                                                 const float* __restrict__ g,
                                                 const float* __restrict__ b,
                                                 float* __restrict__ h) {
    int row = blockIdx.x;
    const float4* xr = (const float4*)(x + (size_t)row * DD);
    float s = 0.f, s2 = 0.f;
    for (int i = threadIdx.x; i < DD / 4; i += 256) {
        float4 v = xr[i];
        s  += v.x + v.y + v.z + v.w;
        s2 += v.x*v.x + v.y*v.y + v.z*v.z + v.w*v.w;
    }
    for (int o = 16; o > 0; o >>= 1) {
        s  += __shfl_xor_sync(~0u, s,  o);
        s2 += __shfl_xor_sync(~0u, s2, o);
    }
    __shared__ float sh[16];
    int w = threadIdx.x >> 5;
    if ((threadIdx.x & 31) == 0) { sh[w] = s; sh[8 + w] = s2; }
    __syncthreads();
    if (threadIdx.x < 32) {
        float a = threadIdx.x < 8 ? sh[threadIdx.x]     : 0.f;
        float c = threadIdx.x < 8 ? sh[8 + threadIdx.x] : 0.f;
        for (int o = 4; o > 0; o >>= 1) {
            a += __shfl_xor_sync(~0u, a, o);
            c += __shfl_xor_sync(~0u, c, o);
        }
        if (threadIdx.x == 0) { sh[0] = a; sh[8] = c; }
    }
    __syncthreads();
    float mean = sh[0] * (1.f / DD);
    float var  = sh[8] * (1.f / DD) - mean * mean;
    float rstd = rsqrtf(var + 1e-6f);
    float4* hr = (float4*)(h + (size_t)row * DD);
    const float4* gg4 = (const float4*)g;
    const float4* bb4 = (const float4*)b;
    for (int i = threadIdx.x; i < DD / 4; i += 256) {
        float4 v = xr[i], gg = gg4[i], bb = bb4[i], o;
        o.x = to_tf32((v.x - mean) * rstd * gg.x + bb.x);
        o.y = to_tf32((v.y - mean) * rstd * gg.y + bb.y);
        o.z = to_tf32((v.z - mean) * rstd * gg.z + bb.z);
        o.w = to_tf32((v.w - mean) * rstd * gg.w + bb.w);
        hr[i] = o;
    }
}

// ---------------- weight transpose [R,C] -> [C,R], rounded to tf32 ----------------
__global__ __launch_bounds__(256) void transpose_kernel(const float* __restrict__ in,
                                                        float* __restrict__ out, int R, int C) {
    __shared__ float t[32][33];
    int bx = blockIdx.x * 32, by = blockIdx.y * 32;
    int tx = threadIdx.x & 31, ty = threadIdx.x >> 5;
#pragma unroll
    for (int i = 0; i < 32; i += 8)
        t[ty + i][tx] = in[(size_t)(by + ty + i) * C + bx + tx];
    __syncthreads();
#pragma unroll
    for (int i = 0; i < 32; i += 8)
        out[(size_t)(bx + ty + i) * R + by + tx] = to_tf32(t[tx][ty + i]);
}

// ---------------- RoPE (applied in-place to q and k) ----------------
__global__ __launch_bounds__(256) void rope_kernel(float* __restrict__ q, float* __restrict__ k) {
    int idx = blockIdx.x * 256 + threadIdx.x;
    int f = idx & 31;
    int hh = (idx >> 5) & (HH - 1);
    int t = idx >> 9;
    float inv = 1.0f / powf(10000.0f, (float)f * (1.0f / 32.0f));
    float ang = (float)t * inv;
    float sn, cs;
    sincosf(ang, &sn, &cs);
    size_t base = (size_t)t * DD + hh * DHD + f;
    {
        float a = q[base], b = q[base + 32];
        q[base]      = a * cs - b * sn;
        q[base + 32] = a * sn + b * cs;
    }
    {
        float a = k[base], b = k[base + 32];
        k[base]      = a * cs - b * sn;
        k[base + 32] = a * sn + b * cs;
    }
}

// ---------------- tf32 mma.sync GEMM: CTA 128x256, warp 64x64, K-step 32, 3-stage cp.async ----------------
// A: [M,K] K-major (tf32-rounded). BT: [N,K] K-major (tf32-rounded). C: [M,N].
// EPI: 0 = store, 1 = gelu(acc+bias) tf32-rounded, 2 = acc+res, 3 = acc+bias+res
__device__ __forceinline__ float gelu_f(float v) {
    float t = tanhf(0.7978845608028654f * (v + 0.044715f * v * v * v));
    return 0.5f * v * (1.f + t);
}

#define STAGE_BYTES 49152            // A 16KB + B 32KB
#define B_SMEM_OFF  16384
#define GSTAGES 3
#define GSMEM_TOTAL (GSTAGES * STAGE_BYTES)   // 147456

template <int EPI>
__device__ __forceinline__ void tgemm_body(const float* __restrict__ A, const float* __restrict__ BT,
                                           const float* __restrict__ bias, const float* __restrict__ res,
                                           float* __restrict__ C, int N, int K) {
    extern __shared__ __align__(1024) char gsm[];
    uint32_t sbase = smem_u32(gsm);
    int tid = threadIdx.x, lane = tid & 31, wid = tid >> 5;
    int bm = blockIdx.y * 128, bn = blockIdx.x * 256;
    int ntiles = K >> 5;
    int wm = (wid >> 2) * 64, wn = (wid & 3) * 64;

    // cp.async mapping: 3072 16B chunks / 256 threads = 12 per thread (j<4: A, j>=4: B)
    uint32_t doff[12];
    int      soff[12];
#pragma unroll
    for (int j = 0; j < 12; ++j) {
        int idx = tid + 256 * j;
        if (j < 4) {                 // A: 128 rows x 8 segs
            int row = idx >> 3, seg = idx & 7;
            soff[j] = row * K + seg * 4;
            doff[j] = TSWZ((uint32_t)(row * 128 + seg * 16));
        } else {                     // B: 256 rows x 8 segs
            int i2 = idx - 1024;
            int row = i2 >> 3, seg = i2 & 7;
            soff[j] = row * K + seg * 4;
            doff[j] = B_SMEM_OFF + TSWZ((uint32_t)(row * 128 + seg * 16));
        }
    }
    const float* Abase = A  + (size_t)bm * K;
    const float* Bbase = BT + (size_t)bn * K;

    // prologue: stages 0,1
#pragma unroll
    for (int p = 0; p < 2; ++p) {
        uint32_t stb = sbase + p * STAGE_BYTES;
#pragma unroll
        for (int j = 0; j < 4; ++j)  cpasync16(stb + doff[j], Abase + soff[j] + p * 32);
#pragma unroll
        for (int j = 4; j < 12; ++j) cpasync16(stb + doff[j], Bbase + soff[j] + p * 32);
        CP_COMMIT();
    }

    float acc[4][8][4];
#pragma unroll
    for (int i = 0; i < 4; ++i)
#pragma unroll
        for (int j = 0; j < 8; ++j)
#pragma unroll
            for (int e = 0; e < 4; ++e) acc[i][j][e] = 0.f;

    // per-lane ldmatrix address components
    int dr = ((lane >> 3) & 1) * 8 + (lane & 7);   // row delta within 16-row block
    int dk = ((lane >> 4) & 1) * 16;               // k-byte delta (0 or 16)

    int stage = 0;
    for (int kt = 0; kt < ntiles; ++kt) {
        asm volatile("cp.async.wait_group 1;" ::: "memory");
        __syncthreads();

        // prefetch stage kt+2
        int jt = kt + 2;
        if (jt < ntiles) {
            int ps = stage + 2; if (ps >= GSTAGES) ps -= GSTAGES;
            uint32_t stb = sbase + ps * STAGE_BYTES;
#pragma unroll
            for (int j = 0; j < 4; ++j)  cpasync16(stb + doff[j], Abase + soff[j] + jt * 32);
#pragma unroll
            for (int j = 4; j < 12; ++j) cpasync16(stb + doff[j], Bbase + soff[j] + jt * 32);
        }
        CP_COMMIT();

        uint32_t stb = sbase + stage * STAGE_BYTES;
#pragma unroll
        for (int k8 = 0; k8 < 4; ++k8) {
            uint32_t kb = (uint32_t)(k8 * 32 + dk);
            uint32_t a[4][4];
#pragma unroll
            for (int i = 0; i < 4; ++i)
                ldsm_x4(a[i], stb + TSWZ((uint32_t)((wm + i * 16 + dr) * 128) + kb));
            uint32_t b[4][4];
#pragma unroll
            for (int jj = 0; jj < 4; ++jj)
                ldsm_x4(b[jj], stb + B_SMEM_OFF + TSWZ((uint32_t)((wn + jj * 16 + dr) * 128) + kb));
            // b[jj][0]=(n+0..7,k0-3)  b[jj][1]=(n+8..15,k0-3)
            // b[jj][2]=(n+0..7,k4-7)  b[jj][3]=(n+8..15,k4-7)
            // mma needs b0=(k0-3,n-slice), b1=(k4-7, SAME n-slice)
#pragma unroll
            for (int i = 0; i < 4; ++i)
#pragma unroll
                for (int j = 0; j < 8; ++j)
                    mma_tf32(acc[i][j], a[i], b[j >> 1][j & 1], b[j >> 1][(j & 1) + 2]);
        }
        if (++stage == GSTAGES) stage = 0;
    }

    // epilogue: direct register -> gmem (float2 per fragment half)
    int lr = lane >> 2, lc = (lane & 3) * 2;
#pragma unroll
    for (int i = 0; i < 4; ++i) {
        int r0 = bm + wm + i * 16 + lr;
        int r1 = r0 + 8;
        size_t ro0 = (size_t)r0 * N, ro1 = (size_t)r1 * N;
#pragma unroll
        for (int j = 0; j < 8; ++j) {
            int c = bn + wn + j * 8 + lc;
            float2 v0 = make_float2(acc[i][j][0], acc[i][j][1]);
            float2 v1 = make_float2(acc[i][j][2], acc[i][j][3]);
            if (EPI == 1) {
                float2 bb = *(const float2*)(bias + c);
                v0.x = to_tf32(gelu_f(v0.x + bb.x)); v0.y = to_tf32(gelu_f(v0.y + bb.y));
                v1.x = to_tf32(gelu_f(v1.x + bb.x)); v1.y = to_tf32(gelu_f(v1.y + bb.y));
            } else if (EPI == 2) {
                float2 ra = *(const float2*)(res + ro0 + c);
                float2 rb = *(const float2*)(res + ro1 + c);
                v0.x += ra.x; v0.y += ra.y; v1.x += rb.x; v1.y += rb.y;
            } else if (EPI == 3) {
                float2 bb = *(const float2*)(bias + c);
                float2 ra = *(const float2*)(res + ro0 + c);
                float2 rb = *(const float2*)(res + ro1 + c);
                v0.x += bb.x + ra.x; v0.y += bb.y + ra.y;
                v1.x += bb.x + rb.x; v1.y += bb.y + rb.y;
            }
            *(float2*)&C[ro0 + c] = v0;
            *(float2*)&C[ro1 + c] = v1;
        }
    }
}

template <int EPI>
__global__ __launch_bounds__(256, 1)
void tgemm_kernel(const float* __restrict__ A, const float* __restrict__ BT,
                  const float* __restrict__ bias, const float* __restrict__ res,
                  float* __restrict__ C, int N, int K) {
    tgemm_body<EPI>(A, BT, bias, res, C, N, K);
}

__global__ __launch_bounds__(256, 1)
void tgemm_qkv_kernel(const float* __restrict__ h, const float* __restrict__ wt,
                      float* __restrict__ q, float* __restrict__ k, float* __restrict__ v) {
    const float* BT = (blockIdx.z == 0) ? (wt + WQT_OFF) : (blockIdx.z == 1) ? (wt + WKT_OFF) : (wt + WVT_OFF);
    float* C        = (blockIdx.z == 0) ? q : (blockIdx.z == 1) ? k : v;
    tgemm_body<0>(h, BT, nullptr, nullptr, C, DD, DD);
}

// ---------------- Flash attention (fp32, Br=Bc=64, online softmax) ----------------
#define QS_STRIDE 260
#define PS_STRIDE 68
#define ATTN_SMEM ((3 * 64 * QS_STRIDE + 64 * PS_STRIDE) * 4)

__global__ __launch_bounds__(256) void attn_kernel(const float* __restrict__ q,
                                                   const float* __restrict__ k,
                                                   const float* __restrict__ v,
                                                   float* __restrict__ y) {
    extern __shared__ float sm[];
    float* Qs = sm;
    float* Ks = Qs + 64 * QS_STRIDE;
    float* Vs = Ks + 64 * QS_STRIDE;
    float* Ps = Vs + 64 * QS_STRIDE;

    int qt = blockIdx.x, hh = blockIdx.y;
    int tid = threadIdx.x, ty = tid >> 4, tx = tid & 15;
    int r0 = ty * 4, c0 = tx * 4;
    size_t hoff = (size_t)hh * DHD;

    for (int i = tid; i < 64 * 64; i += 256) {
        int row = i >> 6, c4 = i & 63;
        float4 t = *(const float4*)(q + (size_t)(qt * 64 + row) * DD + hoff + c4 * 4);
        t.x *= 0.0625f; t.y *= 0.0625f; t.z *= 0.0625f; t.w *= 0.0625f;
        *(float4*)&Qs[row * QS_STRIDE + c4 * 4] = t;
    }

    float O[4][16];
#pragma unroll
    for (int i = 0; i < 4; ++i)
#pragma unroll
        for (int cc = 0; cc < 16; ++cc) O[i][cc] = 0.f;
    float mrow[4] = {-1e30f, -1e30f, -1e30f, -1e30f};
    float lrow[4] = {0.f, 0.f, 0.f, 0.f};

    for (int kt = 0; kt <= qt; ++kt) {
        __syncthreads();
        for (int i = tid; i < 64 * 64; i += 256) {
            int row = i >> 6, c4 = i & 63;
            *(float4*)&Ks[row * QS_STRIDE + c4 * 4] =
                *(const float4*)(k + (size_t)(kt * 64 + row) * DD + hoff + c4 * 4);
            *(float4*)&Vs[row * QS_STRIDE + c4 * 4] =
                *(const float4*)(v + (size_t)(kt * 64 + row) * DD + hoff + c4 * 4);
        }
        __syncthreads();

        float S[4][4];
#pragma unroll
        for (int i = 0; i < 4; ++i)
#pragma unroll
            for (int j = 0; j < 4; ++j) S[i][j] = 0.f;

#pragma unroll 8
        for (int d4 = 0; d4 < 64; ++d4) {
            float4 qa[4], kb[4];
#pragma unroll
            for (int i = 0; i < 4; ++i) qa[i] = *(const float4*)&Qs[(r0 + i) * QS_STRIDE + d4 * 4];
#pragma unroll
            for (int j = 0; j < 4; ++j) kb[j] = *(const float4*)&Ks[(c0 + j) * QS_STRIDE + d4 * 4];
#pragma unroll
            for (int i = 0; i < 4; ++i)
#pragma unroll
                for (int j = 0; j < 4; ++j)
                    S[i][j] += qa[i].x * kb[j].x + qa[i].y * kb[j].y + qa[i].z * kb[j].z + qa[i].w * kb[j].w;
        }

        if (kt == qt) {
#pragma unroll
            for (int i = 0; i < 4; ++i)
#pragma unroll
                for (int j = 0; j < 4; ++j)
                    if (c0 + j > r0 + i) S[i][j] = -1e30f;
        }

#pragma unroll
        for (int i = 0; i < 4; ++i) {
            float tm = fmaxf(fmaxf(S[i][0], S[i][1]), fmaxf(S[i][2], S[i][3]));
            for (int o = 8; o > 0; o >>= 1) tm = fmaxf(tm, __shfl_xor_sync(~0u, tm, o, 16));
            float nm = fmaxf(mrow[i], tm);
            float alpha = expf(mrow[i] - nm);
            mrow[i] = nm;
            float rs = 0.f;
#pragma unroll
            for (int j = 0; j < 4; ++j) {
                float p = expf(S[i][j] - nm);
                S[i][j] = p;
                rs += p;
            }
            for (int o = 8; o > 0; o >>= 1) rs += __shfl_xor_sync(~0u, rs, o, 16);
            lrow[i] = lrow[i] * alpha + rs;
#pragma unroll
            for (int cc = 0; cc < 16; ++cc) O[i][cc] *= alpha;
            float4 pp;
            pp.x = S[i][0]; pp.y = S[i][1]; pp.z = S[i][2]; pp.w = S[i][3];
            *(float4*)&Ps[(r0 + i) * PS_STRIDE + c0] = pp;
        }
        __syncthreads();

#pragma unroll 4
        for (int j = 0; j < 64; ++j) {
            float pv[4];
#pragma unroll
            for (int i = 0; i < 4; ++i) pv[i] = Ps[(r0 + i) * PS_STRIDE + j];
#pragma unroll
            for (int cc = 0; cc < 16; ++cc) {
                float vv = Vs[j * QS_STRIDE + cc * 16 + tx];
#pragma unroll
                for (int i = 0; i < 4; ++i) O[i][cc] += pv[i] * vv;
            }
        }
    }

#pragma unroll
    for (int i = 0; i < 4; ++i) {
        float inv = 1.f / lrow[i];
        size_t rb = (size_t)(qt * 64 + r0 + i) * DD + hoff;
#pragma unroll
        for (int cc = 0; cc < 16; ++cc) y[rb + cc * 16 + tx] = to_tf32(O[i][cc] * inv);
    }
}

// ---------------- launcher ----------------
extern "C" void kernel_launch(void* const* d_in, const int* in_sizes, int n_in,
                              void* d_out, int out_size) {
    const float* x     = (const float*)d_in[0];
    const float* wq    = (const float*)d_in[1];
    const float* wk    = (const float*)d_in[2];
    const float* wv    = (const float*)d_in[3];
    const float* wo    = (const float*)d_in[4];
    const float* w_in  = (const float*)d_in[5];
    const float* b_in  = (const float*)d_in[6];
    const float* w_out = (const float*)d_in[7];
    const float* b_out = (const float*)d_in[8];
    const float* ln_s  = (const float*)d_in[9];
    const float* ln_o  = (const float*)d_in[10];
    float* out = (float*)d_out;

    float *h, *q, *k, *v, *y, *tmp, *m, *wt;
    cudaGetSymbolAddress((void**)&h,   g_h);
    cudaGetSymbolAddress((void**)&q,   g_q);
    cudaGetSymbolAddress((void**)&k,   g_k);
    cudaGetSymbolAddress((void**)&v,   g_v);
    cudaGetSymbolAddress((void**)&y,   g_y);
    cudaGetSymbolAddress((void**)&tmp, g_tmp);
    cudaGetSymbolAddress((void**)&m,   g_m);
    cudaGetSymbolAddress((void**)&wt,  g_wt);

    cudaFuncSetAttribute(attn_kernel, cudaFuncAttributeMaxDynamicSharedMemorySize, ATTN_SMEM);
    cudaFuncSetAttribute(tgemm_qkv_kernel, cudaFuncAttributeMaxDynamicSharedMemorySize, GSMEM_TOTAL);
    cudaFuncSetAttribute(tgemm_kernel<1>,  cudaFuncAttributeMaxDynamicSharedMemorySize, GSMEM_TOTAL);
    cudaFuncSetAttribute(tgemm_kernel<2>,  cudaFuncAttributeMaxDynamicSharedMemorySize, GSMEM_TOTAL);
    cudaFuncSetAttribute(tgemm_kernel<3>,  cudaFuncAttributeMaxDynamicSharedMemorySize, GSMEM_TOTAL);

    // 0. transpose (+ tf32-round) weights into [N,K] K-major scratch
    transpose_kernel<<<dim3(DD / 32, DD / 32), 256>>>(wq, wt + WQT_OFF, DD, DD);
    transpose_kernel<<<dim3(DD / 32, DD / 32), 256>>>(wk, wt + WKT_OFF, DD, DD);
    transpose_kernel<<<dim3(DD / 32, DD / 32), 256>>>(wv, wt + WVT_OFF, DD, DD);
    transpose_kernel<<<dim3(DD / 32, DD / 32), 256>>>(wo, wt + WOT_OFF, DD, DD);
    transpose_kernel<<<dim3(DFF / 32, DD / 32), 256>>>(w_in,  wt + WINT_OFF,  DD, DFF);
    transpose_kernel<<<dim3(DD / 32, DFF / 32), 256>>>(w_out, wt + WOUTT_OFF, DFF, DD);

    // 1. LayerNorm (tf32-rounded output)
    ln_kernel<<<TT, 256>>>(x, ln_s, ln_o, h);
    // 2. QKV projections (mma.sync tf32)
    tgemm_qkv_kernel<<<dim3(DD / 256, TT / 128, 3), 256, GSMEM_TOTAL>>>(h, wt, q, k, v);
    // 3. RoPE on q, k
    rope_kernel<<<(TT * HH * 32) / 256, 256>>>(q, k);
    // 4. Causal flash attention (fp32)
    attn_kernel<<<dim3(TT / 64, HH), 256, ATTN_SMEM>>>(q, k, v, y);
    // 5. tmp = y @ wo + x
    tgemm_kernel<2><<<dim3(DD / 256, TT / 128), 256, GSMEM_TOTAL>>>(y, wt + WOT_OFF, nullptr, x, tmp, DD, DD);
    // 6. m = gelu(h @ w_in + b_in)   (tf32-rounded: feeds next GEMM)
    tgemm_kernel<1><<<dim3(DFF / 256, TT / 128), 256, GSMEM_TOTAL>>>(h, wt + WINT_OFF, b_in, nullptr, m, DFF, DD);
    // 7. out = m @ w_out + b_out + tmp
    tgemm_kernel<3><<<dim3(DD / 256, TT / 128), 256, GSMEM_TOTAL>>>(m, wt + WOUTT_OFF, b_out, tmp, out, DD, DFF);
}

// round 8
// speedup vs baseline: 4.1779x; 1.5019x over previous
#include <cuda_runtime.h>
#include <cuda_fp16.h>
#include <math.h>
#include <stdint.h>

// ---------------- problem constants ----------------
#define TT    2048
#define DD    4096
#define HH    16
#define DHD   256
#define DFF   16384

// ---------------- scratch (device globals; no cudaMalloc allowed) ----------------
__device__ __half g_h  [TT * DD];      // LN output (fp16, feeds GEMMs)
__device__ float  g_q  [TT * DD];
__device__ float  g_k  [TT * DD];
__device__ float  g_v  [TT * DD];
__device__ __half g_y  [TT * DD];      // attention output (fp16, feeds Wo GEMM)
__device__ float  g_tmp[TT * DD];
__device__ __half g_m  [TT * DFF];     // gelu output (fp16, feeds MLP-out GEMM)
// transposed fp16 weights: wqT wkT wvT woT (4x 4096x4096), w_inT (16384x4096), w_outT (4096x16384)
__device__ __half g_wt [4u*4096u*4096u + 2u*4096u*16384u];

#define WQT_OFF   0u
#define WKT_OFF   16777216u
#define WVT_OFF   33554432u
#define WOT_OFF   50331648u
#define WINT_OFF  67108864u
#define WOUTT_OFF 134217728u

// ---------------- helpers ----------------
__device__ __forceinline__ uint32_t smem_u32(const void* p) {
    uint32_t r;
    asm("{ .reg .u64 t; cvta.to.shared.u64 t, %1; cvt.u32.u64 %0, t; }" : "=r"(r) : "l"(p));
    return r;
}
__device__ __forceinline__ void cpasync16(uint32_t dst, const void* src) {
    asm volatile("cp.async.cg.shared.global [%0], [%1], 16;" :: "r"(dst), "l"(src));
}
#define CP_COMMIT() asm volatile("cp.async.commit_group;" ::: "memory")

__device__ __forceinline__ void ldsm_x4(uint32_t (&r)[4], uint32_t addr) {
    asm volatile("ldmatrix.sync.aligned.m8n8.x4.shared.b16 {%0,%1,%2,%3}, [%4];"
        : "=r"(r[0]), "=r"(r[1]), "=r"(r[2]), "=r"(r[3]) : "r"(addr));
}
// m16n8k16 fp16 mma, fp32 accumulate
__device__ __forceinline__ void mma_f16(float (&d)[4], const uint32_t (&a)[4],
                                        uint32_t b0, uint32_t b1) {
    asm volatile("mma.sync.aligned.m16n8k16.row.col.f32.f16.f16.f32 "
        "{%0,%1,%2,%3}, {%4,%5,%6,%7}, {%8,%9}, {%0,%1,%2,%3};"
        : "+f"(d[0]), "+f"(d[1]), "+f"(d[2]), "+f"(d[3])
        : "r"(a[0]), "r"(a[1]), "r"(a[2]), "r"(a[3]), "r"(b0), "r"(b1));
}

// SW128 swizzle: bits[6:4] ^= bits[9:7]
#define TSWZ(off) ((off) ^ (((off) >> 3) & 0x70))

// ---------------- LayerNorm (fp16 output: feeds GEMMs only) ----------------
__global__ __launch_bounds__(256) void ln_kernel(const float* __restrict__ x,
                                                 const float* __restrict__ g,
                                                 const float* __restrict__ b,
                                                 __half* __restrict__ h) {
    int row = blockIdx.x;
    const float4* xr = (const float4*)(x + (size_t)row * DD);
    float s = 0.f, s2 = 0.f;
    for (int i = threadIdx.x; i < DD / 4; i += 256) {
        float4 v = xr[i];
        s  += v.x + v.y + v.z + v.w;
        s2 += v.x*v.x + v.y*v.y + v.z*v.z + v.w*v.w;
    }
    for (int o = 16; o > 0; o >>= 1) {
        s  += __shfl_xor_sync(~0u, s,  o);
        s2 += __shfl_xor_sync(~0u, s2, o);
    }
    __shared__ float sh[16];
    int w = threadIdx.x >> 5;
    if ((threadIdx.x & 31) == 0) { sh[w] = s; sh[8 + w] = s2; }
    __syncthreads();
    if (threadIdx.x < 32) {
        float a = threadIdx.x < 8 ? sh[threadIdx.x]     : 0.f;
        float c = threadIdx.x < 8 ? sh[8 + threadIdx.x] : 0.f;
        for (int o = 4; o > 0; o >>= 1) {
            a += __shfl_xor_sync(~0u, a, o);
            c += __shfl_xor_sync(~0u, c, o);
        }
        if (threadIdx.x == 0) { sh[0] = a; sh[8] = c; }
    }
    __syncthreads();
    float mean = sh[0] * (1.f / DD);
    float var  = sh[8] * (1.f / DD) - mean * mean;
    float rstd = rsqrtf(var + 1e-6f);
    __half2* hr = (__half2*)(h + (size_t)row * DD);
    const float4* gg4 = (const float4*)g;
    const float4* bb4 = (const float4*)b;
    for (int i = threadIdx.x; i < DD / 4; i += 256) {
        float4 v = xr[i], gg = gg4[i], bb = bb4[i];
        float ox = (v.x - mean) * rstd * gg.x + bb.x;
        float oy = (v.y - mean) * rstd * gg.y + bb.y;
        float oz = (v.z - mean) * rstd * gg.z + bb.z;
        float ow = (v.w - mean) * rstd * gg.w + bb.w;
        hr[i * 2]     = __floats2half2_rn(ox, oy);
        hr[i * 2 + 1] = __floats2half2_rn(oz, ow);
    }
}

// ---------------- weight transpose [R,C] fp32 -> [C,R] fp16 ----------------
__global__ __launch_bounds__(256) void transpose_kernel(const float* __restrict__ in,
                                                        __half* __restrict__ out, int R, int C) {
    __shared__ float t[32][33];
    int bx = blockIdx.x * 32, by = blockIdx.y * 32;
    int tx = threadIdx.x & 31, ty = threadIdx.x >> 5;
#pragma unroll
    for (int i = 0; i < 32; i += 8)
        t[ty + i][tx] = in[(size_t)(by + ty + i) * C + bx + tx];
    __syncthreads();
#pragma unroll
    for (int i = 0; i < 32; i += 8)
        out[(size_t)(bx + ty + i) * R + by + tx] = __float2half_rn(t[tx][ty + i]);
}

// ---------------- RoPE (applied in-place to q and k, fp32) ----------------
__global__ __launch_bounds__(256) void rope_kernel(float* __restrict__ q, float* __restrict__ k) {
    int idx = blockIdx.x * 256 + threadIdx.x;
    int f = idx & 31;
    int hh = (idx >> 5) & (HH - 1);
    int t = idx >> 9;
    float inv = 1.0f / powf(10000.0f, (float)f * (1.0f / 32.0f));
    float ang = (float)t * inv;
    float sn, cs;
    sincosf(ang, &sn, &cs);
    size_t base = (size_t)t * DD + hh * DHD + f;
    {
        float a = q[base], b = q[base + 32];
        q[base]      = a * cs - b * sn;
        q[base + 32] = a * sn + b * cs;
    }
    {
        float a = k[base], b = k[base + 32];
        k[base]      = a * cs - b * sn;
        k[base + 32] = a * sn + b * cs;
    }
}

// ---------------- fp16 mma GEMM: CTA 128x256, warp 64x64, K-step 64 halves, 3-stage cp.async ----------------
// A: [M,K] K-major fp16. BT: [N,K] K-major fp16. C: [M,N] OutT.
// EPI: 0 = store, 1 = gelu(acc+bias), 2 = acc+res, 3 = acc+bias+res
__device__ __forceinline__ float gelu_f(float v) {
    float t = tanhf(0.7978845608028654f * (v + 0.044715f * v * v * v));
    return 0.5f * v * (1.f + t);
}

#define STAGE_BYTES 49152            // A 16KB + B 32KB
#define B_SMEM_OFF  16384
#define GSTAGES 3
#define GSMEM_TOTAL (GSTAGES * STAGE_BYTES)   // 147456

template <int EPI, typename OutT>
__device__ __forceinline__ void tgemm_body(const __half* __restrict__ A, const __half* __restrict__ BT,
                                           const float* __restrict__ bias, const float* __restrict__ res,
                                           OutT* __restrict__ C, int N, int K) {
    extern __shared__ __align__(1024) char gsm[];
    uint32_t sbase = smem_u32(gsm);
    int tid = threadIdx.x, lane = tid & 31, wid = tid >> 5;
    int bm = blockIdx.y * 128, bn = blockIdx.x * 256;
    int ntiles = K >> 6;                       // 64 halves (128B) per k-tile
    int wm = (wid >> 2) * 64, wn = (wid & 3) * 64;

    // cp.async mapping: 3072 16B chunks / 256 threads = 12 per thread (j<4: A, j>=4: B)
    uint32_t doff[12];
    int      soff[12];
#pragma unroll
    for (int j = 0; j < 12; ++j) {
        int idx = tid + 256 * j;
        if (j < 4) {                 // A: 128 rows x 8 segs(16B = 8 halves)
            int row = idx >> 3, seg = idx & 7;
            soff[j] = row * K + seg * 8;
            doff[j] = TSWZ((uint32_t)(row * 128 + seg * 16));
        } else {                     // B: 256 rows x 8 segs
            int i2 = idx - 1024;
            int row = i2 >> 3, seg = i2 & 7;
            soff[j] = row * K + seg * 8;
            doff[j] = B_SMEM_OFF + TSWZ((uint32_t)(row * 128 + seg * 16));
        }
    }
    const __half* Abase = A  + (size_t)bm * K;
    const __half* Bbase = BT + (size_t)bn * K;

    // prologue: stages 0,1
#pragma unroll
    for (int p = 0; p < 2; ++p) {
        uint32_t stb = sbase + p * STAGE_BYTES;
#pragma unroll
        for (int j = 0; j < 4; ++j)  cpasync16(stb + doff[j], Abase + soff[j] + p * 64);
#pragma unroll
        for (int j = 4; j < 12; ++j) cpasync16(stb + doff[j], Bbase + soff[j] + p * 64);
        CP_COMMIT();
    }

    float acc[4][8][4];
#pragma unroll
    for (int i = 0; i < 4; ++i)
#pragma unroll
        for (int j = 0; j < 8; ++j)
#pragma unroll
            for (int e = 0; e < 4; ++e) acc[i][j][e] = 0.f;

    // per-lane ldmatrix address components
    int dr = ((lane >> 3) & 1) * 8 + (lane & 7);   // row delta within 16-row block
    int dk = ((lane >> 4) & 1) * 16;               // k-byte delta (0 or 16)

    int stage = 0;
    for (int kt = 0; kt < ntiles; ++kt) {
        asm volatile("cp.async.wait_group 1;" ::: "memory");
        __syncthreads();

        // prefetch stage kt+2
        int jt = kt + 2;
        if (jt < ntiles) {
            int ps = stage + 2; if (ps >= GSTAGES) ps -= GSTAGES;
            uint32_t stb = sbase + ps * STAGE_BYTES;
#pragma unroll
            for (int j = 0; j < 4; ++j)  cpasync16(stb + doff[j], Abase + soff[j] + jt * 64);
#pragma unroll
            for (int j = 4; j < 12; ++j) cpasync16(stb + doff[j], Bbase + soff[j] + jt * 64);
        }
        CP_COMMIT();

        uint32_t stb = sbase + stage * STAGE_BYTES;
#pragma unroll
        for (int k16 = 0; k16 < 4; ++k16) {        // 16 halves (32B) per mma step
            uint32_t kb = (uint32_t)(k16 * 32 + dk);
            uint32_t a[4][4];
#pragma unroll
            for (int i = 0; i < 4; ++i)
                ldsm_x4(a[i], stb + TSWZ((uint32_t)((wm + i * 16 + dr) * 128) + kb));
            uint32_t b[4][4];
#pragma unroll
            for (int jj = 0; jj < 4; ++jj)
                ldsm_x4(b[jj], stb + B_SMEM_OFF + TSWZ((uint32_t)((wn + jj * 16 + dr) * 128) + kb));
            // b[jj][0]=(n+0..7,k0-7)  b[jj][1]=(n+8..15,k0-7)
            // b[jj][2]=(n+0..7,k8-15) b[jj][3]=(n+8..15,k8-15)
#pragma unroll
            for (int i = 0; i < 4; ++i)
#pragma unroll
                for (int j = 0; j < 8; ++j)
                    mma_f16(acc[i][j], a[i], b[j >> 1][j & 1], b[j >> 1][(j & 1) + 2]);
        }
        if (++stage == GSTAGES) stage = 0;
    }

    // epilogue: direct register -> gmem
    int lr = lane >> 2, lc = (lane & 3) * 2;
#pragma unroll
    for (int i = 0; i < 4; ++i) {
        int r0 = bm + wm + i * 16 + lr;
        int r1 = r0 + 8;
        size_t ro0 = (size_t)r0 * N, ro1 = (size_t)r1 * N;
#pragma unroll
        for (int j = 0; j < 8; ++j) {
            int c = bn + wn + j * 8 + lc;
            float2 v0 = make_float2(acc[i][j][0], acc[i][j][1]);
            float2 v1 = make_float2(acc[i][j][2], acc[i][j][3]);
            if (EPI == 1) {
                float2 bb = *(const float2*)(bias + c);
                v0.x = gelu_f(v0.x + bb.x); v0.y = gelu_f(v0.y + bb.y);
                v1.x = gelu_f(v1.x + bb.x); v1.y = gelu_f(v1.y + bb.y);
            } else if (EPI == 2) {
                float2 ra = *(const float2*)(res + ro0 + c);
                float2 rb = *(const float2*)(res + ro1 + c);
                v0.x += ra.x; v0.y += ra.y; v1.x += rb.x; v1.y += rb.y;
            } else if (EPI == 3) {
                float2 bb = *(const float2*)(bias + c);
                float2 ra = *(const float2*)(res + ro0 + c);
                float2 rb = *(const float2*)(res + ro1 + c);
                v0.x += bb.x + ra.x; v0.y += bb.y + ra.y;
                v1.x += bb.x + rb.x; v1.y += bb.y + rb.y;
            }
            if (sizeof(OutT) == 2) {
                *(__half2*)((__half*)C + ro0 + c) = __floats2half2_rn(v0.x, v0.y);
                *(__half2*)((__half*)C + ro1 + c) = __floats2half2_rn(v1.x, v1.y);
            } else {
                *(float2*)((float*)C + ro0 + c) = v0;
                *(float2*)((float*)C + ro1 + c) = v1;
            }
        }
    }
}

template <int EPI, typename OutT>
__global__ __launch_bounds__(256, 1)
void tgemm_kernel(const __half* __restrict__ A, const __half* __restrict__ BT,
                  const float* __restrict__ bias, const float* __restrict__ res,
                  OutT* __restrict__ C, int N, int K) {
    tgemm_body<EPI, OutT>(A, BT, bias, res, C, N, K);
}

__global__ __launch_bounds__(256, 1)
void tgemm_qkv_kernel(const __half* __restrict__ h, const __half* __restrict__ wt,
                      float* __restrict__ q, float* __restrict__ k, float* __restrict__ v) {
    const __half* BT = (blockIdx.z == 0) ? (wt + WQT_OFF) : (blockIdx.z == 1) ? (wt + WKT_OFF) : (wt + WVT_OFF);
    float* C         = (blockIdx.z == 0) ? q : (blockIdx.z == 1) ? k : v;
    tgemm_body<0, float>(h, BT, nullptr, nullptr, C, DD, DD);
}

// ---------------- Flash attention (fp32, Br=Bc=64, online softmax; y out fp16) ----------------
#define QS_STRIDE 260
#define PS_STRIDE 68
#define ATTN_SMEM ((3 * 64 * QS_STRIDE + 64 * PS_STRIDE) * 4)

__global__ __launch_bounds__(256) void attn_kernel(const float* __restrict__ q,
                                                   const float* __restrict__ k,
                                                   const float* __restrict__ v,
                                                   __half* __restrict__ y) {
    extern __shared__ float sm[];
    float* Qs = sm;
    float* Ks = Qs + 64 * QS_STRIDE;
    float* Vs = Ks + 64 * QS_STRIDE;
    float* Ps = Vs + 64 * QS_STRIDE;

    int qt = blockIdx.x, hh = blockIdx.y;
    int tid = threadIdx.x, ty = tid >> 4, tx = tid & 15;
    int r0 = ty * 4, c0 = tx * 4;
    size_t hoff = (size_t)hh * DHD;

    for (int i = tid; i < 64 * 64; i += 256) {
        int row = i >> 6, c4 = i & 63;
        float4 t = *(const float4*)(q + (size_t)(qt * 64 + row) * DD + hoff + c4 * 4);
        t.x *= 0.0625f; t.y *= 0.0625f; t.z *= 0.0625f; t.w *= 0.0625f;
        *(float4*)&Qs[row * QS_STRIDE + c4 * 4] = t;
    }

    float O[4][16];
#pragma unroll
    for (int i = 0; i < 4; ++i)
#pragma unroll
        for (int cc = 0; cc < 16; ++cc) O[i][cc] = 0.f;
    float mrow[4] = {-1e30f, -1e30f, -1e30f, -1e30f};
    float lrow[4] = {0.f, 0.f, 0.f, 0.f};

    for (int kt = 0; kt <= qt; ++kt) {
        __syncthreads();
        for (int i = tid; i < 64 * 64; i += 256) {
            int row = i >> 6, c4 = i & 63;
            *(float4*)&Ks[row * QS_STRIDE + c4 * 4] =
                *(const float4*)(k + (size_t)(kt * 64 + row) * DD + hoff + c4 * 4);
            *(float4*)&Vs[row * QS_STRIDE + c4 * 4] =
                *(const float4*)(v + (size_t)(kt * 64 + row) * DD + hoff + c4 * 4);
        }
        __syncthreads();

        float S[4][4];
#pragma unroll
        for (int i = 0; i < 4; ++i)
#pragma unroll
            for (int j = 0; j < 4; ++j) S[i][j] = 0.f;

#pragma unroll 8
        for (int d4 = 0; d4 < 64; ++d4) {
            float4 qa[4], kb[4];
#pragma unroll
            for (int i = 0; i < 4; ++i) qa[i] = *(const float4*)&Qs[(r0 + i) * QS_STRIDE + d4 * 4];
#pragma unroll
            for (int j = 0; j < 4; ++j) kb[j] = *(const float4*)&Ks[(c0 + j) * QS_STRIDE + d4 * 4];
#pragma unroll
            for (int i = 0; i < 4; ++i)
#pragma unroll
                for (int j = 0; j < 4; ++j)
                    S[i][j] += qa[i].x * kb[j].x + qa[i].y * kb[j].y + qa[i].z * kb[j].z + qa[i].w * kb[j].w;
        }

        if (kt == qt) {
#pragma unroll
            for (int i = 0; i < 4; ++i)
#pragma unroll
                for (int j = 0; j < 4; ++j)
                    if (c0 + j > r0 + i) S[i][j] = -1e30f;
        }

#pragma unroll
        for (int i = 0; i < 4; ++i) {
            float tm = fmaxf(fmaxf(S[i][0], S[i][1]), fmaxf(S[i][2], S[i][3]));
            for (int o = 8; o > 0; o >>= 1) tm = fmaxf(tm, __shfl_xor_sync(~0u, tm, o, 16));
            float nm = fmaxf(mrow[i], tm);
            float alpha = expf(mrow[i] - nm);
            mrow[i] = nm;
            float rs = 0.f;
#pragma unroll
            for (int j = 0; j < 4; ++j) {
                float p = expf(S[i][j] - nm);
                S[i][j] = p;
                rs += p;
            }
            for (int o = 8; o > 0; o >>= 1) rs += __shfl_xor_sync(~0u, rs, o, 16);
            lrow[i] = lrow[i] * alpha + rs;
#pragma unroll
            for (int cc = 0; cc < 16; ++cc) O[i][cc] *= alpha;
            float4 pp;
            pp.x = S[i][0]; pp.y = S[i][1]; pp.z = S[i][2]; pp.w = S[i][3];
            *(float4*)&Ps[(r0 + i) * PS_STRIDE + c0] = pp;
        }
        __syncthreads();

#pragma unroll 4
        for (int j = 0; j < 64; ++j) {
            float pv[4];
#pragma unroll
            for (int i = 0; i < 4; ++i) pv[i] = Ps[(r0 + i) * PS_STRIDE + j];
#pragma unroll
            for (int cc = 0; cc < 16; ++cc) {
                float vv = Vs[j * QS_STRIDE + cc * 16 + tx];
#pragma unroll
                for (int i = 0; i < 4; ++i) O[i][cc] += pv[i] * vv;
            }
        }
    }

#pragma unroll
    for (int i = 0; i < 4; ++i) {
        float inv = 1.f / lrow[i];
        size_t rb = (size_t)(qt * 64 + r0 + i) * DD + hoff;
#pragma unroll
        for (int cc = 0; cc < 16; ++cc) y[rb + cc * 16 + tx] = __float2half_rn(O[i][cc] * inv);
    }
}

// ---------------- launcher ----------------
extern "C" void kernel_launch(void* const* d_in, const int* in_sizes, int n_in,
                              void* d_out, int out_size) {
    const float* x     = (const float*)d_in[0];
    const float* wq    = (const float*)d_in[1];
    const float* wk    = (const float*)d_in[2];
    const float* wv    = (const float*)d_in[3];
    const float* wo    = (const float*)d_in[4];
    const float* w_in  = (const float*)d_in[5];
    const float* b_in  = (const float*)d_in[6];
    const float* w_out = (const float*)d_in[7];
    const float* b_out = (const float*)d_in[8];
    const float* ln_s  = (const float*)d_in[9];
    const float* ln_o  = (const float*)d_in[10];
    float* out = (float*)d_out;

    __half *h, *y, *m, *wt;
    float *q, *k, *v, *tmp;
    cudaGetSymbolAddress((void**)&h,   g_h);
    cudaGetSymbolAddress((void**)&q,   g_q);
    cudaGetSymbolAddress((void**)&k,   g_k);
    cudaGetSymbolAddress((void**)&v,   g_v);
    cudaGetSymbolAddress((void**)&y,   g_y);
    cudaGetSymbolAddress((void**)&tmp, g_tmp);
    cudaGetSymbolAddress((void**)&m,   g_m);
    cudaGetSymbolAddress((void**)&wt,  g_wt);

    cudaFuncSetAttribute(attn_kernel, cudaFuncAttributeMaxDynamicSharedMemorySize, ATTN_SMEM);
    cudaFuncSetAttribute(tgemm_qkv_kernel, cudaFuncAttributeMaxDynamicSharedMemorySize, GSMEM_TOTAL);
    cudaFuncSetAttribute(tgemm_kernel<1, __half>, cudaFuncAttributeMaxDynamicSharedMemorySize, GSMEM_TOTAL);
    cudaFuncSetAttribute(tgemm_kernel<2, float>,  cudaFuncAttributeMaxDynamicSharedMemorySize, GSMEM_TOTAL);
    cudaFuncSetAttribute(tgemm_kernel<3, float>,  cudaFuncAttributeMaxDynamicSharedMemorySize, GSMEM_TOTAL);

    // 0. transpose (+ fp16 round) weights into [N,K] K-major scratch
    transpose_kernel<<<dim3(DD / 32, DD / 32), 256>>>(wq, wt + WQT_OFF, DD, DD);
    transpose_kernel<<<dim3(DD / 32, DD / 32), 256>>>(wk, wt + WKT_OFF, DD, DD);
    transpose_kernel<<<dim3(DD / 32, DD / 32), 256>>>(wv, wt + WVT_OFF, DD, DD);
    transpose_kernel<<<dim3(DD / 32, DD / 32), 256>>>(wo, wt + WOT_OFF, DD, DD);
    transpose_kernel<<<dim3(DFF / 32, DD / 32), 256>>>(w_in,  wt + WINT_OFF,  DD, DFF);
    transpose_kernel<<<dim3(DD / 32, DFF / 32), 256>>>(w_out, wt + WOUTT_OFF, DFF, DD);

    // 1. LayerNorm (fp16 output)
    ln_kernel<<<TT, 256>>>(x, ln_s, ln_o, h);
    // 2. QKV projections (fp16 mma, fp32 out)
    tgemm_qkv_kernel<<<dim3(DD / 256, TT / 128, 3), 256, GSMEM_TOTAL>>>(h, wt, q, k, v);
    // 3. RoPE on q, k
    rope_kernel<<<(TT * HH * 32) / 256, 256>>>(q, k);
    // 4. Causal flash attention (fp32 math, fp16 y)
    attn_kernel<<<dim3(TT / 64, HH), 256, ATTN_SMEM>>>(q, k, v, y);
    // 5. tmp = y @ wo + x
    tgemm_kernel<2, float><<<dim3(DD / 256, TT / 128), 256, GSMEM_TOTAL>>>(y, wt + WOT_OFF, nullptr, x, tmp, DD, DD);
    // 6. m = gelu(h @ w_in + b_in)  (fp16 out)
    tgemm_kernel<1, __half><<<dim3(DFF / 256, TT / 128), 256, GSMEM_TOTAL>>>(h, wt + WINT_OFF, b_in, nullptr, m, DFF, DD);
    // 7. out = m @ w_out + b_out + tmp
    tgemm_kernel<3, float><<<dim3(DD / 256, TT / 128), 256, GSMEM_TOTAL>>>(m, wt + WOUTT_OFF, b_out, tmp, out, DD, DFF);
}

// round 9
// speedup vs baseline: 7.2027x; 1.7240x over previous
#include <cuda_runtime.h>
#include <cuda_fp16.h>
#include <math.h>
#include <stdint.h>

// ---------------- problem constants ----------------
#define TT    2048
#define DD    4096
#define HH    16
#define DHD   256
#define DFF   16384

// ---------------- scratch (device globals; no cudaMalloc allowed) ----------------
__device__ __half g_h  [TT * DD];      // LN output
__device__ __half g_q  [TT * DD];
__device__ __half g_k  [TT * DD];
__device__ __half g_v  [TT * DD];
__device__ __half g_y  [TT * DD];      // attention output
__device__ float  g_tmp[TT * DD];
__device__ __half g_m  [TT * DFF];
__device__ __half g_wt [4u*4096u*4096u + 2u*4096u*16384u];

#define WQT_OFF   0u
#define WKT_OFF   16777216u
#define WVT_OFF   33554432u
#define WOT_OFF   50331648u
#define WINT_OFF  67108864u
#define WOUTT_OFF 134217728u

// ---------------- helpers ----------------
__device__ __forceinline__ uint32_t smem_u32(const void* p) {
    uint32_t r;
    asm("{ .reg .u64 t; cvta.to.shared.u64 t, %1; cvt.u32.u64 %0, t; }" : "=r"(r) : "l"(p));
    return r;
}
__device__ __forceinline__ void cpasync16(uint32_t dst, const void* src) {
    asm volatile("cp.async.cg.shared.global [%0], [%1], 16;" :: "r"(dst), "l"(src));
}
#define CP_COMMIT() asm volatile("cp.async.commit_group;" ::: "memory")

__device__ __forceinline__ void ldsm_x4(uint32_t (&r)[4], uint32_t addr) {
    asm volatile("ldmatrix.sync.aligned.m8n8.x4.shared.b16 {%0,%1,%2,%3}, [%4];"
        : "=r"(r[0]), "=r"(r[1]), "=r"(r[2]), "=r"(r[3]) : "r"(addr));
}
__device__ __forceinline__ void ldsm_x4_trans(uint32_t (&r)[4], uint32_t addr) {
    asm volatile("ldmatrix.sync.aligned.m8n8.x4.trans.shared.b16 {%0,%1,%2,%3}, [%4];"
        : "=r"(r[0]), "=r"(r[1]), "=r"(r[2]), "=r"(r[3]) : "r"(addr));
}
__device__ __forceinline__ void mma_f16(float (&d)[4], const uint32_t (&a)[4],
                                        uint32_t b0, uint32_t b1) {
    asm volatile("mma.sync.aligned.m16n8k16.row.col.f32.f16.f16.f32 "
        "{%0,%1,%2,%3}, {%4,%5,%6,%7}, {%8,%9}, {%0,%1,%2,%3};"
        : "+f"(d[0]), "+f"(d[1]), "+f"(d[2]), "+f"(d[3])
        : "r"(a[0]), "r"(a[1]), "r"(a[2]), "r"(a[3]), "r"(b0), "r"(b1));
}
__device__ __forceinline__ uint32_t h2pack(float x, float y) {
    __half2 h = __floats2half2_rn(x, y);
    return *(uint32_t*)&h;
}

// SW128 swizzle: bits[6:4] ^= bits[9:7]
#define TSWZ(off) ((off) ^ (((off) >> 3) & 0x70))

// ---------------- LayerNorm (fp16 output) ----------------
__global__ __launch_bounds__(256) void ln_kernel(const float* __restrict__ x,
                                                 const float* __restrict__ g,
                                                 const float* __restrict__ b,
                                                 __half* __restrict__ h) {
    int row = blockIdx.x;
    const float4* xr = (const float4*)(x + (size_t)row * DD);
    float s = 0.f, s2 = 0.f;
    for (int i = threadIdx.x; i < DD / 4; i += 256) {
        float4 v = xr[i];
        s  += v.x + v.y + v.z + v.w;
        s2 += v.x*v.x + v.y*v.y + v.z*v.z + v.w*v.w;
    }
    for (int o = 16; o > 0; o >>= 1) {
        s  += __shfl_xor_sync(~0u, s,  o);
        s2 += __shfl_xor_sync(~0u, s2, o);
    }
    __shared__ float sh[16];
    int w = threadIdx.x >> 5;
    if ((threadIdx.x & 31) == 0) { sh[w] = s; sh[8 + w] = s2; }
    __syncthreads();
    if (threadIdx.x < 32) {
        float a = threadIdx.x < 8 ? sh[threadIdx.x]     : 0.f;
        float c = threadIdx.x < 8 ? sh[8 + threadIdx.x] : 0.f;
        for (int o = 4; o > 0; o >>= 1) {
            a += __shfl_xor_sync(~0u, a, o);
            c += __shfl_xor_sync(~0u, c, o);
        }
        if (threadIdx.x == 0) { sh[0] = a; sh[8] = c; }
    }
    __syncthreads();
    float mean = sh[0] * (1.f / DD);
    float var  = sh[8] * (1.f / DD) - mean * mean;
    float rstd = rsqrtf(var + 1e-6f);
    __half2* hr = (__half2*)(h + (size_t)row * DD);
    const float4* gg4 = (const float4*)g;
    const float4* bb4 = (const float4*)b;
    for (int i = threadIdx.x; i < DD / 4; i += 256) {
        float4 v = xr[i], gg = gg4[i], bb = bb4[i];
        hr[i * 2]     = __floats2half2_rn((v.x - mean) * rstd * gg.x + bb.x,
                                          (v.y - mean) * rstd * gg.y + bb.y);
        hr[i * 2 + 1] = __floats2half2_rn((v.z - mean) * rstd * gg.z + bb.z,
                                          (v.w - mean) * rstd * gg.w + bb.w);
    }
}

// ---------------- weight transpose [R,C] fp32 -> [C,R] fp16 ----------------
__global__ __launch_bounds__(256) void transpose_kernel(const float* __restrict__ in,
                                                        __half* __restrict__ out, int R, int C) {
    __shared__ float t[32][33];
    int bx = blockIdx.x * 32, by = blockIdx.y * 32;
    int tx = threadIdx.x & 31, ty = threadIdx.x >> 5;
#pragma unroll
    for (int i = 0; i < 32; i += 8)
        t[ty + i][tx] = in[(size_t)(by + ty + i) * C + bx + tx];
    __syncthreads();
#pragma unroll
    for (int i = 0; i < 32; i += 8)
        out[(size_t)(bx + ty + i) * R + by + tx] = __float2half_rn(t[tx][ty + i]);
}

// ---------------- RoPE in-place on fp16 q, k ----------------
__global__ __launch_bounds__(256) void rope_kernel(__half* __restrict__ q, __half* __restrict__ k) {
    int idx = blockIdx.x * 256 + threadIdx.x;
    int f = idx & 31;
    int hh = (idx >> 5) & (HH - 1);
    int t = idx >> 9;
    float inv = 1.0f / powf(10000.0f, (float)f * (1.0f / 32.0f));
    float ang = (float)t * inv;
    float sn, cs;
    sincosf(ang, &sn, &cs);
    size_t base = (size_t)t * DD + hh * DHD + f;
    {
        float a = __half2float(q[base]), b = __half2float(q[base + 32]);
        q[base]      = __float2half_rn(a * cs - b * sn);
        q[base + 32] = __float2half_rn(a * sn + b * cs);
    }
    {
        float a = __half2float(k[base]), b = __half2float(k[base + 32]);
        k[base]      = __float2half_rn(a * cs - b * sn);
        k[base + 32] = __float2half_rn(a * sn + b * cs);
    }
}

// ---------------- fp16 mma GEMM (unchanged from R8) ----------------
__device__ __forceinline__ float gelu_f(float v) {
    float t = tanhf(0.7978845608028654f * (v + 0.044715f * v * v * v));
    return 0.5f * v * (1.f + t);
}

#define STAGE_BYTES 49152
#define B_SMEM_OFF  16384
#define GSTAGES 3
#define GSMEM_TOTAL (GSTAGES * STAGE_BYTES)

template <int EPI, typename OutT>
__device__ __forceinline__ void tgemm_body(const __half* __restrict__ A, const __half* __restrict__ BT,
                                           const float* __restrict__ bias, const float* __restrict__ res,
                                           OutT* __restrict__ C, int N, int K) {
    extern __shared__ __align__(1024) char gsm[];
    uint32_t sbase = smem_u32(gsm);
    int tid = threadIdx.x, lane = tid & 31, wid = tid >> 5;
    int bm = blockIdx.y * 128, bn = blockIdx.x * 256;
    int ntiles = K >> 6;
    int wm = (wid >> 2) * 64, wn = (wid & 3) * 64;

    uint32_t doff[12];
    int      soff[12];
#pragma unroll
    for (int j = 0; j < 12; ++j) {
        int idx = tid + 256 * j;
        if (j < 4) {
            int row = idx >> 3, seg = idx & 7;
            soff[j] = row * K + seg * 8;
            doff[j] = TSWZ((uint32_t)(row * 128 + seg * 16));
        } else {
            int i2 = idx - 1024;
            int row = i2 >> 3, seg = i2 & 7;
            soff[j] = row * K + seg * 8;
            doff[j] = B_SMEM_OFF + TSWZ((uint32_t)(row * 128 + seg * 16));
        }
    }
    const __half* Abase = A  + (size_t)bm * K;
    const __half* Bbase = BT + (size_t)bn * K;

#pragma unroll
    for (int p = 0; p < 2; ++p) {
        uint32_t stb = sbase + p * STAGE_BYTES;
#pragma unroll
        for (int j = 0; j < 4; ++j)  cpasync16(stb + doff[j], Abase + soff[j] + p * 64);
#pragma unroll
        for (int j = 4; j < 12; ++j) cpasync16(stb + doff[j], Bbase + soff[j] + p * 64);
        CP_COMMIT();
    }

    float acc[4][8][4];
#pragma unroll
    for (int i = 0; i < 4; ++i)
#pragma unroll
        for (int j = 0; j < 8; ++j)
#pragma unroll
            for (int e = 0; e < 4; ++e) acc[i][j][e] = 0.f;

    int dr = ((lane >> 3) & 1) * 8 + (lane & 7);
    int dk = ((lane >> 4) & 1) * 16;

    int stage = 0;
    for (int kt = 0; kt < ntiles; ++kt) {
        asm volatile("cp.async.wait_group 1;" ::: "memory");
        __syncthreads();

        int jt = kt + 2;
        if (jt < ntiles) {
            int ps = stage + 2; if (ps >= GSTAGES) ps -= GSTAGES;
            uint32_t stb = sbase + ps * STAGE_BYTES;
#pragma unroll
            for (int j = 0; j < 4; ++j)  cpasync16(stb + doff[j], Abase + soff[j] + jt * 64);
#pragma unroll
            for (int j = 4; j < 12; ++j) cpasync16(stb + doff[j], Bbase + soff[j] + jt * 64);
        }
        CP_COMMIT();

        uint32_t stb = sbase + stage * STAGE_BYTES;
#pragma unroll
        for (int k16 = 0; k16 < 4; ++k16) {
            uint32_t kb = (uint32_t)(k16 * 32 + dk);
            uint32_t a[4][4];
#pragma unroll
            for (int i = 0; i < 4; ++i)
                ldsm_x4(a[i], stb + TSWZ((uint32_t)((wm + i * 16 + dr) * 128) + kb));
            uint32_t b[4][4];
#pragma unroll
            for (int jj = 0; jj < 4; ++jj)
                ldsm_x4(b[jj], stb + B_SMEM_OFF + TSWZ((uint32_t)((wn + jj * 16 + dr) * 128) + kb));
#pragma unroll
            for (int i = 0; i < 4; ++i)
#pragma unroll
                for (int j = 0; j < 8; ++j)
                    mma_f16(acc[i][j], a[i], b[j >> 1][j & 1], b[j >> 1][(j & 1) + 2]);
        }
        if (++stage == GSTAGES) stage = 0;
    }

    int lr = lane >> 2, lc = (lane & 3) * 2;
#pragma unroll
    for (int i = 0; i < 4; ++i) {
        int r0 = bm + wm + i * 16 + lr;
        int r1 = r0 + 8;
        size_t ro0 = (size_t)r0 * N, ro1 = (size_t)r1 * N;
#pragma unroll
        for (int j = 0; j < 8; ++j) {
            int c = bn + wn + j * 8 + lc;
            float2 v0 = make_float2(acc[i][j][0], acc[i][j][1]);
            float2 v1 = make_float2(acc[i][j][2], acc[i][j][3]);
            if (EPI == 1) {
                float2 bb = *(const float2*)(bias + c);
                v0.x = gelu_f(v0.x + bb.x); v0.y = gelu_f(v0.y + bb.y);
                v1.x = gelu_f(v1.x + bb.x); v1.y = gelu_f(v1.y + bb.y);
            } else if (EPI == 2) {
                float2 ra = *(const float2*)(res + ro0 + c);
                float2 rb = *(const float2*)(res + ro1 + c);
                v0.x += ra.x; v0.y += ra.y; v1.x += rb.x; v1.y += rb.y;
            } else if (EPI == 3) {
                float2 bb = *(const float2*)(bias + c);
                float2 ra = *(const float2*)(res + ro0 + c);
                float2 rb = *(const float2*)(res + ro1 + c);
                v0.x += bb.x + ra.x; v0.y += bb.y + ra.y;
                v1.x += bb.x + rb.x; v1.y += bb.y + rb.y;
            }
            if (sizeof(OutT) == 2) {
                *(__half2*)((__half*)C + ro0 + c) = __floats2half2_rn(v0.x, v0.y);
                *(__half2*)((__half*)C + ro1 + c) = __floats2half2_rn(v1.x, v1.y);
            } else {
                *(float2*)((float*)C + ro0 + c) = v0;
                *(float2*)((float*)C + ro1 + c) = v1;
            }
        }
    }
}

template <int EPI, typename OutT>
__global__ __launch_bounds__(256, 1)
void tgemm_kernel(const __half* __restrict__ A, const __half* __restrict__ BT,
                  const float* __restrict__ bias, const float* __restrict__ res,
                  OutT* __restrict__ C, int N, int K) {
    tgemm_body<EPI, OutT>(A, BT, bias, res, C, N, K);
}

__global__ __launch_bounds__(256, 1)
void tgemm_qkv_kernel(const __half* __restrict__ h, const __half* __restrict__ wt,
                      __half* __restrict__ q, __half* __restrict__ k, __half* __restrict__ v) {
    const __half* BT = (blockIdx.z == 0) ? (wt + WQT_OFF) : (blockIdx.z == 1) ? (wt + WKT_OFF) : (wt + WVT_OFF);
    __half* C        = (blockIdx.z == 0) ? q : (blockIdx.z == 1) ? k : v;
    tgemm_body<0, __half>(h, BT, nullptr, nullptr, C, DD, DD);
}

// ---------------- fp16 mma flash attention ----------------
// CTA: 64 q-rows x 1 head, 128 threads (4 warps x 16 rows), Bc=64, dh=256.
// smem tiles: rows of 256 halves padded to 264 (528B) -> conflict-free ldsm.
#define AT_ROWB   528                       // bytes per smem tile row
#define AT_BYTES  (64 * AT_ROWB)            // 33792 per tile
#define ATTN_SMEM (5 * AT_BYTES)            // Q + 2xK + 2xV = 168960

__device__ __forceinline__ void attn_load_tile(uint32_t dstb, const __half* src, int tid) {
#pragma unroll
    for (int j = 0; j < 16; ++j) {
        int idx = tid + 128 * j;
        int row = idx >> 5, seg = idx & 31;
        cpasync16(dstb + row * AT_ROWB + seg * 16, src + (size_t)row * DD + seg * 8);
    }
}

__global__ __launch_bounds__(128, 1) void attn_kernel(const __half* __restrict__ q,
                                                      const __half* __restrict__ k,
                                                      const __half* __restrict__ v,
                                                      __half* __restrict__ y) {
    extern __shared__ __align__(1024) char asmem[];
    uint32_t sb = smem_u32(asmem);
    int tid = threadIdx.x, lane = tid & 31, wid = tid >> 5;
    int qt = gridDim.x - 1 - blockIdx.x;     // heavy tiles first
    int hh = blockIdx.y;
    size_t hoff = (size_t)hh * DHD;

    uint32_t Qb = sb;
    uint32_t Kb[2] = { sb + AT_BYTES, sb + 2 * AT_BYTES };
    uint32_t Vb[2] = { sb + 3 * AT_BYTES, sb + 4 * AT_BYTES };

    const __half* qsrc = q + (size_t)(qt * 64) * DD + hoff;

    // prologue: Q + K0/V0, then K1/V1
    attn_load_tile(Qb, qsrc, tid);
    attn_load_tile(Kb[0], k + hoff, tid);
    attn_load_tile(Vb[0], v + hoff, tid);
    CP_COMMIT();
    if (qt >= 1) {
        attn_load_tile(Kb[1], k + (size_t)64 * DD + hoff, tid);
        attn_load_tile(Vb[1], v + (size_t)64 * DD + hoff, tid);
    }
    CP_COMMIT();

    float o[32][4];
#pragma unroll
    for (int j = 0; j < 32; ++j)
#pragma unroll
        for (int e = 0; e < 4; ++e) o[j][e] = 0.f;
    float m0 = -1e30f, m1 = -1e30f, l0 = 0.f, l1 = 0.f;

    int dr = ((lane >> 3) & 1) * 8 + (lane & 7);
    int dk = ((lane >> 4) & 1) * 16;
    int wm = wid * 16;
    int lr = lane >> 2, lc = (lane & 3) * 2;
    // V trans-ldsm per-lane address components
    int vmI = lane >> 3, vii = lane & 7;
    int vsrow = (vmI & 1) * 8 + vii;          // + 16*t
    int vcolb = (vmI >> 1) * 16;              // + np*32 (bytes)

    for (int kt = 0; kt <= qt; ++kt) {
        asm volatile("cp.async.wait_group 1;" ::: "memory");
        __syncthreads();
        uint32_t Kt = Kb[kt & 1], Vt = Vb[kt & 1];

        // ---- S = Q K^T (64x64), warp computes 16x64 ----
        float s[8][4];
#pragma unroll
        for (int j = 0; j < 8; ++j)
#pragma unroll
            for (int e = 0; e < 4; ++e) s[j][e] = 0.f;

#pragma unroll
        for (int k16 = 0; k16 < 16; ++k16) {
            uint32_t kb = (uint32_t)(k16 * 32 + dk);
            uint32_t a[4];
            ldsm_x4(a, Qb + (uint32_t)((wm + dr) * AT_ROWB) + kb);
#pragma unroll
            for (int jj = 0; jj < 4; ++jj) {
                uint32_t b[4];
                ldsm_x4(b, Kt + (uint32_t)((jj * 16 + dr) * AT_ROWB) + kb);
                mma_f16(s[2 * jj],     a, b[0], b[2]);
                mma_f16(s[2 * jj + 1], a, b[1], b[3]);
            }
        }

        // scale + causal mask (diagonal tile only)
#pragma unroll
        for (int j = 0; j < 8; ++j)
#pragma unroll
            for (int e = 0; e < 4; ++e) s[j][e] *= 0.0625f;
        if (kt == qt) {
#pragma unroll
            for (int j = 0; j < 8; ++j)
#pragma unroll
                for (int e = 0; e < 4; ++e) {
                    int col = 8 * j + lc + (e & 1);
                    int row = wm + lr + ((e >> 1) << 3);
                    if (col > row) s[j][e] = -1e30f;
                }
        }

        // ---- online softmax (rows lr, lr+8) ----
        float tm0 = -1e30f, tm1 = -1e30f;
#pragma unroll
        for (int j = 0; j < 8; ++j) {
            tm0 = fmaxf(tm0, fmaxf(s[j][0], s[j][1]));
            tm1 = fmaxf(tm1, fmaxf(s[j][2], s[j][3]));
        }
        tm0 = fmaxf(tm0, __shfl_xor_sync(~0u, tm0, 1));
        tm0 = fmaxf(tm0, __shfl_xor_sync(~0u, tm0, 2));
        tm1 = fmaxf(tm1, __shfl_xor_sync(~0u, tm1, 1));
        tm1 = fmaxf(tm1, __shfl_xor_sync(~0u, tm1, 2));
        float nm0 = fmaxf(m0, tm0), nm1 = fmaxf(m1, tm1);
        float al0 = __expf(m0 - nm0), al1 = __expf(m1 - nm1);
        m0 = nm0; m1 = nm1;
        float rs0 = 0.f, rs1 = 0.f;
#pragma unroll
        for (int j = 0; j < 8; ++j) {
            s[j][0] = __expf(s[j][0] - nm0);
            s[j][1] = __expf(s[j][1] - nm0);
            s[j][2] = __expf(s[j][2] - nm1);
            s[j][3] = __expf(s[j][3] - nm1);
            rs0 += s[j][0] + s[j][1];
            rs1 += s[j][2] + s[j][3];
        }
        rs0 += __shfl_xor_sync(~0u, rs0, 1); rs0 += __shfl_xor_sync(~0u, rs0, 2);
        rs1 += __shfl_xor_sync(~0u, rs1, 1); rs1 += __shfl_xor_sync(~0u, rs1, 2);
        l0 = l0 * al0 + rs0;
        l1 = l1 * al1 + rs1;
#pragma unroll
        for (int j = 0; j < 32; ++j) {
            o[j][0] *= al0; o[j][1] *= al0;
            o[j][2] *= al1; o[j][3] *= al1;
        }

        // ---- O += P V  (P from regs, V via trans ldsm) ----
#pragma unroll
        for (int t = 0; t < 4; ++t) {
            uint32_t pa[4];
            pa[0] = h2pack(s[2 * t][0],     s[2 * t][1]);
            pa[1] = h2pack(s[2 * t][2],     s[2 * t][3]);
            pa[2] = h2pack(s[2 * t + 1][0], s[2 * t + 1][1]);
            pa[3] = h2pack(s[2 * t + 1][2], s[2 * t + 1][3]);
            uint32_t vrow = (uint32_t)((16 * t + vsrow) * AT_ROWB);
#pragma unroll
            for (int np = 0; np < 16; ++np) {
                uint32_t bb[4];
                ldsm_x4_trans(bb, Vt + vrow + (uint32_t)(np * 32 + vcolb));
                mma_f16(o[2 * np],     pa, bb[0], bb[1]);
                mma_f16(o[2 * np + 1], pa, bb[2], bb[3]);
            }
        }

        __syncthreads();
        int jt = kt + 2;
        if (jt <= qt) {
            attn_load_tile(Kb[kt & 1], k + (size_t)(jt * 64) * DD + hoff, tid);
            attn_load_tile(Vb[kt & 1], v + (size_t)(jt * 64) * DD + hoff, tid);
        }
        CP_COMMIT();
    }

    // ---- write O / l ----
    float inv0 = 1.f / l0, inv1 = 1.f / l1;
    size_t r0 = (size_t)(qt * 64 + wm + lr) * DD + hoff;
    size_t r1 = r0 + (size_t)8 * DD;
#pragma unroll
    for (int j = 0; j < 32; ++j) {
        *(__half2*)(y + r0 + 8 * j + lc) = __floats2half2_rn(o[j][0] * inv0, o[j][1] * inv0);
        *(__half2*)(y + r1 + 8 * j + lc) = __floats2half2_rn(o[j][2] * inv1, o[j][3] * inv1);
    }
}

// ---------------- launcher ----------------
extern "C" void kernel_launch(void* const* d_in, const int* in_sizes, int n_in,
                              void* d_out, int out_size) {
    const float* x     = (const float*)d_in[0];
    const float* wq    = (const float*)d_in[1];
    const float* wk    = (const float*)d_in[2];
    const float* wv    = (const float*)d_in[3];
    const float* wo    = (const float*)d_in[4];
    const float* w_in  = (const float*)d_in[5];
    const float* b_in  = (const float*)d_in[6];
    const float* w_out = (const float*)d_in[7];
    const float* b_out = (const float*)d_in[8];
    const float* ln_s  = (const float*)d_in[9];
    const float* ln_o  = (const float*)d_in[10];
    float* out = (float*)d_out;

    __half *h, *q, *k, *v, *y, *m, *wt;
    float *tmp;
    cudaGetSymbolAddress((void**)&h,   g_h);
    cudaGetSymbolAddress((void**)&q,   g_q);
    cudaGetSymbolAddress((void**)&k,   g_k);
    cudaGetSymbolAddress((void**)&v,   g_v);
    cudaGetSymbolAddress((void**)&y,   g_y);
    cudaGetSymbolAddress((void**)&tmp, g_tmp);
    cudaGetSymbolAddress((void**)&m,   g_m);
    cudaGetSymbolAddress((void**)&wt,  g_wt);

    cudaFuncSetAttribute(attn_kernel, cudaFuncAttributeMaxDynamicSharedMemorySize, ATTN_SMEM);
    cudaFuncSetAttribute(tgemm_qkv_kernel, cudaFuncAttributeMaxDynamicSharedMemorySize, GSMEM_TOTAL);
    cudaFuncSetAttribute(tgemm_kernel<1, __half>, cudaFuncAttributeMaxDynamicSharedMemorySize, GSMEM_TOTAL);
    cudaFuncSetAttribute(tgemm_kernel<2, float>,  cudaFuncAttributeMaxDynamicSharedMemorySize, GSMEM_TOTAL);
    cudaFuncSetAttribute(tgemm_kernel<3, float>,  cudaFuncAttributeMaxDynamicSharedMemorySize, GSMEM_TOTAL);

    // 0. transpose (+ fp16 round) weights into [N,K] K-major scratch
    transpose_kernel<<<dim3(DD / 32, DD / 32), 256>>>(wq, wt + WQT_OFF, DD, DD);
    transpose_kernel<<<dim3(DD / 32, DD / 32), 256>>>(wk, wt + WKT_OFF, DD, DD);
    transpose_kernel<<<dim3(DD / 32, DD / 32), 256>>>(wv, wt + WVT_OFF, DD, DD);
    transpose_kernel<<<dim3(DD / 32, DD / 32), 256>>>(wo, wt + WOT_OFF, DD, DD);
    transpose_kernel<<<dim3(DFF / 32, DD / 32), 256>>>(w_in,  wt + WINT_OFF,  DD, DFF);
    transpose_kernel<<<dim3(DD / 32, DFF / 32), 256>>>(w_out, wt + WOUTT_OFF, DFF, DD);

    // 1. LayerNorm (fp16 output)
    ln_kernel<<<TT, 256>>>(x, ln_s, ln_o, h);
    // 2. QKV projections (fp16 out)
    tgemm_qkv_kernel<<<dim3(DD / 256, TT / 128, 3), 256, GSMEM_TOTAL>>>(h, wt, q, k, v);
    // 3. RoPE on q, k (fp16)
    rope_kernel<<<(TT * HH * 32) / 256, 256>>>(q, k);
    // 4. Causal flash attention (fp16 mma)
    attn_kernel<<<dim3(TT / 64, HH), 128, ATTN_SMEM>>>(q, k, v, y);
    // 5. tmp = y @ wo + x
    tgemm_kernel<2, float><<<dim3(DD / 256, TT / 128), 256, GSMEM_TOTAL>>>(y, wt + WOT_OFF, nullptr, x, tmp, DD, DD);
    // 6. m = gelu(h @ w_in + b_in)  (fp16 out)
    tgemm_kernel<1, __half><<<dim3(DFF / 256, TT / 128), 256, GSMEM_TOTAL>>>(h, wt + WINT_OFF, b_in, nullptr, m, DFF, DD);
    // 7. out = m @ w_out + b_out + tmp
    tgemm_kernel<3, float><<<dim3(DD / 256, TT / 128), 256, GSMEM_TOTAL>>>(m, wt + WOUTT_OFF, b_out, tmp, out, DD, DFF);
}

// round 10
// speedup vs baseline: 8.6516x; 1.2012x over previous
#include <cuda_runtime.h>
#include <cuda_fp16.h>
#include <math.h>
#include <stdint.h>

// ---------------- problem constants ----------------
#define TT    2048
#define DD    4096
#define HH    16
#define DHD   256
#define DFF   16384

// ---------------- scratch (device globals; no cudaMalloc allowed) ----------------
__device__ __half g_h  [TT * DD];      // LN output
__device__ __half g_q  [TT * DD];
__device__ __half g_k  [TT * DD];
__device__ __half g_v  [TT * DD];
__device__ __half g_y  [TT * DD];      // attention output
__device__ float  g_tmp[TT * DD];
__device__ __half g_m  [TT * DFF];
// fp16 weights in NATIVE [K,N] layout (converted, not transposed)
__device__ __half g_wt [4u*4096u*4096u + 2u*4096u*16384u];

#define WQ_OFF    0u
#define WK_OFF    16777216u
#define WV_OFF    33554432u
#define WO_OFF    50331648u
#define WIN_OFF   67108864u
#define WOUT_OFF  134217728u

// ---------------- helpers ----------------
__device__ __forceinline__ uint32_t smem_u32(const void* p) {
    uint32_t r;
    asm("{ .reg .u64 t; cvta.to.shared.u64 t, %1; cvt.u32.u64 %0, t; }" : "=r"(r) : "l"(p));
    return r;
}
__device__ __forceinline__ void cpasync16(uint32_t dst, const void* src) {
    asm volatile("cp.async.cg.shared.global [%0], [%1], 16;" :: "r"(dst), "l"(src));
}
#define CP_COMMIT() asm volatile("cp.async.commit_group;" ::: "memory")

__device__ __forceinline__ void ldsm_x4(uint32_t (&r)[4], uint32_t addr) {
    asm volatile("ldmatrix.sync.aligned.m8n8.x4.shared.b16 {%0,%1,%2,%3}, [%4];"
        : "=r"(r[0]), "=r"(r[1]), "=r"(r[2]), "=r"(r[3]) : "r"(addr));
}
__device__ __forceinline__ void ldsm_x4_trans(uint32_t (&r)[4], uint32_t addr) {
    asm volatile("ldmatrix.sync.aligned.m8n8.x4.trans.shared.b16 {%0,%1,%2,%3}, [%4];"
        : "=r"(r[0]), "=r"(r[1]), "=r"(r[2]), "=r"(r[3]) : "r"(addr));
}
__device__ __forceinline__ void mma_f16(float (&d)[4], const uint32_t (&a)[4],
                                        uint32_t b0, uint32_t b1) {
    asm volatile("mma.sync.aligned.m16n8k16.row.col.f32.f16.f16.f32 "
        "{%0,%1,%2,%3}, {%4,%5,%6,%7}, {%8,%9}, {%0,%1,%2,%3};"
        : "+f"(d[0]), "+f"(d[1]), "+f"(d[2]), "+f"(d[3])
        : "r"(a[0]), "r"(a[1]), "r"(a[2]), "r"(a[3]), "r"(b0), "r"(b1));
}
__device__ __forceinline__ uint32_t h2pack(float x, float y) {
    __half2 h = __floats2half2_rn(x, y);
    return *(uint32_t*)&h;
}

// swizzles: 128B-row tiles (A) and 512B-row tiles (B)
#define TSWZ(off)   ((off) ^ (((off) >> 3) & 0x70))
#define SWZ512(off) ((off) ^ (((off) >> 5) & 0x70))

// ---------------- LayerNorm (fp16 output) ----------------
__global__ __launch_bounds__(256) void ln_kernel(const float* __restrict__ x,
                                                 const float* __restrict__ g,
                                                 const float* __restrict__ b,
                                                 __half* __restrict__ h) {
    int row = blockIdx.x;
    const float4* xr = (const float4*)(x + (size_t)row * DD);
    float s = 0.f, s2 = 0.f;
    for (int i = threadIdx.x; i < DD / 4; i += 256) {
        float4 v = xr[i];
        s  += v.x + v.y + v.z + v.w;
        s2 += v.x*v.x + v.y*v.y + v.z*v.z + v.w*v.w;
    }
    for (int o = 16; o > 0; o >>= 1) {
        s  += __shfl_xor_sync(~0u, s,  o);
        s2 += __shfl_xor_sync(~0u, s2, o);
    }
    __shared__ float sh[16];
    int w = threadIdx.x >> 5;
    if ((threadIdx.x & 31) == 0) { sh[w] = s; sh[8 + w] = s2; }
    __syncthreads();
    if (threadIdx.x < 32) {
        float a = threadIdx.x < 8 ? sh[threadIdx.x]     : 0.f;
        float c = threadIdx.x < 8 ? sh[8 + threadIdx.x] : 0.f;
        for (int o = 4; o > 0; o >>= 1) {
            a += __shfl_xor_sync(~0u, a, o);
            c += __shfl_xor_sync(~0u, c, o);
        }
        if (threadIdx.x == 0) { sh[0] = a; sh[8] = c; }
    }
    __syncthreads();
    float mean = sh[0] * (1.f / DD);
    float var  = sh[8] * (1.f / DD) - mean * mean;
    float rstd = rsqrtf(var + 1e-6f);
    __half2* hr = (__half2*)(h + (size_t)row * DD);
    const float4* gg4 = (const float4*)g;
    const float4* bb4 = (const float4*)b;
    for (int i = threadIdx.x; i < DD / 4; i += 256) {
        float4 v = xr[i], gg = gg4[i], bb = bb4[i];
        hr[i * 2]     = __floats2half2_rn((v.x - mean) * rstd * gg.x + bb.x,
                                          (v.y - mean) * rstd * gg.y + bb.y);
        hr[i * 2 + 1] = __floats2half2_rn((v.z - mean) * rstd * gg.z + bb.z,
                                          (v.w - mean) * rstd * gg.w + bb.w);
    }
}

// ---------------- streaming fp32 -> fp16 convert (layout preserved) ----------------
__global__ __launch_bounds__(256) void convert_kernel(const float4* __restrict__ in,
                                                      __half2* __restrict__ out) {
    int i = blockIdx.x * 256 + threadIdx.x;
    float4 v = in[i];
    out[2 * i]     = __floats2half2_rn(v.x, v.y);
    out[2 * i + 1] = __floats2half2_rn(v.z, v.w);
}

// ---------------- RoPE in-place on fp16 q, k ----------------
__global__ __launch_bounds__(256) void rope_kernel(__half* __restrict__ q, __half* __restrict__ k) {
    int idx = blockIdx.x * 256 + threadIdx.x;
    int f = idx & 31;
    int hh = (idx >> 5) & (HH - 1);
    int t = idx >> 9;
    float inv = 1.0f / powf(10000.0f, (float)f * (1.0f / 32.0f));
    float ang = (float)t * inv;
    float sn, cs;
    sincosf(ang, &sn, &cs);
    size_t base = (size_t)t * DD + hh * DHD + f;
    {
        float a = __half2float(q[base]), b = __half2float(q[base + 32]);
        q[base]      = __float2half_rn(a * cs - b * sn);
        q[base + 32] = __float2half_rn(a * sn + b * cs);
    }
    {
        float a = __half2float(k[base]), b = __half2float(k[base + 32]);
        k[base]      = __float2half_rn(a * cs - b * sn);
        k[base + 32] = __float2half_rn(a * sn + b * cs);
    }
}

// ---------------- fp16 mma GEMM: CTA 128x256, warp 64x64, B native [K,N] via trans-ldsm ----------------
__device__ __forceinline__ float gelu_f(float v) {
    float t = tanhf(0.7978845608028654f * (v + 0.044715f * v * v * v));
    return 0.5f * v * (1.f + t);
}

#define STAGE_BYTES 49152            // A 16KB (128m x 128B) + B 32KB (64k x 512B)
#define B_SMEM_OFF  16384
#define GSTAGES 3
#define GSMEM_TOTAL (GSTAGES * STAGE_BYTES)

template <int EPI, typename OutT>
__device__ __forceinline__ void tgemm_body(const __half* __restrict__ A, const __half* __restrict__ B,
                                           const float* __restrict__ bias, const float* __restrict__ res,
                                           OutT* __restrict__ C, int N, int K) {
    extern __shared__ __align__(1024) char gsm[];
    uint32_t sbase = smem_u32(gsm);
    int tid = threadIdx.x, lane = tid & 31, wid = tid >> 5;
    int bm = blockIdx.y * 128, bn = blockIdx.x * 256;
    int ntiles = K >> 6;
    int wm = (wid >> 2) * 64, wn = (wid & 3) * 64;

    // A chunks: 1024 (128 rows x 8 segs of 16B); B chunks: 2048 (64 k-rows x 32 segs of 16B)
    uint32_t doffA[4]; int soffA[4];
#pragma unroll
    for (int j = 0; j < 4; ++j) {
        int idx = tid + 256 * j;
        int row = idx >> 3, seg = idx & 7;
        soffA[j] = row * K + seg * 8;
        doffA[j] = TSWZ((uint32_t)(row * 128 + seg * 16));
    }
    uint32_t doffB[8]; size_t soffB[8];
#pragma unroll
    for (int j = 0; j < 8; ++j) {
        int idx = tid + 256 * j;
        int krow = idx >> 5, seg = idx & 31;
        soffB[j] = (size_t)krow * N + seg * 8;
        doffB[j] = B_SMEM_OFF + SWZ512((uint32_t)(krow * 512 + seg * 16));
    }
    const __half* Abase = A + (size_t)bm * K;
    const __half* Bbase = B + bn;

#pragma unroll
    for (int p = 0; p < 2; ++p) {
        uint32_t stb = sbase + p * STAGE_BYTES;
#pragma unroll
        for (int j = 0; j < 4; ++j) cpasync16(stb + doffA[j], Abase + soffA[j] + p * 64);
#pragma unroll
        for (int j = 0; j < 8; ++j) cpasync16(stb + doffB[j], Bbase + soffB[j] + (size_t)p * 64 * N);
        CP_COMMIT();
    }

    float acc[4][8][4];
#pragma unroll
    for (int i = 0; i < 4; ++i)
#pragma unroll
        for (int j = 0; j < 8; ++j)
#pragma unroll
            for (int e = 0; e < 4; ++e) acc[i][j][e] = 0.f;

    // A ldsm lane addressing
    int dr = ((lane >> 3) & 1) * 8 + (lane & 7);
    int dk = ((lane >> 4) & 1) * 16;
    // B trans-ldsm lane addressing (identical to validated attention V path)
    int vmI = lane >> 3, vii = lane & 7;
    int vsrow = (vmI & 1) * 8 + vii;
    int vcolb = (vmI >> 1) * 16;

    int stage = 0;
    for (int kt = 0; kt < ntiles; ++kt) {
        asm volatile("cp.async.wait_group 1;" ::: "memory");
        __syncthreads();

        int jt = kt + 2;
        if (jt < ntiles) {
            int ps = stage + 2; if (ps >= GSTAGES) ps -= GSTAGES;
            uint32_t stb = sbase + ps * STAGE_BYTES;
#pragma unroll
            for (int j = 0; j < 4; ++j) cpasync16(stb + doffA[j], Abase + soffA[j] + jt * 64);
#pragma unroll
            for (int j = 0; j < 8; ++j) cpasync16(stb + doffB[j], Bbase + soffB[j] + (size_t)jt * 64 * N);
        }
        CP_COMMIT();

        uint32_t stb = sbase + stage * STAGE_BYTES;
#pragma unroll
        for (int k16 = 0; k16 < 4; ++k16) {
            uint32_t a[4][4];
#pragma unroll
            for (int i = 0; i < 4; ++i)
                ldsm_x4(a[i], stb + TSWZ((uint32_t)((wm + i * 16 + dr) * 128) + (uint32_t)(k16 * 32 + dk)));
            uint32_t b[4][4];
#pragma unroll
            for (int jj = 0; jj < 4; ++jj) {
                uint32_t off = (uint32_t)((k16 * 16 + vsrow) * 512 + (wn + jj * 16) * 2 + vcolb);
                ldsm_x4_trans(b[jj], stb + B_SMEM_OFF + SWZ512(off));
            }
            // b[jj][0],b[jj][1] -> n-slice jj*16..+8 ; b[jj][2],b[jj][3] -> +8..+16
#pragma unroll
            for (int i = 0; i < 4; ++i)
#pragma unroll
                for (int jj = 0; jj < 4; ++jj) {
                    mma_f16(acc[i][2 * jj],     a[i], b[jj][0], b[jj][1]);
                    mma_f16(acc[i][2 * jj + 1], a[i], b[jj][2], b[jj][3]);
                }
        }
        if (++stage == GSTAGES) stage = 0;
    }

    int lr = lane >> 2, lc = (lane & 3) * 2;
#pragma unroll
    for (int i = 0; i < 4; ++i) {
        int r0 = bm + wm + i * 16 + lr;
        int r1 = r0 + 8;
        size_t ro0 = (size_t)r0 * N, ro1 = (size_t)r1 * N;
#pragma unroll
        for (int j = 0; j < 8; ++j) {
            int c = bn + wn + j * 8 + lc;
            float2 v0 = make_float2(acc[i][j][0], acc[i][j][1]);
            float2 v1 = make_float2(acc[i][j][2], acc[i][j][3]);
            if (EPI == 1) {
                float2 bb = *(const float2*)(bias + c);
                v0.x = gelu_f(v0.x + bb.x); v0.y = gelu_f(v0.y + bb.y);
                v1.x = gelu_f(v1.x + bb.x); v1.y = gelu_f(v1.y + bb.y);
            } else if (EPI == 2) {
                float2 ra = *(const float2*)(res + ro0 + c);
                float2 rb = *(const float2*)(res + ro1 + c);
                v0.x += ra.x; v0.y += ra.y; v1.x += rb.x; v1.y += rb.y;
            } else if (EPI == 3) {
                float2 bb = *(const float2*)(bias + c);
                float2 ra = *(const float2*)(res + ro0 + c);
                float2 rb = *(const float2*)(res + ro1 + c);
                v0.x += bb.x + ra.x; v0.y += bb.y + ra.y;
                v1.x += bb.x + rb.x; v1.y += bb.y + rb.y;
            }
            if (sizeof(OutT) == 2) {
                *(__half2*)((__half*)C + ro0 + c) = __floats2half2_rn(v0.x, v0.y);
                *(__half2*)((__half*)C + ro1 + c) = __floats2half2_rn(v1.x, v1.y);
            } else {
                *(float2*)((float*)C + ro0 + c) = v0;
                *(float2*)((float*)C + ro1 + c) = v1;
            }
        }
    }
}

template <int EPI, typename OutT>
__global__ __launch_bounds__(256, 1)
void tgemm_kernel(const __half* __restrict__ A, const __half* __restrict__ B,
                  const float* __restrict__ bias, const float* __restrict__ res,
                  OutT* __restrict__ C, int N, int K) {
    tgemm_body<EPI, OutT>(A, B, bias, res, C, N, K);
}

__global__ __launch_bounds__(256, 1)
void tgemm_qkv_kernel(const __half* __restrict__ h, const __half* __restrict__ wt,
                      __half* __restrict__ q, __half* __restrict__ k, __half* __restrict__ v) {
    const __half* B = (blockIdx.z == 0) ? (wt + WQ_OFF) : (blockIdx.z == 1) ? (wt + WK_OFF) : (wt + WV_OFF);
    __half* C       = (blockIdx.z == 0) ? q : (blockIdx.z == 1) ? k : v;
    tgemm_body<0, __half>(h, B, nullptr, nullptr, C, DD, DD);
}

// ---------------- fp16 mma flash attention (unchanged from R9) ----------------
#define AT_ROWB   528
#define AT_BYTES  (64 * AT_ROWB)
#define ATTN_SMEM (5 * AT_BYTES)

__device__ __forceinline__ void attn_load_tile(uint32_t dstb, const __half* src, int tid) {
#pragma unroll
    for (int j = 0; j < 16; ++j) {
        int idx = tid + 128 * j;
        int row = idx >> 5, seg = idx & 31;
        cpasync16(dstb + row * AT_ROWB + seg * 16, src + (size_t)row * DD + seg * 8);
    }
}

__global__ __launch_bounds__(128, 1) void attn_kernel(const __half* __restrict__ q,
                                                      const __half* __restrict__ k,
                                                      const __half* __restrict__ v,
                                                      __half* __restrict__ y) {
    extern __shared__ __align__(1024) char asmem[];
    uint32_t sb = smem_u32(asmem);
    int tid = threadIdx.x, lane = tid & 31, wid = tid >> 5;
    int qt = gridDim.x - 1 - blockIdx.x;
    int hh = blockIdx.y;
    size_t hoff = (size_t)hh * DHD;

    uint32_t Qb = sb;
    uint32_t Kb[2] = { sb + AT_BYTES, sb + 2 * AT_BYTES };
    uint32_t Vb[2] = { sb + 3 * AT_BYTES, sb + 4 * AT_BYTES };

    const __half* qsrc = q + (size_t)(qt * 64) * DD + hoff;

    attn_load_tile(Qb, qsrc, tid);
    attn_load_tile(Kb[0], k + hoff, tid);
    attn_load_tile(Vb[0], v + hoff, tid);
    CP_COMMIT();
    if (qt >= 1) {
        attn_load_tile(Kb[1], k + (size_t)64 * DD + hoff, tid);
        attn_load_tile(Vb[1], v + (size_t)64 * DD + hoff, tid);
    }
    CP_COMMIT();

    float o[32][4];
#pragma unroll
    for (int j = 0; j < 32; ++j)
#pragma unroll
        for (int e = 0; e < 4; ++e) o[j][e] = 0.f;
    float m0 = -1e30f, m1 = -1e30f, l0 = 0.f, l1 = 0.f;

    int dr = ((lane >> 3) & 1) * 8 + (lane & 7);
    int dk = ((lane >> 4) & 1) * 16;
    int wm = wid * 16;
    int lr = lane >> 2, lc = (lane & 3) * 2;
    int vmI = lane >> 3, vii = lane & 7;
    int vsrow = (vmI & 1) * 8 + vii;
    int vcolb = (vmI >> 1) * 16;

    for (int kt = 0; kt <= qt; ++kt) {
        asm volatile("cp.async.wait_group 1;" ::: "memory");
        __syncthreads();
        uint32_t Kt = Kb[kt & 1], Vt = Vb[kt & 1];

        float s[8][4];
#pragma unroll
        for (int j = 0; j < 8; ++j)
#pragma unroll
            for (int e = 0; e < 4; ++e) s[j][e] = 0.f;

#pragma unroll
        for (int k16 = 0; k16 < 16; ++k16) {
            uint32_t kb = (uint32_t)(k16 * 32 + dk);
            uint32_t a[4];
            ldsm_x4(a, Qb + (uint32_t)((wm + dr) * AT_ROWB) + kb);
#pragma unroll
            for (int jj = 0; jj < 4; ++jj) {
                uint32_t b[4];
                ldsm_x4(b, Kt + (uint32_t)((jj * 16 + dr) * AT_ROWB) + kb);
                mma_f16(s[2 * jj],     a, b[0], b[2]);
                mma_f16(s[2 * jj + 1], a, b[1], b[3]);
            }
        }

#pragma unroll
        for (int j = 0; j < 8; ++j)
#pragma unroll
            for (int e = 0; e < 4; ++e) s[j][e] *= 0.0625f;
        if (kt == qt) {
#pragma unroll
            for (int j = 0; j < 8; ++j)
#pragma unroll
                for (int e = 0; e < 4; ++e) {
                    int col = 8 * j + lc + (e & 1);
                    int row = wm + lr + ((e >> 1) << 3);
                    if (col > row) s[j][e] = -1e30f;
                }
        }

        float tm0 = -1e30f, tm1 = -1e30f;
#pragma unroll
        for (int j = 0; j < 8; ++j) {
            tm0 = fmaxf(tm0, fmaxf(s[j][0], s[j][1]));
            tm1 = fmaxf(tm1, fmaxf(s[j][2], s[j][3]));
        }
        tm0 = fmaxf(tm0, __shfl_xor_sync(~0u, tm0, 1));
        tm0 = fmaxf(tm0, __shfl_xor_sync(~0u, tm0, 2));
        tm1 = fmaxf(tm1, __shfl_xor_sync(~0u, tm1, 1));
        tm1 = fmaxf(tm1, __shfl_xor_sync(~0u, tm1, 2));
        float nm0 = fmaxf(m0, tm0), nm1 = fmaxf(m1, tm1);
        float al0 = __expf(m0 - nm0), al1 = __expf(m1 - nm1);
        m0 = nm0; m1 = nm1;
        float rs0 = 0.f, rs1 = 0.f;
#pragma unroll
        for (int j = 0; j < 8; ++j) {
            s[j][0] = __expf(s[j][0] - nm0);
            s[j][1] = __expf(s[j][1] - nm0);
            s[j][2] = __expf(s[j][2] - nm1);
            s[j][3] = __expf(s[j][3] - nm1);
            rs0 += s[j][0] + s[j][1];
            rs1 += s[j][2] + s[j][3];
        }
        rs0 += __shfl_xor_sync(~0u, rs0, 1); rs0 += __shfl_xor_sync(~0u, rs0, 2);
        rs1 += __shfl_xor_sync(~0u, rs1, 1); rs1 += __shfl_xor_sync(~0u, rs1, 2);
        l0 = l0 * al0 + rs0;
        l1 = l1 * al1 + rs1;
#pragma unroll
        for (int j = 0; j < 32; ++j) {
            o[j][0] *= al0; o[j][1] *= al0;
            o[j][2] *= al1; o[j][3] *= al1;
        }

#pragma unroll
        for (int t = 0; t < 4; ++t) {
            uint32_t pa[4];
            pa[0] = h2pack(s[2 * t][0],     s[2 * t][1]);
            pa[1] = h2pack(s[2 * t][2],     s[2 * t][3]);
            pa[2] = h2pack(s[2 * t + 1][0], s[2 * t + 1][1]);
            pa[3] = h2pack(s[2 * t + 1][2], s[2 * t + 1][3]);
            uint32_t vrow = (uint32_t)((16 * t + vsrow) * AT_ROWB);
#pragma unroll
            for (int np = 0; np < 16; ++np) {
                uint32_t bb[4];
                ldsm_x4_trans(bb, Vt + vrow + (uint32_t)(np * 32 + vcolb));
                mma_f16(o[2 * np],     pa, bb[0], bb[1]);
                mma_f16(o[2 * np + 1], pa, bb[2], bb[3]);
            }
        }

        __syncthreads();
        int jt = kt + 2;
        if (jt <= qt) {
            attn_load_tile(Kb[kt & 1], k + (size_t)(jt * 64) * DD + hoff, tid);
            attn_load_tile(Vb[kt & 1], v + (size_t)(jt * 64) * DD + hoff, tid);
        }
        CP_COMMIT();
    }

    float inv0 = 1.f / l0, inv1 = 1.f / l1;
    size_t r0 = (size_t)(qt * 64 + wm + lr) * DD + hoff;
    size_t r1 = r0 + (size_t)8 * DD;
#pragma unroll
    for (int j = 0; j < 32; ++j) {
        *(__half2*)(y + r0 + 8 * j + lc) = __floats2half2_rn(o[j][0] * inv0, o[j][1] * inv0);
        *(__half2*)(y + r1 + 8 * j + lc) = __floats2half2_rn(o[j][2] * inv1, o[j][3] * inv1);
    }
}

// ---------------- launcher (dual-stream overlap) ----------------
extern "C" void kernel_launch(void* const* d_in, const int* in_sizes, int n_in,
                              void* d_out, int out_size) {
    const float* x     = (const float*)d_in[0];
    const float* wq    = (const float*)d_in[1];
    const float* wk    = (const float*)d_in[2];
    const float* wv    = (const float*)d_in[3];
    const float* wo    = (const float*)d_in[4];
    const float* w_in  = (const float*)d_in[5];
    const float* b_in  = (const float*)d_in[6];
    const float* w_out = (const float*)d_in[7];
    const float* b_out = (const float*)d_in[8];
    const float* ln_s  = (const float*)d_in[9];
    const float* ln_o  = (const float*)d_in[10];
    float* out = (float*)d_out;

    __half *h, *q, *k, *v, *y, *m, *wt;
    float *tmp;
    cudaGetSymbolAddress((void**)&h,   g_h);
    cudaGetSymbolAddress((void**)&q,   g_q);
    cudaGetSymbolAddress((void**)&k,   g_k);
    cudaGetSymbolAddress((void**)&v,   g_v);
    cudaGetSymbolAddress((void**)&y,   g_y);
    cudaGetSymbolAddress((void**)&tmp, g_tmp);
    cudaGetSymbolAddress((void**)&m,   g_m);
    cudaGetSymbolAddress((void**)&wt,  g_wt);

    cudaFuncSetAttribute(attn_kernel, cudaFuncAttributeMaxDynamicSharedMemorySize, ATTN_SMEM);
    cudaFuncSetAttribute(tgemm_qkv_kernel, cudaFuncAttributeMaxDynamicSharedMemorySize, GSMEM_TOTAL);
    cudaFuncSetAttribute(tgemm_kernel<1, __half>, cudaFuncAttributeMaxDynamicSharedMemorySize, GSMEM_TOTAL);
    cudaFuncSetAttribute(tgemm_kernel<2, float>,  cudaFuncAttributeMaxDynamicSharedMemorySize, GSMEM_TOTAL);
    cudaFuncSetAttribute(tgemm_kernel<3, float>,  cudaFuncAttributeMaxDynamicSharedMemorySize, GSMEM_TOTAL);

    // lazy one-time stream/event setup (handles only; no device allocations)
    static cudaStream_t s1 = nullptr;
    static cudaEvent_t evS = nullptr, evA = nullptr, evWoCv = nullptr, evM = nullptr;
    if (s1 == nullptr) {
        cudaStreamCreateWithFlags(&s1, cudaStreamNonBlocking);
        cudaEventCreateWithFlags(&evS,    cudaEventDisableTiming);
        cudaEventCreateWithFlags(&evA,    cudaEventDisableTiming);
        cudaEventCreateWithFlags(&evWoCv, cudaEventDisableTiming);
        cudaEventCreateWithFlags(&evM,    cudaEventDisableTiming);
    }

    const int G44 = (DD / 4) * DD / 256;          // 16384 blocks for 4096x4096
    const int G416 = (DD / 4) * DFF / 256;        // 65536 blocks for 4096x16384

    // fork s1 from main stream
    cudaEventRecord(evS, 0);
    cudaStreamWaitEvent(s1, evS, 0);

    // s1: convert wo (needed by Wo GEMM), then MLP weights
    convert_kernel<<<G44, 256, 0, s1>>>((const float4*)wo, (__half2*)(wt + WO_OFF));
    cudaEventRecord(evWoCv, s1);
    convert_kernel<<<G416, 256, 0, s1>>>((const float4*)w_in,  (__half2*)(wt + WIN_OFF));
    convert_kernel<<<G416, 256, 0, s1>>>((const float4*)w_out, (__half2*)(wt + WOUT_OFF));

    // main: convert qkv weights, LN
    convert_kernel<<<G44, 256>>>((const float4*)wq, (__half2*)(wt + WQ_OFF));
    convert_kernel<<<G44, 256>>>((const float4*)wk, (__half2*)(wt + WK_OFF));
    convert_kernel<<<G44, 256>>>((const float4*)wv, (__half2*)(wt + WV_OFF));
    ln_kernel<<<TT, 256>>>(x, ln_s, ln_o, h);
    cudaEventRecord(evA, 0);

    // s1: MLP-in GEMM (needs h + w_in convert)
    cudaStreamWaitEvent(s1, evA, 0);
    tgemm_kernel<1, __half><<<dim3(DFF / 256, TT / 128), 256, GSMEM_TOTAL, s1>>>(h, wt + WIN_OFF, b_in, nullptr, m, DFF, DD);
    cudaEventRecord(evM, s1);

    // main: QKV -> RoPE -> attention -> Wo
    tgemm_qkv_kernel<<<dim3(DD / 256, TT / 128, 3), 256, GSMEM_TOTAL>>>(h, wt, q, k, v);
    rope_kernel<<<(TT * HH * 32) / 256, 256>>>(q, k);
    attn_kernel<<<dim3(TT / 64, HH), 128, ATTN_SMEM>>>(q, k, v, y);
    cudaStreamWaitEvent(0, evWoCv, 0);
    tgemm_kernel<2, float><<<dim3(DD / 256, TT / 128), 256, GSMEM_TOTAL>>>(y, wt + WO_OFF, nullptr, x, tmp, DD, DD);

    // join: MLP-out needs m (s1) and tmp (main)
    cudaStreamWaitEvent(0, evM, 0);
    tgemm_kernel<3, float><<<dim3(DD / 256, TT / 128), 256, GSMEM_TOTAL>>>(m, wt + WOUT_OFF, b_out, tmp, out, DD, DFF);
}

// round 11
// speedup vs baseline: 8.9032x; 1.0291x over previous
#include <cuda_runtime.h>
#include <cuda_fp16.h>
#include <math.h>
#include <stdint.h>

// ---------------- problem constants ----------------
#define TT    2048
#define DD    4096
#define HH    16
#define DHD   256
#define DFF   16384

// ---------------- scratch (device globals; no cudaMalloc allowed) ----------------
__device__ __half g_h  [TT * DD];      // LN output
__device__ __half g_q  [TT * DD];
__device__ __half g_k  [TT * DD];
__device__ __half g_v  [TT * DD];
__device__ __half g_y  [TT * DD];      // attention output
__device__ float  g_tmp[TT * DD];
__device__ __half g_m  [TT * DFF];
// fp16 weights in NATIVE [K,N] layout (converted, not transposed)
__device__ __half g_wt [4u*4096u*4096u + 2u*4096u*16384u];

#define WQ_OFF    0u
#define WK_OFF    16777216u
#define WV_OFF    33554432u
#define WO_OFF    50331648u
#define WIN_OFF   67108864u
#define WOUT_OFF  134217728u

// ---------------- helpers ----------------
__device__ __forceinline__ uint32_t smem_u32(const void* p) {
    uint32_t r;
    asm("{ .reg .u64 t; cvta.to.shared.u64 t, %1; cvt.u32.u64 %0, t; }" : "=r"(r) : "l"(p));
    return r;
}
__device__ __forceinline__ void cpasync16(uint32_t dst, const void* src) {
    asm volatile("cp.async.cg.shared.global [%0], [%1], 16;" :: "r"(dst), "l"(src));
}
#define CP_COMMIT() asm volatile("cp.async.commit_group;" ::: "memory")

__device__ __forceinline__ void ldsm_x4(uint32_t (&r)[4], uint32_t addr) {
    asm volatile("ldmatrix.sync.aligned.m8n8.x4.shared.b16 {%0,%1,%2,%3}, [%4];"
        : "=r"(r[0]), "=r"(r[1]), "=r"(r[2]), "=r"(r[3]) : "r"(addr));
}
__device__ __forceinline__ void ldsm_x4_trans(uint32_t (&r)[4], uint32_t addr) {
    asm volatile("ldmatrix.sync.aligned.m8n8.x4.trans.shared.b16 {%0,%1,%2,%3}, [%4];"
        : "=r"(r[0]), "=r"(r[1]), "=r"(r[2]), "=r"(r[3]) : "r"(addr));
}
__device__ __forceinline__ void mma_f16(float (&d)[4], const uint32_t (&a)[4],
                                        uint32_t b0, uint32_t b1) {
    asm volatile("mma.sync.aligned.m16n8k16.row.col.f32.f16.f16.f32 "
        "{%0,%1,%2,%3}, {%4,%5,%6,%7}, {%8,%9}, {%0,%1,%2,%3};"
        : "+f"(d[0]), "+f"(d[1]), "+f"(d[2]), "+f"(d[3])
        : "r"(a[0]), "r"(a[1]), "r"(a[2]), "r"(a[3]), "r"(b0), "r"(b1));
}
__device__ __forceinline__ uint32_t h2pack(float x, float y) {
    __half2 h = __floats2half2_rn(x, y);
    return *(uint32_t*)&h;
}

// swizzles: 128B-row tiles (A) and 512B-row tiles (B)
#define TSWZ(off)   ((off) ^ (((off) >> 3) & 0x70))
#define SWZ512(off) ((off) ^ (((off) >> 5) & 0x70))

// ---------------- LayerNorm (fp16 output) ----------------
__global__ __launch_bounds__(256) void ln_kernel(const float* __restrict__ x,
                                                 const float* __restrict__ g,
                                                 const float* __restrict__ b,
                                                 __half* __restrict__ h) {
    int row = blockIdx.x;
    const float4* xr = (const float4*)(x + (size_t)row * DD);
    float s = 0.f, s2 = 0.f;
    for (int i = threadIdx.x; i < DD / 4; i += 256) {
        float4 v = xr[i];
        s  += v.x + v.y + v.z + v.w;
        s2 += v.x*v.x + v.y*v.y + v.z*v.z + v.w*v.w;
    }
    for (int o = 16; o > 0; o >>= 1) {
        s  += __shfl_xor_sync(~0u, s,  o);
        s2 += __shfl_xor_sync(~0u, s2, o);
    }
    __shared__ float sh[16];
    int w = threadIdx.x >> 5;
    if ((threadIdx.x & 31) == 0) { sh[w] = s; sh[8 + w] = s2; }
    __syncthreads();
    if (threadIdx.x < 32) {
        float a = threadIdx.x < 8 ? sh[threadIdx.x]     : 0.f;
        float c = threadIdx.x < 8 ? sh[8 + threadIdx.x] : 0.f;
        for (int o = 4; o > 0; o >>= 1) {
            a += __shfl_xor_sync(~0u, a, o);
            c += __shfl_xor_sync(~0u, c, o);
        }
        if (threadIdx.x == 0) { sh[0] = a; sh[8] = c; }
    }
    __syncthreads();
    float mean = sh[0] * (1.f / DD);
    float var  = sh[8] * (1.f / DD) - mean * mean;
    float rstd = rsqrtf(var + 1e-6f);
    __half2* hr = (__half2*)(h + (size_t)row * DD);
    const float4* gg4 = (const float4*)g;
    const float4* bb4 = (const float4*)b;
    for (int i = threadIdx.x; i < DD / 4; i += 256) {
        float4 v = xr[i], gg = gg4[i], bb = bb4[i];
        hr[i * 2]     = __floats2half2_rn((v.x - mean) * rstd * gg.x + bb.x,
                                          (v.y - mean) * rstd * gg.y + bb.y);
        hr[i * 2 + 1] = __floats2half2_rn((v.z - mean) * rstd * gg.z + bb.z,
                                          (v.w - mean) * rstd * gg.w + bb.w);
    }
}

// ---------------- streaming fp32 -> fp16 convert (layout preserved) ----------------
__global__ __launch_bounds__(256) void convert_kernel(const float4* __restrict__ in,
                                                      __half2* __restrict__ out) {
    int i = blockIdx.x * 256 + threadIdx.x;
    float4 v = in[i];
    out[2 * i]     = __floats2half2_rn(v.x, v.y);
    out[2 * i + 1] = __floats2half2_rn(v.z, v.w);
}

// ---------------- RoPE in-place on fp16 q, k ----------------
__global__ __launch_bounds__(256) void rope_kernel(__half* __restrict__ q, __half* __restrict__ k) {
    int idx = blockIdx.x * 256 + threadIdx.x;
    int f = idx & 31;
    int hh = (idx >> 5) & (HH - 1);
    int t = idx >> 9;
    float inv = 1.0f / powf(10000.0f, (float)f * (1.0f / 32.0f));
    float ang = (float)t * inv;
    float sn, cs;
    sincosf(ang, &sn, &cs);
    size_t base = (size_t)t * DD + hh * DHD + f;
    {
        float a = __half2float(q[base]), b = __half2float(q[base + 32]);
        q[base]      = __float2half_rn(a * cs - b * sn);
        q[base + 32] = __float2half_rn(a * sn + b * cs);
    }
    {
        float a = __half2float(k[base]), b = __half2float(k[base + 32]);
        k[base]      = __float2half_rn(a * cs - b * sn);
        k[base + 32] = __float2half_rn(a * sn + b * cs);
    }
}

// ---------------- fp16 mma GEMM: CTA 128x256, warp 64x64, 4-stage cp.async ----------------
__device__ __forceinline__ float gelu_f(float v) {
    float t = tanhf(0.7978845608028654f * (v + 0.044715f * v * v * v));
    return 0.5f * v * (1.f + t);
}

#define STAGE_BYTES 49152            // A 16KB (128m x 128B) + B 32KB (64k x 512B)
#define B_SMEM_OFF  16384
#define GSTAGES 4
#define GSMEM_TOTAL (GSTAGES * STAGE_BYTES)   // 196608

template <int EPI, typename OutT>
__device__ __forceinline__ void tgemm_body(const __half* __restrict__ A, const __half* __restrict__ B,
                                           const float* __restrict__ bias, const float* __restrict__ res,
                                           OutT* __restrict__ C, int N, int K) {
    extern __shared__ __align__(1024) char gsm[];
    uint32_t sbase = smem_u32(gsm);
    int tid = threadIdx.x, lane = tid & 31, wid = tid >> 5;
    int bm = blockIdx.y * 128, bn = blockIdx.x * 256;
    int ntiles = K >> 6;
    int wm = (wid >> 2) * 64, wn = (wid & 3) * 64;

    uint32_t doffA[4]; int soffA[4];
#pragma unroll
    for (int j = 0; j < 4; ++j) {
        int idx = tid + 256 * j;
        int row = idx >> 3, seg = idx & 7;
        soffA[j] = row * K + seg * 8;
        doffA[j] = TSWZ((uint32_t)(row * 128 + seg * 16));
    }
    uint32_t doffB[8]; size_t soffB[8];
#pragma unroll
    for (int j = 0; j < 8; ++j) {
        int idx = tid + 256 * j;
        int krow = idx >> 5, seg = idx & 31;
        soffB[j] = (size_t)krow * N + seg * 8;
        doffB[j] = B_SMEM_OFF + SWZ512((uint32_t)(krow * 512 + seg * 16));
    }
    const __half* Abase = A + (size_t)bm * K;
    const __half* Bbase = B + bn;

#pragma unroll
    for (int p = 0; p < GSTAGES - 1; ++p) {
        uint32_t stb = sbase + p * STAGE_BYTES;
#pragma unroll
        for (int j = 0; j < 4; ++j) cpasync16(stb + doffA[j], Abase + soffA[j] + p * 64);
#pragma unroll
        for (int j = 0; j < 8; ++j) cpasync16(stb + doffB[j], Bbase + soffB[j] + (size_t)p * 64 * N);
        CP_COMMIT();
    }

    float acc[4][8][4];
#pragma unroll
    for (int i = 0; i < 4; ++i)
#pragma unroll
        for (int j = 0; j < 8; ++j)
#pragma unroll
            for (int e = 0; e < 4; ++e) acc[i][j][e] = 0.f;

    int dr = ((lane >> 3) & 1) * 8 + (lane & 7);
    int dk = ((lane >> 4) & 1) * 16;
    int vmI = lane >> 3, vii = lane & 7;
    int vsrow = (vmI & 1) * 8 + vii;
    int vcolb = (vmI >> 1) * 16;

    int stage = 0;
    for (int kt = 0; kt < ntiles; ++kt) {
        asm volatile("cp.async.wait_group 2;" ::: "memory");
        __syncthreads();

        int jt = kt + 3;
        if (jt < ntiles) {
            int ps = stage + 3; if (ps >= GSTAGES) ps -= GSTAGES;
            uint32_t stb = sbase + ps * STAGE_BYTES;
#pragma unroll
            for (int j = 0; j < 4; ++j) cpasync16(stb + doffA[j], Abase + soffA[j] + jt * 64);
#pragma unroll
            for (int j = 0; j < 8; ++j) cpasync16(stb + doffB[j], Bbase + soffB[j] + (size_t)jt * 64 * N);
        }
        CP_COMMIT();

        uint32_t stb = sbase + stage * STAGE_BYTES;
#pragma unroll
        for (int k16 = 0; k16 < 4; ++k16) {
            uint32_t a[4][4];
#pragma unroll
            for (int i = 0; i < 4; ++i)
                ldsm_x4(a[i], stb + TSWZ((uint32_t)((wm + i * 16 + dr) * 128) + (uint32_t)(k16 * 32 + dk)));
            uint32_t b[4][4];
#pragma unroll
            for (int jj = 0; jj < 4; ++jj) {
                uint32_t off = (uint32_t)((k16 * 16 + vsrow) * 512 + (wn + jj * 16) * 2 + vcolb);
                ldsm_x4_trans(b[jj], stb + B_SMEM_OFF + SWZ512(off));
            }
#pragma unroll
            for (int i = 0; i < 4; ++i)
#pragma unroll
                for (int jj = 0; jj < 4; ++jj) {
                    mma_f16(acc[i][2 * jj],     a[i], b[jj][0], b[jj][1]);
                    mma_f16(acc[i][2 * jj + 1], a[i], b[jj][2], b[jj][3]);
                }
        }
        if (++stage == GSTAGES) stage = 0;
    }

    int lr = lane >> 2, lc = (lane & 3) * 2;
#pragma unroll
    for (int i = 0; i < 4; ++i) {
        int r0 = bm + wm + i * 16 + lr;
        int r1 = r0 + 8;
        size_t ro0 = (size_t)r0 * N, ro1 = (size_t)r1 * N;
#pragma unroll
        for (int j = 0; j < 8; ++j) {
            int c = bn + wn + j * 8 + lc;
            float2 v0 = make_float2(acc[i][j][0], acc[i][j][1]);
            float2 v1 = make_float2(acc[i][j][2], acc[i][j][3]);
            if (EPI == 1) {
                float2 bb = *(const float2*)(bias + c);
                v0.x = gelu_f(v0.x + bb.x); v0.y = gelu_f(v0.y + bb.y);
                v1.x = gelu_f(v1.x + bb.x); v1.y = gelu_f(v1.y + bb.y);
            } else if (EPI == 2) {
                float2 ra = *(const float2*)(res + ro0 + c);
                float2 rb = *(const float2*)(res + ro1 + c);
                v0.x += ra.x; v0.y += ra.y; v1.x += rb.x; v1.y += rb.y;
            } else if (EPI == 3) {
                float2 bb = *(const float2*)(bias + c);
                float2 ra = *(const float2*)(res + ro0 + c);
                float2 rb = *(const float2*)(res + ro1 + c);
                v0.x += bb.x + ra.x; v0.y += bb.y + ra.y;
                v1.x += bb.x + rb.x; v1.y += bb.y + rb.y;
            }
            if (sizeof(OutT) == 2) {
                *(__half2*)((__half*)C + ro0 + c) = __floats2half2_rn(v0.x, v0.y);
                *(__half2*)((__half*)C + ro1 + c) = __floats2half2_rn(v1.x, v1.y);
            } else {
                *(float2*)((float*)C + ro0 + c) = v0;
                *(float2*)((float*)C + ro1 + c) = v1;
            }
        }
    }
}

template <int EPI, typename OutT>
__global__ __launch_bounds__(256, 1)
void tgemm_kernel(const __half* __restrict__ A, const __half* __restrict__ B,
                  const float* __restrict__ bias, const float* __restrict__ res,
                  OutT* __restrict__ C, int N, int K) {
    tgemm_body<EPI, OutT>(A, B, bias, res, C, N, K);
}

__global__ __launch_bounds__(256, 1)
void tgemm_qkv_kernel(const __half* __restrict__ h, const __half* __restrict__ wt,
                      __half* __restrict__ q, __half* __restrict__ k, __half* __restrict__ v) {
    const __half* B = (blockIdx.z == 0) ? (wt + WQ_OFF) : (blockIdx.z == 1) ? (wt + WK_OFF) : (wt + WV_OFF);
    __half* C       = (blockIdx.z == 0) ? q : (blockIdx.z == 1) ? k : v;
    tgemm_body<0, __half>(h, B, nullptr, nullptr, C, DD, DD);
}

// ---------------- fp16 mma flash attention: Br=128, 8 warps, Bc=64 ----------------
#define AT_ROWB    528
#define ATQ_BYTES  (128 * AT_ROWB)                 // 67584
#define ATKV_BYTES (64 * AT_ROWB)                  // 33792
#define ATTN_SMEM  (ATQ_BYTES + 4 * ATKV_BYTES)    // 202752

__device__ __forceinline__ void attn_load_q(uint32_t dstb, const __half* src, int tid) {
#pragma unroll
    for (int j = 0; j < 16; ++j) {
        int idx = tid + 256 * j;
        int row = idx >> 5, seg = idx & 31;
        cpasync16(dstb + row * AT_ROWB + seg * 16, src + (size_t)row * DD + seg * 8);
    }
}
__device__ __forceinline__ void attn_load_kv(uint32_t dstb, const __half* src, int tid) {
#pragma unroll
    for (int j = 0; j < 8; ++j) {
        int idx = tid + 256 * j;
        int row = idx >> 5, seg = idx & 31;
        cpasync16(dstb + row * AT_ROWB + seg * 16, src + (size_t)row * DD + seg * 8);
    }
}

__global__ __launch_bounds__(256, 1) void attn_kernel(const __half* __restrict__ q,
                                                      const __half* __restrict__ k,
                                                      const __half* __restrict__ v,
                                                      __half* __restrict__ y) {
    extern __shared__ __align__(1024) char asmem[];
    uint32_t sb = smem_u32(asmem);
    int tid = threadIdx.x, lane = tid & 31, wid = tid >> 5;   // 8 warps
    int qt = gridDim.x - 1 - blockIdx.x;                      // heavy tiles first
    int hh = blockIdx.y;
    size_t hoff = (size_t)hh * DHD;
    int ntk = 2 * qt + 2;

    uint32_t Qb = sb;
    uint32_t Kb[2] = { sb + ATQ_BYTES, sb + ATQ_BYTES + ATKV_BYTES };
    uint32_t Vb[2] = { sb + ATQ_BYTES + 2 * ATKV_BYTES, sb + ATQ_BYTES + 3 * ATKV_BYTES };

    const __half* qsrc = q + (size_t)(qt * 128) * DD + hoff;

    attn_load_q(Qb, qsrc, tid);
    attn_load_kv(Kb[0], k + hoff, tid);
    attn_load_kv(Vb[0], v + hoff, tid);
    CP_COMMIT();
    attn_load_kv(Kb[1], k + (size_t)64 * DD + hoff, tid);
    attn_load_kv(Vb[1], v + (size_t)64 * DD + hoff, tid);
    CP_COMMIT();

    float o[32][4];
#pragma unroll
    for (int j = 0; j < 32; ++j)
#pragma unroll
        for (int e = 0; e < 4; ++e) o[j][e] = 0.f;
    float m0 = -1e30f, m1 = -1e30f, l0 = 0.f, l1 = 0.f;

    int dr = ((lane >> 3) & 1) * 8 + (lane & 7);
    int dk = ((lane >> 4) & 1) * 16;
    int wm = wid * 16;                       // warp's 16 q-rows within 128
    int lr = lane >> 2, lc = (lane & 3) * 2;
    int vmI = lane >> 3, vii = lane & 7;
    int vsrow = (vmI & 1) * 8 + vii;
    int vcolb = (vmI >> 1) * 16;

    for (int kt = 0; kt < ntk; ++kt) {
        asm volatile("cp.async.wait_group 1;" ::: "memory");
        __syncthreads();
        uint32_t Kt = Kb[kt & 1], Vt = Vb[kt & 1];

        // ---- S = Q K^T : warp computes 16x64 ----
        float s[8][4];
#pragma unroll
        for (int j = 0; j < 8; ++j)
#pragma unroll
            for (int e = 0; e < 4; ++e) s[j][e] = 0.f;

#pragma unroll
        for (int k16 = 0; k16 < 16; ++k16) {
            uint32_t kb = (uint32_t)(k16 * 32 + dk);
            uint32_t a[4];
            ldsm_x4(a, Qb + (uint32_t)((wm + dr) * AT_ROWB) + kb);
#pragma unroll
            for (int jj = 0; jj < 4; ++jj) {
                uint32_t b[4];
                ldsm_x4(b, Kt + (uint32_t)((jj * 16 + dr) * AT_ROWB) + kb);
                mma_f16(s[2 * jj],     a, b[0], b[2]);
                mma_f16(s[2 * jj + 1], a, b[1], b[3]);
            }
        }

#pragma unroll
        for (int j = 0; j < 8; ++j)
#pragma unroll
            for (int e = 0; e < 4; ++e) s[j][e] *= 0.0625f;
        if (kt >= 2 * qt) {       // tiles intersecting the diagonal
            int rowg_base = qt * 128 + wm + lr;
            int colg_base = kt * 64 + lc;
#pragma unroll
            for (int j = 0; j < 8; ++j)
#pragma unroll
                for (int e = 0; e < 4; ++e) {
                    int colg = colg_base + 8 * j + (e & 1);
                    int rowg = rowg_base + ((e >> 1) << 3);
                    if (colg > rowg) s[j][e] = -1e30f;
                }
        }

        // ---- online softmax (rows lr, lr+8 of warp tile) ----
        float tm0 = -1e30f, tm1 = -1e30f;
#pragma unroll
        for (int j = 0; j < 8; ++j) {
            tm0 = fmaxf(tm0, fmaxf(s[j][0], s[j][1]));
            tm1 = fmaxf(tm1, fmaxf(s[j][2], s[j][3]));
        }
        tm0 = fmaxf(tm0, __shfl_xor_sync(~0u, tm0, 1));
        tm0 = fmaxf(tm0, __shfl_xor_sync(~0u, tm0, 2));
        tm1 = fmaxf(tm1, __shfl_xor_sync(~0u, tm1, 1));
        tm1 = fmaxf(tm1, __shfl_xor_sync(~0u, tm1, 2));
        float nm0 = fmaxf(m0, tm0), nm1 = fmaxf(m1, tm1);
        float al0 = __expf(m0 - nm0), al1 = __expf(m1 - nm1);
        m0 = nm0; m1 = nm1;
        float rs0 = 0.f, rs1 = 0.f;
#pragma unroll
        for (int j = 0; j < 8; ++j) {
            s[j][0] = __expf(s[j][0] - nm0);
            s[j][1] = __expf(s[j][1] - nm0);
            s[j][2] = __expf(s[j][2] - nm1);
            s[j][3] = __expf(s[j][3] - nm1);
            rs0 += s[j][0] + s[j][1];
            rs1 += s[j][2] + s[j][3];
        }
        rs0 += __shfl_xor_sync(~0u, rs0, 1); rs0 += __shfl_xor_sync(~0u, rs0, 2);
        rs1 += __shfl_xor_sync(~0u, rs1, 1); rs1 += __shfl_xor_sync(~0u, rs1, 2);
        l0 = l0 * al0 + rs0;
        l1 = l1 * al1 + rs1;
#pragma unroll
        for (int j = 0; j < 32; ++j) {
            o[j][0] *= al0; o[j][1] *= al0;
            o[j][2] *= al1; o[j][3] *= al1;
        }

        // ---- O += P V ----
#pragma unroll
        for (int t = 0; t < 4; ++t) {
            uint32_t pa[4];
            pa[0] = h2pack(s[2 * t][0],     s[2 * t][1]);
            pa[1] = h2pack(s[2 * t][2],     s[2 * t][3]);
            pa[2] = h2pack(s[2 * t + 1][0], s[2 * t + 1][1]);
            pa[3] = h2pack(s[2 * t + 1][2], s[2 * t + 1][3]);
            uint32_t vrow = (uint32_t)((16 * t + vsrow) * AT_ROWB);
#pragma unroll
            for (int np = 0; np < 16; ++np) {
                uint32_t bb[4];
                ldsm_x4_trans(bb, Vt + vrow + (uint32_t)(np * 32 + vcolb));
                mma_f16(o[2 * np],     pa, bb[0], bb[1]);
                mma_f16(o[2 * np + 1], pa, bb[2], bb[3]);
            }
        }

        __syncthreads();
        int jt = kt + 2;
        if (jt < ntk) {
            attn_load_kv(Kb[kt & 1], k + (size_t)(jt * 64) * DD + hoff, tid);
            attn_load_kv(Vb[kt & 1], v + (size_t)(jt * 64) * DD + hoff, tid);
        }
        CP_COMMIT();
    }

    float inv0 = 1.f / l0, inv1 = 1.f / l1;
    size_t r0 = (size_t)(qt * 128 + wm + lr) * DD + hoff;
    size_t r1 = r0 + (size_t)8 * DD;
#pragma unroll
    for (int j = 0; j < 32; ++j) {
        *(__half2*)(y + r0 + 8 * j + lc) = __floats2half2_rn(o[j][0] * inv0, o[j][1] * inv0);
        *(__half2*)(y + r1 + 8 * j + lc) = __floats2half2_rn(o[j][2] * inv1, o[j][3] * inv1);
    }
}

// ---------------- launcher (dual-stream overlap) ----------------
extern "C" void kernel_launch(void* const* d_in, const int* in_sizes, int n_in,
                              void* d_out, int out_size) {
    const float* x     = (const float*)d_in[0];
    const float* wq    = (const float*)d_in[1];
    const float* wk    = (const float*)d_in[2];
    const float* wv    = (const float*)d_in[3];
    const float* wo    = (const float*)d_in[4];
    const float* w_in  = (const float*)d_in[5];
    const float* b_in  = (const float*)d_in[6];
    const float* w_out = (const float*)d_in[7];
    const float* b_out = (const float*)d_in[8];
    const float* ln_s  = (const float*)d_in[9];
    const float* ln_o  = (const float*)d_in[10];
    float* out = (float*)d_out;

    __half *h, *q, *k, *v, *y, *m, *wt;
    float *tmp;
    cudaGetSymbolAddress((void**)&h,   g_h);
    cudaGetSymbolAddress((void**)&q,   g_q);
    cudaGetSymbolAddress((void**)&k,   g_k);
    cudaGetSymbolAddress((void**)&v,   g_v);
    cudaGetSymbolAddress((void**)&y,   g_y);
    cudaGetSymbolAddress((void**)&tmp, g_tmp);
    cudaGetSymbolAddress((void**)&m,   g_m);
    cudaGetSymbolAddress((void**)&wt,  g_wt);

    cudaFuncSetAttribute(attn_kernel, cudaFuncAttributeMaxDynamicSharedMemorySize, ATTN_SMEM);
    cudaFuncSetAttribute(tgemm_qkv_kernel, cudaFuncAttributeMaxDynamicSharedMemorySize, GSMEM_TOTAL);
    cudaFuncSetAttribute(tgemm_kernel<1, __half>, cudaFuncAttributeMaxDynamicSharedMemorySize, GSMEM_TOTAL);
    cudaFuncSetAttribute(tgemm_kernel<2, float>,  cudaFuncAttributeMaxDynamicSharedMemorySize, GSMEM_TOTAL);
    cudaFuncSetAttribute(tgemm_kernel<3, float>,  cudaFuncAttributeMaxDynamicSharedMemorySize, GSMEM_TOTAL);

    // lazy one-time stream/event setup (handles only; no device allocations)
    static cudaStream_t s1 = nullptr;
    static cudaEvent_t evS = nullptr, evA = nullptr, evWoCv = nullptr, evM = nullptr;
    if (s1 == nullptr) {
        cudaStreamCreateWithFlags(&s1, cudaStreamNonBlocking);
        cudaEventCreateWithFlags(&evS,    cudaEventDisableTiming);
        cudaEventCreateWithFlags(&evA,    cudaEventDisableTiming);
        cudaEventCreateWithFlags(&evWoCv, cudaEventDisableTiming);
        cudaEventCreateWithFlags(&evM,    cudaEventDisableTiming);
    }

    const int G44  = (DD / 4) * DD / 256;
    const int G416 = (DD / 4) * DFF / 256;

    // fork s1 from main stream
    cudaEventRecord(evS, 0);
    cudaStreamWaitEvent(s1, evS, 0);

    // s1: convert wo, then MLP weights
    convert_kernel<<<G44, 256, 0, s1>>>((const float4*)wo, (__half2*)(wt + WO_OFF));
    cudaEventRecord(evWoCv, s1);
    convert_kernel<<<G416, 256, 0, s1>>>((const float4*)w_in,  (__half2*)(wt + WIN_OFF));
    convert_kernel<<<G416, 256, 0, s1>>>((const float4*)w_out, (__half2*)(wt + WOUT_OFF));

    // main: convert qkv weights, LN
    convert_kernel<<<G44, 256>>>((const float4*)wq, (__half2*)(wt + WQ_OFF));
    convert_kernel<<<G44, 256>>>((const float4*)wk, (__half2*)(wt + WK_OFF));
    convert_kernel<<<G44, 256>>>((const float4*)wv, (__half2*)(wt + WV_OFF));
    ln_kernel<<<TT, 256>>>(x, ln_s, ln_o, h);
    cudaEventRecord(evA, 0);

    // s1: MLP-in GEMM (needs h + w_in convert)
    cudaStreamWaitEvent(s1, evA, 0);
    tgemm_kernel<1, __half><<<dim3(DFF / 256, TT / 128), 256, GSMEM_TOTAL, s1>>>(h, wt + WIN_OFF, b_in, nullptr, m, DFF, DD);
    cudaEventRecord(evM, s1);

    // main: QKV -> RoPE -> attention -> Wo
    tgemm_qkv_kernel<<<dim3(DD / 256, TT / 128, 3), 256, GSMEM_TOTAL>>>(h, wt, q, k, v);
    rope_kernel<<<(TT * HH * 32) / 256, 256>>>(q, k);
    attn_kernel<<<dim3(TT / 128, HH), 256, ATTN_SMEM>>>(q, k, v, y);
    cudaStreamWaitEvent(0, evWoCv, 0);
    tgemm_kernel<2, float><<<dim3(DD / 256, TT / 128), 256, GSMEM_TOTAL>>>(y, wt + WO_OFF, nullptr, x, tmp, DD, DD);

    // join: MLP-out needs m (s1) and tmp (main)
    cudaStreamWaitEvent(0, evM, 0);
    tgemm_kernel<3, float><<<dim3(DD / 256, TT / 128), 256, GSMEM_TOTAL>>>(m, wt + WOUT_OFF, b_out, tmp, out, DD, DFF);
}

// round 12
// speedup vs baseline: 8.9188x; 1.0017x over previous
#include <cuda_runtime.h>
#include <cuda_fp16.h>
#include <math.h>
#include <stdint.h>

// ---------------- problem constants ----------------
#define TT    2048
#define DD    4096
#define HH    16
#define DHD   256
#define DFF   16384

// ---------------- scratch (device globals; no cudaMalloc allowed) ----------------
__device__ __half g_h  [TT * DD];      // LN output
__device__ __half g_q  [TT * DD];
__device__ __half g_k  [TT * DD];
__device__ __half g_v  [TT * DD];
__device__ __half g_y  [TT * DD];      // attention output
__device__ float  g_tmp[TT * DD];
__device__ __half g_m  [TT * DFF];
// fp16 weights in NATIVE [K,N] layout (converted, not transposed)
__device__ __half g_wt [4u*4096u*4096u + 2u*4096u*16384u];

#define WQ_OFF    0u
#define WK_OFF    16777216u
#define WV_OFF    33554432u
#define WO_OFF    50331648u
#define WIN_OFF   67108864u
#define WOUT_OFF  134217728u

// ---------------- helpers ----------------
__device__ __forceinline__ uint32_t smem_u32(const void* p) {
    uint32_t r;
    asm("{ .reg .u64 t; cvta.to.shared.u64 t, %1; cvt.u32.u64 %0, t; }" : "=r"(r) : "l"(p));
    return r;
}
__device__ __forceinline__ void cpasync16(uint32_t dst, const void* src) {
    asm volatile("cp.async.cg.shared.global [%0], [%1], 16;" :: "r"(dst), "l"(src));
}
#define CP_COMMIT() asm volatile("cp.async.commit_group;" ::: "memory")

__device__ __forceinline__ void ldsm_x4(uint32_t (&r)[4], uint32_t addr) {
    asm volatile("ldmatrix.sync.aligned.m8n8.x4.shared.b16 {%0,%1,%2,%3}, [%4];"
        : "=r"(r[0]), "=r"(r[1]), "=r"(r[2]), "=r"(r[3]) : "r"(addr));
}
__device__ __forceinline__ void ldsm_x4_trans(uint32_t (&r)[4], uint32_t addr) {
    asm volatile("ldmatrix.sync.aligned.m8n8.x4.trans.shared.b16 {%0,%1,%2,%3}, [%4];"
        : "=r"(r[0]), "=r"(r[1]), "=r"(r[2]), "=r"(r[3]) : "r"(addr));
}
__device__ __forceinline__ void mma_f16(float (&d)[4], const uint32_t (&a)[4],
                                        uint32_t b0, uint32_t b1) {
    asm volatile("mma.sync.aligned.m16n8k16.row.col.f32.f16.f16.f32 "
        "{%0,%1,%2,%3}, {%4,%5,%6,%7}, {%8,%9}, {%0,%1,%2,%3};"
        : "+f"(d[0]), "+f"(d[1]), "+f"(d[2]), "+f"(d[3])
        : "r"(a[0]), "r"(a[1]), "r"(a[2]), "r"(a[3]), "r"(b0), "r"(b1));
}
__device__ __forceinline__ uint32_t h2pack(float x, float y) {
    __half2 h = __floats2half2_rn(x, y);
    return *(uint32_t*)&h;
}

// swizzles: 128B-row tiles (A) and 512B-row tiles (B)
#define TSWZ(off)   ((off) ^ (((off) >> 3) & 0x70))
#define SWZ512(off) ((off) ^ (((off) >> 5) & 0x70))

// ---------------- LayerNorm (fp16 output) ----------------
__global__ __launch_bounds__(256) void ln_kernel(const float* __restrict__ x,
                                                 const float* __restrict__ g,
                                                 const float* __restrict__ b,
                                                 __half* __restrict__ h) {
    int row = blockIdx.x;
    const float4* xr = (const float4*)(x + (size_t)row * DD);
    float s = 0.f, s2 = 0.f;
    for (int i = threadIdx.x; i < DD / 4; i += 256) {
        float4 v = xr[i];
        s  += v.x + v.y + v.z + v.w;
        s2 += v.x*v.x + v.y*v.y + v.z*v.z + v.w*v.w;
    }
    for (int o = 16; o > 0; o >>= 1) {
        s  += __shfl_xor_sync(~0u, s,  o);
        s2 += __shfl_xor_sync(~0u, s2, o);
    }
    __shared__ float sh[16];
    int w = threadIdx.x >> 5;
    if ((threadIdx.x & 31) == 0) { sh[w] = s; sh[8 + w] = s2; }
    __syncthreads();
    if (threadIdx.x < 32) {
        float a = threadIdx.x < 8 ? sh[threadIdx.x]     : 0.f;
        float c = threadIdx.x < 8 ? sh[8 + threadIdx.x] : 0.f;
        for (int o = 4; o > 0; o >>= 1) {
            a += __shfl_xor_sync(~0u, a, o);
            c += __shfl_xor_sync(~0u, c, o);
        }
        if (threadIdx.x == 0) { sh[0] = a; sh[8] = c; }
    }
    __syncthreads();
    float mean = sh[0] * (1.f / DD);
    float var  = sh[8] * (1.f / DD) - mean * mean;
    float rstd = rsqrtf(var + 1e-6f);
    __half2* hr = (__half2*)(h + (size_t)row * DD);
    const float4* gg4 = (const float4*)g;
    const float4* bb4 = (const float4*)b;
    for (int i = threadIdx.x; i < DD / 4; i += 256) {
        float4 v = xr[i], gg = gg4[i], bb = bb4[i];
        hr[i * 2]     = __floats2half2_rn((v.x - mean) * rstd * gg.x + bb.x,
                                          (v.y - mean) * rstd * gg.y + bb.y);
        hr[i * 2 + 1] = __floats2half2_rn((v.z - mean) * rstd * gg.z + bb.z,
                                          (v.w - mean) * rstd * gg.w + bb.w);
    }
}

// ---------------- streaming fp32 -> fp16 convert (layout preserved) ----------------
__global__ __launch_bounds__(256) void convert_kernel(const float4* __restrict__ in,
                                                      uint2* __restrict__ out) {
    int i = blockIdx.x * 256 + threadIdx.x;
    float4 v = in[i];
    uint2 o;
    o.x = h2pack(v.x, v.y);
    o.y = h2pack(v.z, v.w);
    out[i] = o;
}

// ---------------- RoPE in-place on fp16 q, k ----------------
__global__ __launch_bounds__(256) void rope_kernel(__half* __restrict__ q, __half* __restrict__ k) {
    int idx = blockIdx.x * 256 + threadIdx.x;
    int f = idx & 31;
    int hh = (idx >> 5) & (HH - 1);
    int t = idx >> 9;
    float inv = 1.0f / powf(10000.0f, (float)f * (1.0f / 32.0f));
    float ang = (float)t * inv;
    float sn, cs;
    sincosf(ang, &sn, &cs);
    size_t base = (size_t)t * DD + hh * DHD + f;
    {
        float a = __half2float(q[base]), b = __half2float(q[base + 32]);
        q[base]      = __float2half_rn(a * cs - b * sn);
        q[base + 32] = __float2half_rn(a * sn + b * cs);
    }
    {
        float a = __half2float(k[base]), b = __half2float(k[base + 32]);
        k[base]      = __float2half_rn(a * cs - b * sn);
        k[base + 32] = __float2half_rn(a * sn + b * cs);
    }
}

// ---------------- fp16 mma GEMM: CTA 128x256, warp 64x64, 4-stage cp.async ----------------
__device__ __forceinline__ float gelu_f(float v) {
    float t = tanhf(0.7978845608028654f * (v + 0.044715f * v * v * v));
    return 0.5f * v * (1.f + t);
}

#define STAGE_BYTES 49152            // A 16KB (128m x 128B) + B 32KB (64k x 512B)
#define B_SMEM_OFF  16384
#define GSTAGES 4
#define GSMEM_TOTAL (GSTAGES * STAGE_BYTES)   // 196608

template <int EPI, typename OutT>
__device__ __forceinline__ void tgemm_body(const __half* __restrict__ A, const __half* __restrict__ B,
                                           const float* __restrict__ bias, const float* __restrict__ res,
                                           OutT* __restrict__ C, int N, int K) {
    extern __shared__ __align__(1024) char gsm[];
    uint32_t sbase = smem_u32(gsm);
    int tid = threadIdx.x, lane = tid & 31, wid = tid >> 5;
    int bm = blockIdx.y * 128, bn = blockIdx.x * 256;
    int ntiles = K >> 6;
    int wm = (wid >> 2) * 64, wn = (wid & 3) * 64;

    uint32_t doffA[4]; int soffA[4];
#pragma unroll
    for (int j = 0; j < 4; ++j) {
        int idx = tid + 256 * j;
        int row = idx >> 3, seg = idx & 7;
        soffA[j] = row * K + seg * 8;
        doffA[j] = TSWZ((uint32_t)(row * 128 + seg * 16));
    }
    uint32_t doffB[8]; size_t soffB[8];
#pragma unroll
    for (int j = 0; j < 8; ++j) {
        int idx = tid + 256 * j;
        int krow = idx >> 5, seg = idx & 31;
        soffB[j] = (size_t)krow * N + seg * 8;
        doffB[j] = B_SMEM_OFF + SWZ512((uint32_t)(krow * 512 + seg * 16));
    }
    const __half* Abase = A + (size_t)bm * K;
    const __half* Bbase = B + bn;

#pragma unroll
    for (int p = 0; p < GSTAGES - 1; ++p) {
        uint32_t stb = sbase + p * STAGE_BYTES;
#pragma unroll
        for (int j = 0; j < 4; ++j) cpasync16(stb + doffA[j], Abase + soffA[j] + p * 64);
#pragma unroll
        for (int j = 0; j < 8; ++j) cpasync16(stb + doffB[j], Bbase + soffB[j] + (size_t)p * 64 * N);
        CP_COMMIT();
    }

    float acc[4][8][4];
#pragma unroll
    for (int i = 0; i < 4; ++i)
#pragma unroll
        for (int j = 0; j < 8; ++j)
#pragma unroll
            for (int e = 0; e < 4; ++e) acc[i][j][e] = 0.f;

    int dr = ((lane >> 3) & 1) * 8 + (lane & 7);
    int dk = ((lane >> 4) & 1) * 16;
    int vmI = lane >> 3, vii = lane & 7;
    int vsrow = (vmI & 1) * 8 + vii;
    int vcolb = (vmI >> 1) * 16;

    int stage = 0;
    for (int kt = 0; kt < ntiles; ++kt) {
        asm volatile("cp.async.wait_group 2;" ::: "memory");
        __syncthreads();

        int jt = kt + 3;
        if (jt < ntiles) {
            int ps = stage + 3; if (ps >= GSTAGES) ps -= GSTAGES;
            uint32_t stb = sbase + ps * STAGE_BYTES;
#pragma unroll
            for (int j = 0; j < 4; ++j) cpasync16(stb + doffA[j], Abase + soffA[j] + jt * 64);
#pragma unroll
            for (int j = 0; j < 8; ++j) cpasync16(stb + doffB[j], Bbase + soffB[j] + (size_t)jt * 64 * N);
        }
        CP_COMMIT();

        uint32_t stb = sbase + stage * STAGE_BYTES;
#pragma unroll
        for (int k16 = 0; k16 < 4; ++k16) {
            uint32_t a[4][4];
#pragma unroll
            for (int i = 0; i < 4; ++i)
                ldsm_x4(a[i], stb + TSWZ((uint32_t)((wm + i * 16 + dr) * 128) + (uint32_t)(k16 * 32 + dk)));
            uint32_t b[4][4];
#pragma unroll
            for (int jj = 0; jj < 4; ++jj) {
                uint32_t off = (uint32_t)((k16 * 16 + vsrow) * 512 + (wn + jj * 16) * 2 + vcolb);
                ldsm_x4_trans(b[jj], stb + B_SMEM_OFF + SWZ512(off));
            }
#pragma unroll
            for (int i = 0; i < 4; ++i)
#pragma unroll
                for (int jj = 0; jj < 4; ++jj) {
                    mma_f16(acc[i][2 * jj],     a[i], b[jj][0], b[jj][1]);
                    mma_f16(acc[i][2 * jj + 1], a[i], b[jj][2], b[jj][3]);
                }
        }
        if (++stage == GSTAGES) stage = 0;
    }

    int lr = lane >> 2, lc = (lane & 3) * 2;
#pragma unroll
    for (int i = 0; i < 4; ++i) {
        int r0 = bm + wm + i * 16 + lr;
        int r1 = r0 + 8;
        size_t ro0 = (size_t)r0 * N, ro1 = (size_t)r1 * N;
#pragma unroll
        for (int j = 0; j < 8; ++j) {
            int c = bn + wn + j * 8 + lc;
            float2 v0 = make_float2(acc[i][j][0], acc[i][j][1]);
            float2 v1 = make_float2(acc[i][j][2], acc[i][j][3]);
            if (EPI == 1) {
                float2 bb = *(const float2*)(bias + c);
                v0.x = gelu_f(v0.x + bb.x); v0.y = gelu_f(v0.y + bb.y);
                v1.x = gelu_f(v1.x + bb.x); v1.y = gelu_f(v1.y + bb.y);
            } else if (EPI == 2) {
                float2 ra = *(const float2*)(res + ro0 + c);
                float2 rb = *(const float2*)(res + ro1 + c);
                v0.x += ra.x; v0.y += ra.y; v1.x += rb.x; v1.y += rb.y;
            } else if (EPI == 3) {
                float2 bb = *(const float2*)(bias + c);
                float2 ra = *(const float2*)(res + ro0 + c);
                float2 rb = *(const float2*)(res + ro1 + c);
                v0.x += bb.x + ra.x; v0.y += bb.y + ra.y;
                v1.x += bb.x + rb.x; v1.y += bb.y + rb.y;
            }
            if (sizeof(OutT) == 2) {
                *(__half2*)((__half*)C + ro0 + c) = __floats2half2_rn(v0.x, v0.y);
                *(__half2*)((__half*)C + ro1 + c) = __floats2half2_rn(v1.x, v1.y);
            } else {
                *(float2*)((float*)C + ro0 + c) = v0;
                *(float2*)((float*)C + ro1 + c) = v1;
            }
        }
    }
}

template <int EPI, typename OutT>
__global__ __launch_bounds__(256, 1)
void tgemm_kernel(const __half* __restrict__ A, const __half* __restrict__ B,
                  const float* __restrict__ bias, const float* __restrict__ res,
                  OutT* __restrict__ C, int N, int K) {
    tgemm_body<EPI, OutT>(A, B, bias, res, C, N, K);
}

__global__ __launch_bounds__(256, 1)
void tgemm_qkv_kernel(const __half* __restrict__ h, const __half* __restrict__ wt,
                      __half* __restrict__ q, __half* __restrict__ k, __half* __restrict__ v) {
    const __half* B = (blockIdx.z == 0) ? (wt + WQ_OFF) : (blockIdx.z == 1) ? (wt + WK_OFF) : (wt + WV_OFF);
    __half* C       = (blockIdx.z == 0) ? q : (blockIdx.z == 1) ? k : v;
    tgemm_body<0, __half>(h, B, nullptr, nullptr, C, DD, DD);
}

// ---------------- fp16 mma flash attention: Br=128, 8 warps, Bc=64 ----------------
#define AT_ROWB    528
#define ATQ_BYTES  (128 * AT_ROWB)                 // 67584
#define ATKV_BYTES (64 * AT_ROWB)                  // 33792
#define ATTN_SMEM  (ATQ_BYTES + 4 * ATKV_BYTES)    // 202752

__device__ __forceinline__ void attn_load_q(uint32_t dstb, const __half* src, int tid) {
#pragma unroll
    for (int j = 0; j < 16; ++j) {
        int idx = tid + 256 * j;
        int row = idx >> 5, seg = idx & 31;
        cpasync16(dstb + row * AT_ROWB + seg * 16, src + (size_t)row * DD + seg * 8);
    }
}
__device__ __forceinline__ void attn_load_kv(uint32_t dstb, const __half* src, int tid) {
#pragma unroll
    for (int j = 0; j < 8; ++j) {
        int idx = tid + 256 * j;
        int row = idx >> 5, seg = idx & 31;
        cpasync16(dstb + row * AT_ROWB + seg * 16, src + (size_t)row * DD + seg * 8);
    }
}

__global__ __launch_bounds__(256, 1) void attn_kernel(const __half* __restrict__ q,
                                                      const __half* __restrict__ k,
                                                      const __half* __restrict__ v,
                                                      __half* __restrict__ y) {
    extern __shared__ __align__(1024) char asmem[];
    uint32_t sb = smem_u32(asmem);
    int tid = threadIdx.x, lane = tid & 31, wid = tid >> 5;   // 8 warps
    int qt = gridDim.x - 1 - blockIdx.x;                      // heavy tiles first
    int hh = blockIdx.y;
    size_t hoff = (size_t)hh * DHD;
    int ntk = 2 * qt + 2;

    uint32_t Qb = sb;
    uint32_t Kb[2] = { sb + ATQ_BYTES, sb + ATQ_BYTES + ATKV_BYTES };
    uint32_t Vb[2] = { sb + ATQ_BYTES + 2 * ATKV_BYTES, sb + ATQ_BYTES + 3 * ATKV_BYTES };

    const __half* qsrc = q + (size_t)(qt * 128) * DD + hoff;

    attn_load_q(Qb, qsrc, tid);
    attn_load_kv(Kb[0], k + hoff, tid);
    attn_load_kv(Vb[0], v + hoff, tid);
    CP_COMMIT();
    attn_load_kv(Kb[1], k + (size_t)64 * DD + hoff, tid);
    attn_load_kv(Vb[1], v + (size_t)64 * DD + hoff, tid);
    CP_COMMIT();

    float o[32][4];
#pragma unroll
    for (int j = 0; j < 32; ++j)
#pragma unroll
        for (int e = 0; e < 4; ++e) o[j][e] = 0.f;
    float m0 = -1e30f, m1 = -1e30f, l0 = 0.f, l1 = 0.f;

    int dr = ((lane >> 3) & 1) * 8 + (lane & 7);
    int dk = ((lane >> 4) & 1) * 16;
    int wm = wid * 16;                       // warp's 16 q-rows within 128
    int lr = lane >> 2, lc = (lane & 3) * 2;
    int vmI = lane >> 3, vii = lane & 7;
    int vsrow = (vmI & 1) * 8 + vii;
    int vcolb = (vmI >> 1) * 16;

    for (int kt = 0; kt < ntk; ++kt) {
        asm volatile("cp.async.wait_group 1;" ::: "memory");
        __syncthreads();
        uint32_t Kt = Kb[kt & 1], Vt = Vb[kt & 1];

        // fully-masked warp tile? (entire 16 rows above diagonal for this kt)
        bool active = (kt * 64 <= qt * 128 + wm + 15);
        if (active) {
            // ---- S = Q K^T : warp computes 16x64 ----
            float s[8][4];
#pragma unroll
            for (int j = 0; j < 8; ++j)
#pragma unroll
                for (int e = 0; e < 4; ++e) s[j][e] = 0.f;

#pragma unroll
            for (int k16 = 0; k16 < 16; ++k16) {
                uint32_t kb = (uint32_t)(k16 * 32 + dk);
                uint32_t a[4];
                ldsm_x4(a, Qb + (uint32_t)((wm + dr) * AT_ROWB) + kb);
#pragma unroll
                for (int jj = 0; jj < 4; ++jj) {
                    uint32_t b[4];
                    ldsm_x4(b, Kt + (uint32_t)((jj * 16 + dr) * AT_ROWB) + kb);
                    mma_f16(s[2 * jj],     a, b[0], b[2]);
                    mma_f16(s[2 * jj + 1], a, b[1], b[3]);
                }
            }

#pragma unroll
            for (int j = 0; j < 8; ++j)
#pragma unroll
                for (int e = 0; e < 4; ++e) s[j][e] *= 0.0625f;
            if (kt >= 2 * qt) {       // tiles intersecting the diagonal
                int rowg_base = qt * 128 + wm + lr;
                int colg_base = kt * 64 + lc;
#pragma unroll
                for (int j = 0; j < 8; ++j)
#pragma unroll
                    for (int e = 0; e < 4; ++e) {
                        int colg = colg_base + 8 * j + (e & 1);
                        int rowg = rowg_base + ((e >> 1) << 3);
                        if (colg > rowg) s[j][e] = -1e30f;
                    }
            }

            // ---- online softmax (rows lr, lr+8 of warp tile) ----
            float tm0 = -1e30f, tm1 = -1e30f;
#pragma unroll
            for (int j = 0; j < 8; ++j) {
                tm0 = fmaxf(tm0, fmaxf(s[j][0], s[j][1]));
                tm1 = fmaxf(tm1, fmaxf(s[j][2], s[j][3]));
            }
            tm0 = fmaxf(tm0, __shfl_xor_sync(~0u, tm0, 1));
            tm0 = fmaxf(tm0, __shfl_xor_sync(~0u, tm0, 2));
            tm1 = fmaxf(tm1, __shfl_xor_sync(~0u, tm1, 1));
            tm1 = fmaxf(tm1, __shfl_xor_sync(~0u, tm1, 2));
            float nm0 = fmaxf(m0, tm0), nm1 = fmaxf(m1, tm1);
            float al0 = __expf(m0 - nm0), al1 = __expf(m1 - nm1);
            m0 = nm0; m1 = nm1;
            float rs0 = 0.f, rs1 = 0.f;
#pragma unroll
            for (int j = 0; j < 8; ++j) {
                s[j][0] = __expf(s[j][0] - nm0);
                s[j][1] = __expf(s[j][1] - nm0);
                s[j][2] = __expf(s[j][2] - nm1);
                s[j][3] = __expf(s[j][3] - nm1);
                rs0 += s[j][0] + s[j][1];
                rs1 += s[j][2] + s[j][3];
            }
            rs0 += __shfl_xor_sync(~0u, rs0, 1); rs0 += __shfl_xor_sync(~0u, rs0, 2);
            rs1 += __shfl_xor_sync(~0u, rs1, 1); rs1 += __shfl_xor_sync(~0u, rs1, 2);
            l0 = l0 * al0 + rs0;
            l1 = l1 * al1 + rs1;
#pragma unroll
            for (int j = 0; j < 32; ++j) {
                o[j][0] *= al0; o[j][1] *= al0;
                o[j][2] *= al1; o[j][3] *= al1;
            }

            // ---- O += P V ----
#pragma unroll
            for (int t = 0; t < 4; ++t) {
                uint32_t pa[4];
                pa[0] = h2pack(s[2 * t][0],     s[2 * t][1]);
                pa[1] = h2pack(s[2 * t][2],     s[2 * t][3]);
                pa[2] = h2pack(s[2 * t + 1][0], s[2 * t + 1][1]);
                pa[3] = h2pack(s[2 * t + 1][2], s[2 * t + 1][3]);
                uint32_t vrow = (uint32_t)((16 * t + vsrow) * AT_ROWB);
#pragma unroll
                for (int np = 0; np < 16; ++np) {
                    uint32_t bb[4];
                    ldsm_x4_trans(bb, Vt + vrow + (uint32_t)(np * 32 + vcolb));
                    mma_f16(o[2 * np],     pa, bb[0], bb[1]);
                    mma_f16(o[2 * np + 1], pa, bb[2], bb[3]);
                }
            }
        }

        __syncthreads();
        int jt = kt + 2;
        if (jt < ntk) {
            attn_load_kv(Kb[kt & 1], k + (size_t)(jt * 64) * DD + hoff, tid);
            attn_load_kv(Vb[kt & 1], v + (size_t)(jt * 64) * DD + hoff, tid);
        }
        CP_COMMIT();
    }

    float inv0 = 1.f / l0, inv1 = 1.f / l1;
    size_t r0 = (size_t)(qt * 128 + wm + lr) * DD + hoff;
    size_t r1 = r0 + (size_t)8 * DD;
#pragma unroll
    for (int j = 0; j < 32; ++j) {
        *(__half2*)(y + r0 + 8 * j + lc) = __floats2half2_rn(o[j][0] * inv0, o[j][1] * inv0);
        *(__half2*)(y + r1 + 8 * j + lc) = __floats2half2_rn(o[j][2] * inv1, o[j][3] * inv1);
    }
}

// ---------------- launcher (tri-stream overlap) ----------------
extern "C" void kernel_launch(void* const* d_in, const int* in_sizes, int n_in,
                              void* d_out, int out_size) {
    const float* x     = (const float*)d_in[0];
    const float* wq    = (const float*)d_in[1];
    const float* wk    = (const float*)d_in[2];
    const float* wv    = (const float*)d_in[3];
    const float* wo    = (const float*)d_in[4];
    const float* w_in  = (const float*)d_in[5];
    const float* b_in  = (const float*)d_in[6];
    const float* w_out = (const float*)d_in[7];
    const float* b_out = (const float*)d_in[8];
    const float* ln_s  = (const float*)d_in[9];
    const float* ln_o  = (const float*)d_in[10];
    float* out = (float*)d_out;

    __half *h, *q, *k, *v, *y, *m, *wt;
    float *tmp;
    cudaGetSymbolAddress((void**)&h,   g_h);
    cudaGetSymbolAddress((void**)&q,   g_q);
    cudaGetSymbolAddress((void**)&k,   g_k);
    cudaGetSymbolAddress((void**)&v,   g_v);
    cudaGetSymbolAddress((void**)&y,   g_y);
    cudaGetSymbolAddress((void**)&tmp, g_tmp);
    cudaGetSymbolAddress((void**)&m,   g_m);
    cudaGetSymbolAddress((void**)&wt,  g_wt);

    cudaFuncSetAttribute(attn_kernel, cudaFuncAttributeMaxDynamicSharedMemorySize, ATTN_SMEM);
    cudaFuncSetAttribute(tgemm_qkv_kernel, cudaFuncAttributeMaxDynamicSharedMemorySize, GSMEM_TOTAL);
    cudaFuncSetAttribute(tgemm_kernel<1, __half>, cudaFuncAttributeMaxDynamicSharedMemorySize, GSMEM_TOTAL);
    cudaFuncSetAttribute(tgemm_kernel<2, float>,  cudaFuncAttributeMaxDynamicSharedMemorySize, GSMEM_TOTAL);
    cudaFuncSetAttribute(tgemm_kernel<3, float>,  cudaFuncAttributeMaxDynamicSharedMemorySize, GSMEM_TOTAL);

    // lazy one-time stream/event setup (handles only; no device allocations)
    static cudaStream_t s1 = nullptr, s2 = nullptr;
    static cudaEvent_t evRoot = nullptr, evLN = nullptr, evKV = nullptr,
                       evWoCv = nullptr, evWoutCv = nullptr, evM = nullptr;
    if (s1 == nullptr) {
        cudaStreamCreateWithFlags(&s1, cudaStreamNonBlocking);
        cudaStreamCreateWithFlags(&s2, cudaStreamNonBlocking);
        cudaEventCreateWithFlags(&evRoot,   cudaEventDisableTiming);
        cudaEventCreateWithFlags(&evLN,     cudaEventDisableTiming);
        cudaEventCreateWithFlags(&evKV,     cudaEventDisableTiming);
        cudaEventCreateWithFlags(&evWoCv,   cudaEventDisableTiming);
        cudaEventCreateWithFlags(&evWoutCv, cudaEventDisableTiming);
        cudaEventCreateWithFlags(&evM,      cudaEventDisableTiming);
    }

    const int G44  = (DD / 4) * DD / 256;
    const int G416 = (DD / 4) * DFF / 256;

    // fork s1, s2 from main stream
    cudaEventRecord(evRoot, 0);
    cudaStreamWaitEvent(s1, evRoot, 0);
    cudaStreamWaitEvent(s2, evRoot, 0);

    // s2: wo + w_out converts (consumed late; hide under GEMMs)
    convert_kernel<<<G44, 256, 0, s2>>>((const float4*)wo, (uint2*)(wt + WO_OFF));
    cudaEventRecord(evWoCv, s2);
    convert_kernel<<<G416, 256, 0, s2>>>((const float4*)w_out, (uint2*)(wt + WOUT_OFF));
    cudaEventRecord(evWoutCv, s2);

    // s1: wk + wv converts (QKV dep), then w_in convert + MLP-in GEMM
    convert_kernel<<<G44, 256, 0, s1>>>((const float4*)wk, (uint2*)(wt + WK_OFF));
    convert_kernel<<<G44, 256, 0, s1>>>((const float4*)wv, (uint2*)(wt + WV_OFF));
    cudaEventRecord(evKV, s1);
    convert_kernel<<<G416, 256, 0, s1>>>((const float4*)w_in, (uint2*)(wt + WIN_OFF));

    // main: wq convert + LN
    convert_kernel<<<G44, 256>>>((const float4*)wq, (uint2*)(wt + WQ_OFF));
    ln_kernel<<<TT, 256>>>(x, ln_s, ln_o, h);
    cudaEventRecord(evLN, 0);

    // s1: MLP-in GEMM (needs h + w_in)
    cudaStreamWaitEvent(s1, evLN, 0);
    tgemm_kernel<1, __half><<<dim3(DFF / 256, TT / 128), 256, GSMEM_TOTAL, s1>>>(h, wt + WIN_OFF, b_in, nullptr, m, DFF, DD);
    cudaEventRecord(evM, s1);

    // main: QKV -> RoPE -> attention -> Wo
    cudaStreamWaitEvent(0, evKV, 0);
    tgemm_qkv_kernel<<<dim3(DD / 256, TT / 128, 3), 256, GSMEM_TOTAL>>>(h, wt, q, k, v);
    rope_kernel<<<(TT * HH * 32) / 256, 256>>>(q, k);
    attn_kernel<<<dim3(TT / 128, HH), 256, ATTN_SMEM>>>(q, k, v, y);
    cudaStreamWaitEvent(0, evWoCv, 0);
    tgemm_kernel<2, float><<<dim3(DD / 256, TT / 128), 256, GSMEM_TOTAL>>>(y, wt + WO_OFF, nullptr, x, tmp, DD, DD);

    // join: MLP-out needs m (s1), w_out (s2), tmp (main)
    cudaStreamWaitEvent(0, evM, 0);
    cudaStreamWaitEvent(0, evWoutCv, 0);
    tgemm_kernel<3, float><<<dim3(DD / 256, TT / 128), 256, GSMEM_TOTAL>>>(m, wt + WOUT_OFF, b_out, tmp, out, DD, DFF);
}

// round 13
// speedup vs baseline: 8.9300x; 1.0013x over previous
#include <cuda_runtime.h>
#include <cuda_fp16.h>
#include <math.h>
#include <stdint.h>

// ---------------- problem constants ----------------
#define TT    2048
#define DD    4096
#define HH    16
#define DHD   256
#define DFF   16384

// ---------------- scratch (device globals; no cudaMalloc allowed) ----------------
__device__ __half g_h  [TT * DD];      // LN output
__device__ __half g_q  [TT * DD];
__device__ __half g_k  [TT * DD];
__device__ __half g_v  [TT * DD];
__device__ __half g_y  [TT * DD];      // attention output
__device__ float  g_tmp[TT * DD];
__device__ __half g_m  [TT * DFF];
// fp16 weights in NATIVE [K,N] layout (converted, not transposed)
__device__ __half g_wt [4u*4096u*4096u + 2u*4096u*16384u];

#define WQ_OFF    0u
#define WK_OFF    16777216u
#define WV_OFF    33554432u
#define WO_OFF    50331648u
#define WIN_OFF   67108864u
#define WOUT_OFF  134217728u

// ---------------- helpers ----------------
__device__ __forceinline__ uint32_t smem_u32(const void* p) {
    uint32_t r;
    asm("{ .reg .u64 t; cvta.to.shared.u64 t, %1; cvt.u32.u64 %0, t; }" : "=r"(r) : "l"(p));
    return r;
}
__device__ __forceinline__ void cpasync16(uint32_t dst, const void* src) {
    asm volatile("cp.async.cg.shared.global [%0], [%1], 16;" :: "r"(dst), "l"(src));
}
#define CP_COMMIT() asm volatile("cp.async.commit_group;" ::: "memory")

__device__ __forceinline__ void ldsm_x4(uint32_t (&r)[4], uint32_t addr) {
    asm volatile("ldmatrix.sync.aligned.m8n8.x4.shared.b16 {%0,%1,%2,%3}, [%4];"
        : "=r"(r[0]), "=r"(r[1]), "=r"(r[2]), "=r"(r[3]) : "r"(addr));
}
__device__ __forceinline__ void ldsm_x4_trans(uint32_t (&r)[4], uint32_t addr) {
    asm volatile("ldmatrix.sync.aligned.m8n8.x4.trans.shared.b16 {%0,%1,%2,%3}, [%4];"
        : "=r"(r[0]), "=r"(r[1]), "=r"(r[2]), "=r"(r[3]) : "r"(addr));
}
__device__ __forceinline__ void mma_f16(float (&d)[4], const uint32_t (&a)[4],
                                        uint32_t b0, uint32_t b1) {
    asm volatile("mma.sync.aligned.m16n8k16.row.col.f32.f16.f16.f32 "
        "{%0,%1,%2,%3}, {%4,%5,%6,%7}, {%8,%9}, {%0,%1,%2,%3};"
        : "+f"(d[0]), "+f"(d[1]), "+f"(d[2]), "+f"(d[3])
        : "r"(a[0]), "r"(a[1]), "r"(a[2]), "r"(a[3]), "r"(b0), "r"(b1));
}
__device__ __forceinline__ uint32_t h2pack(float x, float y) {
    __half2 h = __floats2half2_rn(x, y);
    return *(uint32_t*)&h;
}

// swizzles: 128B-row tiles (A) and 512B-row tiles (B)
#define TSWZ(off)   ((off) ^ (((off) >> 3) & 0x70))
#define SWZ512(off) ((off) ^ (((off) >> 5) & 0x70))

// ---------------- LayerNorm (fp16 output) ----------------
__global__ __launch_bounds__(256) void ln_kernel(const float* __restrict__ x,
                                                 const float* __restrict__ g,
                                                 const float* __restrict__ b,
                                                 __half* __restrict__ h) {
    int row = blockIdx.x;
    const float4* xr = (const float4*)(x + (size_t)row * DD);
    float s = 0.f, s2 = 0.f;
    for (int i = threadIdx.x; i < DD / 4; i += 256) {
        float4 v = xr[i];
        s  += v.x + v.y + v.z + v.w;
        s2 += v.x*v.x + v.y*v.y + v.z*v.z + v.w*v.w;
    }
    for (int o = 16; o > 0; o >>= 1) {
        s  += __shfl_xor_sync(~0u, s,  o);
        s2 += __shfl_xor_sync(~0u, s2, o);
    }
    __shared__ float sh[16];
    int w = threadIdx.x >> 5;
    if ((threadIdx.x & 31) == 0) { sh[w] = s; sh[8 + w] = s2; }
    __syncthreads();
    if (threadIdx.x < 32) {
        float a = threadIdx.x < 8 ? sh[threadIdx.x]     : 0.f;
        float c = threadIdx.x < 8 ? sh[8 + threadIdx.x] : 0.f;
        for (int o = 4; o > 0; o >>= 1) {
            a += __shfl_xor_sync(~0u, a, o);
            c += __shfl_xor_sync(~0u, c, o);
        }
        if (threadIdx.x == 0) { sh[0] = a; sh[8] = c; }
    }
    __syncthreads();
    float mean = sh[0] * (1.f / DD);
    float var  = sh[8] * (1.f / DD) - mean * mean;
    float rstd = rsqrtf(var + 1e-6f);
    __half2* hr = (__half2*)(h + (size_t)row * DD);
    const float4* gg4 = (const float4*)g;
    const float4* bb4 = (const float4*)b;
    for (int i = threadIdx.x; i < DD / 4; i += 256) {
        float4 v = xr[i], gg = gg4[i], bb = bb4[i];
        hr[i * 2]     = __floats2half2_rn((v.x - mean) * rstd * gg.x + bb.x,
                                          (v.y - mean) * rstd * gg.y + bb.y);
        hr[i * 2 + 1] = __floats2half2_rn((v.z - mean) * rstd * gg.z + bb.z,
                                          (v.w - mean) * rstd * gg.w + bb.w);
    }
}

// ---------------- streaming fp32 -> fp16 convert (layout preserved) ----------------
__global__ __launch_bounds__(256) void convert_kernel(const float4* __restrict__ in,
                                                      uint2* __restrict__ out) {
    int i = blockIdx.x * 256 + threadIdx.x;
    float4 v = in[i];
    uint2 o;
    o.x = h2pack(v.x, v.y);
    o.y = h2pack(v.z, v.w);
    out[i] = o;
}

// ---------------- RoPE in-place on fp16 q, k ----------------
__global__ __launch_bounds__(256) void rope_kernel(__half* __restrict__ q, __half* __restrict__ k) {
    int idx = blockIdx.x * 256 + threadIdx.x;
    int f = idx & 31;
    int hh = (idx >> 5) & (HH - 1);
    int t = idx >> 9;
    float inv = 1.0f / powf(10000.0f, (float)f * (1.0f / 32.0f));
    float ang = (float)t * inv;
    float sn, cs;
    sincosf(ang, &sn, &cs);
    size_t base = (size_t)t * DD + hh * DHD + f;
    {
        float a = __half2float(q[base]), b = __half2float(q[base + 32]);
        q[base]      = __float2half_rn(a * cs - b * sn);
        q[base + 32] = __float2half_rn(a * sn + b * cs);
    }
    {
        float a = __half2float(k[base]), b = __half2float(k[base + 32]);
        k[base]      = __float2half_rn(a * cs - b * sn);
        k[base + 32] = __float2half_rn(a * sn + b * cs);
    }
}

// ---------------- fp16 mma GEMM: CTA 128x256, warp 64x64, 4-stage cp.async ----------------
__device__ __forceinline__ float gelu_f(float v) {
    float t = tanhf(0.7978845608028654f * (v + 0.044715f * v * v * v));
    return 0.5f * v * (1.f + t);
}

#define STAGE_BYTES 49152            // A 16KB (128m x 128B) + B 32KB (64k x 512B)
#define B_SMEM_OFF  16384
#define GSTAGES 4
#define GSMEM_TOTAL (GSTAGES * STAGE_BYTES)   // 196608

template <int EPI, typename OutT>
__device__ __forceinline__ void tgemm_body(const __half* __restrict__ A, const __half* __restrict__ B,
                                           const float* __restrict__ bias, const float* __restrict__ res,
                                           OutT* __restrict__ C, int N, int K) {
    extern __shared__ __align__(1024) char gsm[];
    uint32_t sbase = smem_u32(gsm);
    int tid = threadIdx.x, lane = tid & 31, wid = tid >> 5;

    // column-major CTA raster: consecutive CTAs walk the M dimension so the
    // ~148 co-resident CTAs share ONE B strip (read B once, keep A in L2)
    int bid = blockIdx.y * gridDim.x + blockIdx.x;
    int by  = bid % gridDim.y;
    int bx  = bid / gridDim.y;
    int bm = by * 128, bn = bx * 256;

    int ntiles = K >> 6;
    int wm = (wid >> 2) * 64, wn = (wid & 3) * 64;

    uint32_t doffA[4]; int soffA[4];
#pragma unroll
    for (int j = 0; j < 4; ++j) {
        int idx = tid + 256 * j;
        int row = idx >> 3, seg = idx & 7;
        soffA[j] = row * K + seg * 8;
        doffA[j] = TSWZ((uint32_t)(row * 128 + seg * 16));
    }
    uint32_t doffB[8]; size_t soffB[8];
#pragma unroll
    for (int j = 0; j < 8; ++j) {
        int idx = tid + 256 * j;
        int krow = idx >> 5, seg = idx & 31;
        soffB[j] = (size_t)krow * N + seg * 8;
        doffB[j] = B_SMEM_OFF + SWZ512((uint32_t)(krow * 512 + seg * 16));
    }
    const __half* Abase = A + (size_t)bm * K;
    const __half* Bbase = B + bn;

#pragma unroll
    for (int p = 0; p < GSTAGES - 1; ++p) {
        uint32_t stb = sbase + p * STAGE_BYTES;
#pragma unroll
        for (int j = 0; j < 4; ++j) cpasync16(stb + doffA[j], Abase + soffA[j] + p * 64);
#pragma unroll
        for (int j = 0; j < 8; ++j) cpasync16(stb + doffB[j], Bbase + soffB[j] + (size_t)p * 64 * N);
        CP_COMMIT();
    }

    float acc[4][8][4];
#pragma unroll
    for (int i = 0; i < 4; ++i)
#pragma unroll
        for (int j = 0; j < 8; ++j)
#pragma unroll
            for (int e = 0; e < 4; ++e) acc[i][j][e] = 0.f;

    int dr = ((lane >> 3) & 1) * 8 + (lane & 7);
    int dk = ((lane >> 4) & 1) * 16;
    int vmI = lane >> 3, vii = lane & 7;
    int vsrow = (vmI & 1) * 8 + vii;
    int vcolb = (vmI >> 1) * 16;

    int stage = 0;
    for (int kt = 0; kt < ntiles; ++kt) {
        asm volatile("cp.async.wait_group 2;" ::: "memory");
        __syncthreads();

        int jt = kt + 3;
        if (jt < ntiles) {
            int ps = stage + 3; if (ps >= GSTAGES) ps -= GSTAGES;
            uint32_t stb = sbase + ps * STAGE_BYTES;
#pragma unroll
            for (int j = 0; j < 4; ++j) cpasync16(stb + doffA[j], Abase + soffA[j] + jt * 64);
#pragma unroll
            for (int j = 0; j < 8; ++j) cpasync16(stb + doffB[j], Bbase + soffB[j] + (size_t)jt * 64 * N);
        }
        CP_COMMIT();

        uint32_t stb = sbase + stage * STAGE_BYTES;
#pragma unroll
        for (int k16 = 0; k16 < 4; ++k16) {
            uint32_t a[4][4];
#pragma unroll
            for (int i = 0; i < 4; ++i)
                ldsm_x4(a[i], stb + TSWZ((uint32_t)((wm + i * 16 + dr) * 128) + (uint32_t)(k16 * 32 + dk)));
            uint32_t b[4][4];
#pragma unroll
            for (int jj = 0; jj < 4; ++jj) {
                uint32_t off = (uint32_t)((k16 * 16 + vsrow) * 512 + (wn + jj * 16) * 2 + vcolb);
                ldsm_x4_trans(b[jj], stb + B_SMEM_OFF + SWZ512(off));
            }
#pragma unroll
            for (int i = 0; i < 4; ++i)
#pragma unroll
                for (int jj = 0; jj < 4; ++jj) {
                    mma_f16(acc[i][2 * jj],     a[i], b[jj][0], b[jj][1]);
                    mma_f16(acc[i][2 * jj + 1], a[i], b[jj][2], b[jj][3]);
                }
        }
        if (++stage == GSTAGES) stage = 0;
    }

    int lr = lane >> 2, lc = (lane & 3) * 2;
#pragma unroll
    for (int i = 0; i < 4; ++i) {
        int r0 = bm + wm + i * 16 + lr;
        int r1 = r0 + 8;
        size_t ro0 = (size_t)r0 * N, ro1 = (size_t)r1 * N;
#pragma unroll
        for (int j = 0; j < 8; ++j) {
            int c = bn + wn + j * 8 + lc;
            float2 v0 = make_float2(acc[i][j][0], acc[i][j][1]);
            float2 v1 = make_float2(acc[i][j][2], acc[i][j][3]);
            if (EPI == 1) {
                float2 bb = *(const float2*)(bias + c);
                v0.x = gelu_f(v0.x + bb.x); v0.y = gelu_f(v0.y + bb.y);
                v1.x = gelu_f(v1.x + bb.x); v1.y = gelu_f(v1.y + bb.y);
            } else if (EPI == 2) {
                float2 ra = *(const float2*)(res + ro0 + c);
                float2 rb = *(const float2*)(res + ro1 + c);
                v0.x += ra.x; v0.y += ra.y; v1.x += rb.x; v1.y += rb.y;
            } else if (EPI == 3) {
                float2 bb = *(const float2*)(bias + c);
                float2 ra = *(const float2*)(res + ro0 + c);
                float2 rb = *(const float2*)(res + ro1 + c);
                v0.x += bb.x + ra.x; v0.y += bb.y + ra.y;
                v1.x += bb.x + rb.x; v1.y += bb.y + rb.y;
            }
            if (sizeof(OutT) == 2) {
                *(__half2*)((__half*)C + ro0 + c) = __floats2half2_rn(v0.x, v0.y);
                *(__half2*)((__half*)C + ro1 + c) = __floats2half2_rn(v1.x, v1.y);
            } else {
                *(float2*)((float*)C + ro0 + c) = v0;
                *(float2*)((float*)C + ro1 + c) = v1;
            }
        }
    }
}

template <int EPI, typename OutT>
__global__ __launch_bounds__(256, 1)
void tgemm_kernel(const __half* __restrict__ A, const __half* __restrict__ B,
                  const float* __restrict__ bias, const float* __restrict__ res,
                  OutT* __restrict__ C, int N, int K) {
    tgemm_body<EPI, OutT>(A, B, bias, res, C, N, K);
}

__global__ __launch_bounds__(256, 1)
void tgemm_qkv_kernel(const __half* __restrict__ h, const __half* __restrict__ wt,
                      __half* __restrict__ q, __half* __restrict__ k, __half* __restrict__ v) {
    const __half* B = (blockIdx.z == 0) ? (wt + WQ_OFF) : (blockIdx.z == 1) ? (wt + WK_OFF) : (wt + WV_OFF);
    __half* C       = (blockIdx.z == 0) ? q : (blockIdx.z == 1) ? k : v;
    tgemm_body<0, __half>(h, B, nullptr, nullptr, C, DD, DD);
}

// ---------------- fp16 mma flash attention: Br=128, 8 warps, Bc=64 ----------------
#define AT_ROWB    528
#define ATQ_BYTES  (128 * AT_ROWB)                 // 67584
#define ATKV_BYTES (64 * AT_ROWB)                  // 33792
#define ATTN_SMEM  (ATQ_BYTES + 4 * ATKV_BYTES)    // 202752

__device__ __forceinline__ void attn_load_q(uint32_t dstb, const __half* src, int tid) {
#pragma unroll
    for (int j = 0; j < 16; ++j) {
        int idx = tid + 256 * j;
        int row = idx >> 5, seg = idx & 31;
        cpasync16(dstb + row * AT_ROWB + seg * 16, src + (size_t)row * DD + seg * 8);
    }
}
__device__ __forceinline__ void attn_load_kv(uint32_t dstb, const __half* src, int tid) {
#pragma unroll
    for (int j = 0; j < 8; ++j) {
        int idx = tid + 256 * j;
        int row = idx >> 5, seg = idx & 31;
        cpasync16(dstb + row * AT_ROWB + seg * 16, src + (size_t)row * DD + seg * 8);
    }
}

__global__ __launch_bounds__(256, 1) void attn_kernel(const __half* __restrict__ q,
                                                      const __half* __restrict__ k,
                                                      const __half* __restrict__ v,
                                                      __half* __restrict__ y) {
    extern __shared__ __align__(1024) char asmem[];
    uint32_t sb = smem_u32(asmem);
    int tid = threadIdx.x, lane = tid & 31, wid = tid >> 5;   // 8 warps
    int qt = gridDim.x - 1 - blockIdx.x;                      // heavy tiles first
    int hh = blockIdx.y;
    size_t hoff = (size_t)hh * DHD;
    int ntk = 2 * qt + 2;

    uint32_t Qb = sb;
    uint32_t Kb[2] = { sb + ATQ_BYTES, sb + ATQ_BYTES + ATKV_BYTES };
    uint32_t Vb[2] = { sb + ATQ_BYTES + 2 * ATKV_BYTES, sb + ATQ_BYTES + 3 * ATKV_BYTES };

    const __half* qsrc = q + (size_t)(qt * 128) * DD + hoff;

    attn_load_q(Qb, qsrc, tid);
    attn_load_kv(Kb[0], k + hoff, tid);
    attn_load_kv(Vb[0], v + hoff, tid);
    CP_COMMIT();
    attn_load_kv(Kb[1], k + (size_t)64 * DD + hoff, tid);
    attn_load_kv(Vb[1], v + (size_t)64 * DD + hoff, tid);
    CP_COMMIT();

    float o[32][4];
#pragma unroll
    for (int j = 0; j < 32; ++j)
#pragma unroll
        for (int e = 0; e < 4; ++e) o[j][e] = 0.f;
    float m0 = -1e30f, m1 = -1e30f, l0 = 0.f, l1 = 0.f;

    int dr = ((lane >> 3) & 1) * 8 + (lane & 7);
    int dk = ((lane >> 4) & 1) * 16;
    int wm = wid * 16;                       // warp's 16 q-rows within 128
    int lr = lane >> 2, lc = (lane & 3) * 2;
    int vmI = lane >> 3, vii = lane & 7;
    int vsrow = (vmI & 1) * 8 + vii;
    int vcolb = (vmI >> 1) * 16;

    for (int kt = 0; kt < ntk; ++kt) {
        asm volatile("cp.async.wait_group 1;" ::: "memory");
        __syncthreads();
        uint32_t Kt = Kb[kt & 1], Vt = Vb[kt & 1];

        // fully-masked warp tile? (entire 16 rows above diagonal for this kt)
        bool active = (kt * 64 <= qt * 128 + wm + 15);
        if (active) {
            // ---- S = Q K^T : warp computes 16x64 ----
            float s[8][4];
#pragma unroll
            for (int j = 0; j < 8; ++j)
#pragma unroll
                for (int e = 0; e < 4; ++e) s[j][e] = 0.f;

#pragma unroll
            for (int k16 = 0; k16 < 16; ++k16) {
                uint32_t kb = (uint32_t)(k16 * 32 + dk);
                uint32_t a[4];
                ldsm_x4(a, Qb + (uint32_t)((wm + dr) * AT_ROWB) + kb);
#pragma unroll
                for (int jj = 0; jj < 4; ++jj) {
                    uint32_t b[4];
                    ldsm_x4(b, Kt + (uint32_t)((jj * 16 + dr) * AT_ROWB) + kb);
                    mma_f16(s[2 * jj],     a, b[0], b[2]);
                    mma_f16(s[2 * jj + 1], a, b[1], b[3]);
                }
            }

#pragma unroll
            for (int j = 0; j < 8; ++j)
#pragma unroll
                for (int e = 0; e < 4; ++e) s[j][e] *= 0.0625f;
            if (kt >= 2 * qt) {       // tiles intersecting the diagonal
                int rowg_base = qt * 128 + wm + lr;
                int colg_base = kt * 64 + lc;
#pragma unroll
                for (int j = 0; j < 8; ++j)
#pragma unroll
                    for (int e = 0; e < 4; ++e) {
                        int colg = colg_base + 8 * j + (e & 1);
                        int rowg = rowg_base + ((e >> 1) << 3);
                        if (colg > rowg) s[j][e] = -1e30f;
                    }
            }

            // ---- online softmax (rows lr, lr+8 of warp tile) ----
            float tm0 = -1e30f, tm1 = -1e30f;
#pragma unroll
            for (int j = 0; j < 8; ++j) {
                tm0 = fmaxf(tm0, fmaxf(s[j][0], s[j][1]));
                tm1 = fmaxf(tm1, fmaxf(s[j][2], s[j][3]));
            }
            tm0 = fmaxf(tm0, __shfl_xor_sync(~0u, tm0, 1));
            tm0 = fmaxf(tm0, __shfl_xor_sync(~0u, tm0, 2));
            tm1 = fmaxf(tm1, __shfl_xor_sync(~0u, tm1, 1));
            tm1 = fmaxf(tm1, __shfl_xor_sync(~0u, tm1, 2));
            float nm0 = fmaxf(m0, tm0), nm1 = fmaxf(m1, tm1);
            float al0 = __expf(m0 - nm0), al1 = __expf(m1 - nm1);
            m0 = nm0; m1 = nm1;
            float rs0 = 0.f, rs1 = 0.f;
#pragma unroll
            for (int j = 0; j < 8; ++j) {
                s[j][0] = __expf(s[j][0] - nm0);
                s[j][1] = __expf(s[j][1] - nm0);
                s[j][2] = __expf(s[j][2] - nm1);
                s[j][3] = __expf(s[j][3] - nm1);
                rs0 += s[j][0] + s[j][1];
                rs1 += s[j][2] + s[j][3];
            }
            rs0 += __shfl_xor_sync(~0u, rs0, 1); rs0 += __shfl_xor_sync(~0u, rs0, 2);
            rs1 += __shfl_xor_sync(~0u, rs1, 1); rs1 += __shfl_xor_sync(~0u, rs1, 2);
            l0 = l0 * al0 + rs0;
            l1 = l1 * al1 + rs1;
#pragma unroll
            for (int j = 0; j < 32; ++j) {
                o[j][0] *= al0; o[j][1] *= al0;
                o[j][2] *= al1; o[j][3] *= al1;
            }

            // ---- O += P V ----
#pragma unroll
            for (int t = 0; t < 4; ++t) {
                uint32_t pa[4];
                pa[0] = h2pack(s[2 * t][0],     s[2 * t][1]);
                pa[1] = h2pack(s[2 * t][2],     s[2 * t][3]);
                pa[2] = h2pack(s[2 * t + 1][0], s[2 * t + 1][1]);
                pa[3] = h2pack(s[2 * t + 1][2], s[2 * t + 1][3]);
                uint32_t vrow = (uint32_t)((16 * t + vsrow) * AT_ROWB);
#pragma unroll
                for (int np = 0; np < 16; ++np) {
                    uint32_t bb[4];
                    ldsm_x4_trans(bb, Vt + vrow + (uint32_t)(np * 32 + vcolb));
                    mma_f16(o[2 * np],     pa, bb[0], bb[1]);
                    mma_f16(o[2 * np + 1], pa, bb[2], bb[3]);
                }
            }
        }

        __syncthreads();
        int jt = kt + 2;
        if (jt < ntk) {
            attn_load_kv(Kb[kt & 1], k + (size_t)(jt * 64) * DD + hoff, tid);
            attn_load_kv(Vb[kt & 1], v + (size_t)(jt * 64) * DD + hoff, tid);
        }
        CP_COMMIT();
    }

    float inv0 = 1.f / l0, inv1 = 1.f / l1;
    size_t r0 = (size_t)(qt * 128 + wm + lr) * DD + hoff;
    size_t r1 = r0 + (size_t)8 * DD;
#pragma unroll
    for (int j = 0; j < 32; ++j) {
        *(__half2*)(y + r0 + 8 * j + lc) = __floats2half2_rn(o[j][0] * inv0, o[j][1] * inv0);
        *(__half2*)(y + r1 + 8 * j + lc) = __floats2half2_rn(o[j][2] * inv1, o[j][3] * inv1);
    }
}

// ---------------- launcher (tri-stream overlap) ----------------
extern "C" void kernel_launch(void* const* d_in, const int* in_sizes, int n_in,
                              void* d_out, int out_size) {
    const float* x     = (const float*)d_in[0];
    const float* wq    = (const float*)d_in[1];
    const float* wk    = (const float*)d_in[2];
    const float* wv    = (const float*)d_in[3];
    const float* wo    = (const float*)d_in[4];
    const float* w_in  = (const float*)d_in[5];
    const float* b_in  = (const float*)d_in[6];
    const float* w_out = (const float*)d_in[7];
    const float* b_out = (const float*)d_in[8];
    const float* ln_s  = (const float*)d_in[9];
    const float* ln_o  = (const float*)d_in[10];
    float* out = (float*)d_out;

    __half *h, *q, *k, *v, *y, *m, *wt;
    float *tmp;
    cudaGetSymbolAddress((void**)&h,   g_h);
    cudaGetSymbolAddress((void**)&q,   g_q);
    cudaGetSymbolAddress((void**)&k,   g_k);
    cudaGetSymbolAddress((void**)&v,   g_v);
    cudaGetSymbolAddress((void**)&y,   g_y);
    cudaGetSymbolAddress((void**)&tmp, g_tmp);
    cudaGetSymbolAddress((void**)&m,   g_m);
    cudaGetSymbolAddress((void**)&wt,  g_wt);

    cudaFuncSetAttribute(attn_kernel, cudaFuncAttributeMaxDynamicSharedMemorySize, ATTN_SMEM);
    cudaFuncSetAttribute(tgemm_qkv_kernel, cudaFuncAttributeMaxDynamicSharedMemorySize, GSMEM_TOTAL);
    cudaFuncSetAttribute(tgemm_kernel<1, __half>, cudaFuncAttributeMaxDynamicSharedMemorySize, GSMEM_TOTAL);
    cudaFuncSetAttribute(tgemm_kernel<2, float>,  cudaFuncAttributeMaxDynamicSharedMemorySize, GSMEM_TOTAL);
    cudaFuncSetAttribute(tgemm_kernel<3, float>,  cudaFuncAttributeMaxDynamicSharedMemorySize, GSMEM_TOTAL);

    // lazy one-time stream/event setup (handles only; no device allocations)
    static cudaStream_t s1 = nullptr, s2 = nullptr;
    static cudaEvent_t evRoot = nullptr, evLN = nullptr, evKV = nullptr,
                       evWoCv = nullptr, evWoutCv = nullptr, evM = nullptr;
    if (s1 == nullptr) {
        cudaStreamCreateWithFlags(&s1, cudaStreamNonBlocking);
        cudaStreamCreateWithFlags(&s2, cudaStreamNonBlocking);
        cudaEventCreateWithFlags(&evRoot,   cudaEventDisableTiming);
        cudaEventCreateWithFlags(&evLN,     cudaEventDisableTiming);
        cudaEventCreateWithFlags(&evKV,     cudaEventDisableTiming);
        cudaEventCreateWithFlags(&evWoCv,   cudaEventDisableTiming);
        cudaEventCreateWithFlags(&evWoutCv, cudaEventDisableTiming);
        cudaEventCreateWithFlags(&evM,      cudaEventDisableTiming);
    }

    const int G44  = (DD / 4) * DD / 256;
    const int G416 = (DD / 4) * DFF / 256;

    // fork s1, s2 from main stream
    cudaEventRecord(evRoot, 0);
    cudaStreamWaitEvent(s1, evRoot, 0);
    cudaStreamWaitEvent(s2, evRoot, 0);

    // s2: wo + w_out converts (consumed late; hide under GEMMs)
    convert_kernel<<<G44, 256, 0, s2>>>((const float4*)wo, (uint2*)(wt + WO_OFF));
    cudaEventRecord(evWoCv, s2);
    convert_kernel<<<G416, 256, 0, s2>>>((const float4*)w_out, (uint2*)(wt + WOUT_OFF));
    cudaEventRecord(evWoutCv, s2);

    // s1: wk + wv converts (QKV dep), then w_in convert + MLP-in GEMM
    convert_kernel<<<G44, 256, 0, s1>>>((const float4*)wk, (uint2*)(wt + WK_OFF));
    convert_kernel<<<G44, 256, 0, s1>>>((const float4*)wv, (uint2*)(wt + WV_OFF));
    cudaEventRecord(evKV, s1);
    convert_kernel<<<G416, 256, 0, s1>>>((const float4*)w_in, (uint2*)(wt + WIN_OFF));

    // main: wq convert + LN
    convert_kernel<<<G44, 256>>>((const float4*)wq, (uint2*)(wt + WQ_OFF));
    ln_kernel<<<TT, 256>>>(x, ln_s, ln_o, h);
    cudaEventRecord(evLN, 0);

    // s1: MLP-in GEMM (needs h + w_in)
    cudaStreamWaitEvent(s1, evLN, 0);
    tgemm_kernel<1, __half><<<dim3(DFF / 256, TT / 128), 256, GSMEM_TOTAL, s1>>>(h, wt + WIN_OFF, b_in, nullptr, m, DFF, DD);
    cudaEventRecord(evM, s1);

    // main: QKV -> RoPE -> attention -> Wo
    cudaStreamWaitEvent(0, evKV, 0);
    tgemm_qkv_kernel<<<dim3(DD / 256, TT / 128, 3), 256, GSMEM_TOTAL>>>(h, wt, q, k, v);
    rope_kernel<<<(TT * HH * 32) / 256, 256>>>(q, k);
    attn_kernel<<<dim3(TT / 128, HH), 256, ATTN_SMEM>>>(q, k, v, y);
    cudaStreamWaitEvent(0, evWoCv, 0);
    tgemm_kernel<2, float><<<dim3(DD / 256, TT / 128), 256, GSMEM_TOTAL>>>(y, wt + WO_OFF, nullptr, x, tmp, DD, DD);

    // join: MLP-out needs m (s1), w_out (s2), tmp (main)
    cudaStreamWaitEvent(0, evM, 0);
    cudaStreamWaitEvent(0, evWoutCv, 0);
    tgemm_kernel<3, float><<<dim3(DD / 256, TT / 128), 256, GSMEM_TOTAL>>>(m, wt + WOUT_OFF, b_out, tmp, out, DD, DFF);
}